// round 1
// baseline (speedup 1.0000x reference)
#include <cuda_runtime.h>
#include <math.h>

// ---------------- dimensions ----------------
#define S   2048
#define D   2048
#define H   16
#define HD  128
#define FF  8192
#define VOC 32000
#define LN_EPS 1e-5f

// ---------------- scratch (static device globals; no allocation) ----------------
__device__ float g_x  [S * D];
__device__ float g_h  [S * D];
__device__ float g_q  [S * D];
__device__ float g_k  [S * D];
__device__ float g_v  [S * D];
__device__ float g_at [H * S * S];   // 268 MB attention scores / probs
__device__ float g_ao [S * D];
__device__ float g_x2 [S * D];
__device__ float g_h2 [S * D];
__device__ float g_ff [S * FF];
__device__ float g_x3 [S * D];
__device__ float g_hf [S * D];
__device__ int   g_tok64;            // 1 if tokens buffer is int64, 0 if int32

// ---------------- token dtype detection ----------------
// If tokens are int64 (little-endian), every odd 32-bit word of the first S
// words is a zero high-half (tokens in [0,32000)). If int32, odd words are
// random tokens -> virtually surely nonzero somewhere.
__global__ void detect_tok_kernel(const int* __restrict__ t)
{
    __shared__ int any;
    if (threadIdx.x == 0) any = 0;
    __syncthreads();
    int local = 0;
    for (int i = threadIdx.x; i < S / 2; i += blockDim.x)
        if (t[2 * i + 1] != 0) local = 1;
    if (local) any = 1;              // benign race, same value
    __syncthreads();
    if (threadIdx.x == 0) g_tok64 = (any == 0) ? 1 : 0;
}

// ---------------- embedding ----------------
__global__ void embed_kernel(const int* __restrict__ tok,
                             const float* __restrict__ te,
                             const float* __restrict__ pe,
                             float* __restrict__ x)
{
    const int s = blockIdx.x;
    const int t = g_tok64 ? tok[2 * s] : tok[s];   // int64 low word or int32
    const float4* e = (const float4*)(te + (size_t)t * D);
    const float4* p = (const float4*)(pe + (size_t)s * D);
    float4*       o = (float4*)(x + (size_t)s * D);
    for (int i = threadIdx.x; i < D / 4; i += blockDim.x) {
        float4 a = e[i], b = p[i];
        o[i] = make_float4(a.x + b.x, a.y + b.y, a.z + b.z, a.w + b.w);
    }
}

// ---------------- layernorm (one block per row, D=2048) ----------------
__global__ void ln_kernel(const float* __restrict__ x,
                          const float* __restrict__ g,
                          const float* __restrict__ b,
                          float* __restrict__ out)
{
    __shared__ float r1[8], r2[8];
    __shared__ float s_mean, s_inv;
    const int s   = blockIdx.x;
    const int tid = threadIdx.x;
    const float4* xr = (const float4*)(x + (size_t)s * D);
    float4 v0 = xr[tid];
    float4 v1 = xr[tid + 256];
    float sum = v0.x + v0.y + v0.z + v0.w + v1.x + v1.y + v1.z + v1.w;
    float sq  = v0.x * v0.x + v0.y * v0.y + v0.z * v0.z + v0.w * v0.w
              + v1.x * v1.x + v1.y * v1.y + v1.z * v1.z + v1.w * v1.w;
#pragma unroll
    for (int o = 16; o; o >>= 1) {
        sum += __shfl_xor_sync(0xffffffffu, sum, o);
        sq  += __shfl_xor_sync(0xffffffffu, sq,  o);
    }
    const int w = tid >> 5;
    if ((tid & 31) == 0) { r1[w] = sum; r2[w] = sq; }
    __syncthreads();
    if (tid == 0) {
        float ts = 0.f, tq = 0.f;
#pragma unroll
        for (int i = 0; i < 8; i++) { ts += r1[i]; tq += r2[i]; }
        const float mean = ts / (float)D;
        const float var  = tq / (float)D - mean * mean;
        s_mean = mean;
        s_inv  = rsqrtf(var + LN_EPS);
    }
    __syncthreads();
    const float mean = s_mean, inv = s_inv;
    const float4* gg = (const float4*)g;
    const float4* bb = (const float4*)b;
    float4* oo = (float4*)(out + (size_t)s * D);
    float4 g0 = gg[tid], g1 = gg[tid + 256];
    float4 b0 = bb[tid], b1 = bb[tid + 256];
    float4 o0, o1;
    o0.x = (v0.x - mean) * inv * g0.x + b0.x;
    o0.y = (v0.y - mean) * inv * g0.y + b0.y;
    o0.z = (v0.z - mean) * inv * g0.z + b0.z;
    o0.w = (v0.w - mean) * inv * g0.w + b0.w;
    o1.x = (v1.x - mean) * inv * g1.x + b1.x;
    o1.y = (v1.y - mean) * inv * g1.y + b1.y;
    o1.z = (v1.z - mean) * inv * g1.z + b1.z;
    o1.w = (v1.w - mean) * inv * g1.w + b1.w;
    oo[tid]       = o0;
    oo[tid + 256] = o1;
}

// ---------------- softmax over rows of length S ----------------
__global__ void softmax_kernel(float* __restrict__ sc)
{
    __shared__ float r1[8];
    __shared__ float s_max, s_inv;
    const int tid = threadIdx.x;
    float* r = sc + (size_t)blockIdx.x * S;
    float4 v0 = ((float4*)r)[tid];
    float4 v1 = ((float4*)r)[tid + 256];
    float mx = fmaxf(fmaxf(fmaxf(v0.x, v0.y), fmaxf(v0.z, v0.w)),
                     fmaxf(fmaxf(v1.x, v1.y), fmaxf(v1.z, v1.w)));
#pragma unroll
    for (int o = 16; o; o >>= 1) mx = fmaxf(mx, __shfl_xor_sync(0xffffffffu, mx, o));
    const int w = tid >> 5;
    if ((tid & 31) == 0) r1[w] = mx;
    __syncthreads();
    if (tid == 0) {
        float m = r1[0];
#pragma unroll
        for (int i = 1; i < 8; i++) m = fmaxf(m, r1[i]);
        s_max = m;
    }
    __syncthreads();
    mx = s_max;
    v0.x = expf(v0.x - mx); v0.y = expf(v0.y - mx);
    v0.z = expf(v0.z - mx); v0.w = expf(v0.w - mx);
    v1.x = expf(v1.x - mx); v1.y = expf(v1.y - mx);
    v1.z = expf(v1.z - mx); v1.w = expf(v1.w - mx);
    float sum = v0.x + v0.y + v0.z + v0.w + v1.x + v1.y + v1.z + v1.w;
#pragma unroll
    for (int o = 16; o; o >>= 1) sum += __shfl_xor_sync(0xffffffffu, sum, o);
    __syncthreads();                       // r1 reuse
    if ((tid & 31) == 0) r1[w] = sum;
    __syncthreads();
    if (tid == 0) {
        float t = 0.f;
#pragma unroll
        for (int i = 0; i < 8; i++) t += r1[i];
        s_inv = 1.0f / t;
    }
    __syncthreads();
    const float inv = s_inv;
    v0.x *= inv; v0.y *= inv; v0.z *= inv; v0.w *= inv;
    v1.x *= inv; v1.y *= inv; v1.z *= inv; v1.w *= inv;
    ((float4*)r)[tid]       = v0;
    ((float4*)r)[tid + 256] = v1;
}

// ---------------- generic tiled fp32 GEMM ----------------
// C[z] = epi(alpha * A[z] @ op(B[z]) (+ Res))  ; op = B (NN) or B^T (NT)
// Tiles: 128x128x8, 256 threads, 8x8 per-thread. All dims multiples of tile.
#define BM 128
#define BN 128
#define BK 8

#define EPI_NONE 0
#define EPI_RES  1
#define EPI_RELU 2

template <int EPI, bool BT>
__global__ void __launch_bounds__(256, 2)
gemm_kernel(const float* __restrict__ A, int lda, long long sA,
            const float* __restrict__ B, int ldb, long long sB,
            const float* __restrict__ Res,
            float* __restrict__ C, int ldc, long long sC,
            int K, float alpha)
{
    __shared__ float As[BK][BM];
    __shared__ float Bs[BK][BN];

    const int z = blockIdx.z;
    A += (size_t)z * sA;
    B += (size_t)z * sB;
    C += (size_t)z * sC;

    const int tid = threadIdx.x;
    const int m0 = blockIdx.y * BM;
    const int n0 = blockIdx.x * BN;

    // A tile loader: 128 rows x 8 cols, one float4 per thread, stored transposed
    const int arow = tid >> 1;
    const int acol = (tid & 1) << 2;
    const float* Ap = A + (size_t)(m0 + arow) * lda + acol;

    // B tile loader
    const int brow_nn = tid >> 5;          // NN: 8 rows x 128 cols
    const int bcol_nn = (tid & 31) << 2;
    const float* Bp;
    if (BT) Bp = B + (size_t)(n0 + arow) * ldb + acol;       // NT: like A
    else    Bp = B + (size_t)brow_nn * ldb + n0 + bcol_nn;   // NN

    const int ty = tid >> 4, tx = tid & 15;

    float acc[8][8];
#pragma unroll
    for (int i = 0; i < 8; i++)
#pragma unroll
        for (int j = 0; j < 8; j++) acc[i][j] = 0.f;

    for (int k0 = 0; k0 < K; k0 += BK) {
        const float4 a = *(const float4*)Ap;
        const float4 b = *(const float4*)Bp;
        As[acol + 0][arow] = a.x;
        As[acol + 1][arow] = a.y;
        As[acol + 2][arow] = a.z;
        As[acol + 3][arow] = a.w;
        if (BT) {
            Bs[acol + 0][arow] = b.x;
            Bs[acol + 1][arow] = b.y;
            Bs[acol + 2][arow] = b.z;
            Bs[acol + 3][arow] = b.w;
        } else {
            *(float4*)&Bs[brow_nn][bcol_nn] = b;
        }
        __syncthreads();
#pragma unroll
        for (int k = 0; k < BK; k++) {
            float ar[8], br[8];
            *(float4*)&ar[0] = *(const float4*)&As[k][ty * 8];
            *(float4*)&ar[4] = *(const float4*)&As[k][ty * 8 + 4];
            *(float4*)&br[0] = *(const float4*)&Bs[k][tx * 8];
            *(float4*)&br[4] = *(const float4*)&Bs[k][tx * 8 + 4];
#pragma unroll
            for (int i = 0; i < 8; i++)
#pragma unroll
                for (int j = 0; j < 8; j++)
                    acc[i][j] = fmaf(ar[i], br[j], acc[i][j]);
        }
        __syncthreads();
        Ap += BK;
        Bp += BT ? (size_t)BK : (size_t)BK * ldb;
    }

#pragma unroll
    for (int i = 0; i < 8; i++) {
        const int m = m0 + ty * 8 + i;
        float* cp = C + (size_t)m * ldc + n0 + tx * 8;
#pragma unroll
        for (int j = 0; j < 8; j += 4) {
            float4 v = make_float4(acc[i][j] * alpha, acc[i][j + 1] * alpha,
                                   acc[i][j + 2] * alpha, acc[i][j + 3] * alpha);
            if (EPI == EPI_RES) {
                const float4 r = *(const float4*)(Res + (size_t)m * ldc + n0 + tx * 8 + j);
                v.x += r.x; v.y += r.y; v.z += r.z; v.w += r.w;
            } else if (EPI == EPI_RELU) {
                v.x = fmaxf(v.x, 0.f); v.y = fmaxf(v.y, 0.f);
                v.z = fmaxf(v.z, 0.f); v.w = fmaxf(v.w, 0.f);
            }
            *(float4*)(cp + j) = v;
        }
    }
}

// ---------------- launch ----------------
extern "C" void kernel_launch(void* const* d_in, const int* in_sizes, int n_in,
                              void* d_out, int out_size)
{
    const int*   tokens = (const int*)d_in[0];
    const float* temb   = (const float*)d_in[1];
    const float* pemb   = (const float*)d_in[2];
    const float* wq     = (const float*)d_in[3];
    const float* wk     = (const float*)d_in[4];
    const float* wv     = (const float*)d_in[5];
    const float* wo     = (const float*)d_in[6];
    const float* wfi    = (const float*)d_in[7];
    const float* wfo    = (const float*)d_in[8];
    const float* ln1g   = (const float*)d_in[9];
    const float* ln1b   = (const float*)d_in[10];
    const float* ln2g   = (const float*)d_in[11];
    const float* ln2b   = (const float*)d_in[12];
    const float* lnfg   = (const float*)d_in[13];
    const float* lnfb   = (const float*)d_in[14];
    const float* wout   = (const float*)d_in[15];
    float*       out    = (float*)d_out;

    float *px, *ph, *pq, *pk, *pv, *pat, *pao, *px2, *ph2, *pff, *px3, *phf;
    cudaGetSymbolAddress((void**)&px,  g_x);
    cudaGetSymbolAddress((void**)&ph,  g_h);
    cudaGetSymbolAddress((void**)&pq,  g_q);
    cudaGetSymbolAddress((void**)&pk,  g_k);
    cudaGetSymbolAddress((void**)&pv,  g_v);
    cudaGetSymbolAddress((void**)&pat, g_at);
    cudaGetSymbolAddress((void**)&pao, g_ao);
    cudaGetSymbolAddress((void**)&px2, g_x2);
    cudaGetSymbolAddress((void**)&ph2, g_h2);
    cudaGetSymbolAddress((void**)&pff, g_ff);
    cudaGetSymbolAddress((void**)&px3, g_x3);
    cudaGetSymbolAddress((void**)&phf, g_hf);

    detect_tok_kernel<<<1, 256>>>(tokens);
    embed_kernel<<<S, 256>>>(tokens, temb, pemb, px);

    // attention block
    ln_kernel<<<S, 256>>>(px, ln1g, ln1b, ph);
    const dim3 gDD(D / BN, S / BM, 1);
    gemm_kernel<EPI_NONE, false><<<gDD, 256>>>(ph, D, 0, wq, D, 0, nullptr, pq, D, 0, D, 1.f);
    gemm_kernel<EPI_NONE, false><<<gDD, 256>>>(ph, D, 0, wk, D, 0, nullptr, pk, D, 0, D, 1.f);
    gemm_kernel<EPI_NONE, false><<<gDD, 256>>>(ph, D, 0, wv, D, 0, nullptr, pv, D, 0, D, 1.f);

    // scores[h] = (1/sqrt(HD)) * Q_h @ K_h^T
    gemm_kernel<EPI_NONE, true><<<dim3(S / BN, S / BM, H), 256>>>(
        pq, D, HD, pk, D, HD, nullptr, pat, S, (long long)S * S, HD,
        0.08838834764831845f);
    softmax_kernel<<<H * S, 256>>>(pat);
    // attn_out[h] = P_h @ V_h
    gemm_kernel<EPI_NONE, false><<<dim3(1, S / BM, H), 256>>>(
        pat, S, (long long)S * S, pv, D, HD, nullptr, pao, D, HD, S, 1.f);
    // x2 = x + attn_out @ Wo
    gemm_kernel<EPI_RES, false><<<gDD, 256>>>(pao, D, 0, wo, D, 0, px, px2, D, 0, D, 1.f);

    // FFN block
    ln_kernel<<<S, 256>>>(px2, ln2g, ln2b, ph2);
    gemm_kernel<EPI_RELU, false><<<dim3(FF / BN, S / BM, 1), 256>>>(
        ph2, D, 0, wfi, FF, 0, nullptr, pff, FF, 0, D, 1.f);
    gemm_kernel<EPI_RES, false><<<gDD, 256>>>(
        pff, FF, 0, wfo, D, 0, px2, px3, D, 0, FF, 1.f);

    // final LN + logits
    ln_kernel<<<S, 256>>>(px3, lnfg, lnfb, phf);
    gemm_kernel<EPI_NONE, false><<<dim3(VOC / BN, S / BM, 1), 256>>>(
        phf, D, 0, wout, VOC, 0, nullptr, out, VOC, 0, D, 1.f);
}

// round 3
// speedup vs baseline: 1.3945x; 1.3945x over previous
#include <cuda_runtime.h>
#include <cuda_bf16.h>
#include <stdint.h>
#include <math.h>

// ---------------- dimensions ----------------
#define S   2048
#define D   2048
#define H   16
#define HD  128
#define FF  8192
#define VOC 32000
#define LN_EPS 1e-5f

// ---------------- scratch ----------------
__device__ float g_x  [S * D];
__device__ float g_h  [S * D];
__device__ float g_q  [S * D];
__device__ float g_k  [S * D];
__device__ float g_v  [S * D];
__device__ float g_at [H * S * S];
__device__ float g_ao [S * D];
__device__ float g_x2 [S * D];
__device__ float g_h2 [S * D];
__device__ float g_ff [S * FF];
__device__ float g_x3 [S * D];
__device__ float g_hf [S * D];
__device__ int   g_tok64;

// ---------------- small PTX helpers (all plain-sm_103-legal) ----------------
__device__ __forceinline__ uint32_t smem_u32(const void* p) {
    uint32_t a;
    asm("{ .reg .u64 t; cvta.to.shared.u64 t, %1; cvt.u32.u64 %0, t; }" : "=r"(a) : "l"(p));
    return a;
}
__device__ __forceinline__ void sts128(uint32_t addr, uint4 v) {
    asm volatile("st.shared.v4.b32 [%0], {%1,%2,%3,%4};"
                 :: "r"(addr), "r"(v.x), "r"(v.y), "r"(v.z), "r"(v.w) : "memory");
}
__device__ __forceinline__ void sts32(uint32_t addr, uint32_t v) {
    asm volatile("st.shared.b32 [%0], %1;" :: "r"(addr), "r"(v) : "memory");
}
__device__ __forceinline__ void ldm_x4(uint32_t* r, uint32_t addr) {
    asm volatile("ldmatrix.sync.aligned.m8n8.x4.shared.b16 {%0,%1,%2,%3}, [%4];"
                 : "=r"(r[0]), "=r"(r[1]), "=r"(r[2]), "=r"(r[3]) : "r"(addr));
}
__device__ __forceinline__ void mma_bf16(float* c, const uint32_t* a, const uint32_t* b) {
    asm volatile(
        "mma.sync.aligned.m16n8k16.row.col.f32.bf16.bf16.f32 "
        "{%0,%1,%2,%3}, {%4,%5,%6,%7}, {%8,%9}, {%0,%1,%2,%3};"
        : "+f"(c[0]), "+f"(c[1]), "+f"(c[2]), "+f"(c[3])
        : "r"(a[0]), "r"(a[1]), "r"(a[2]), "r"(a[3]), "r"(b[0]), "r"(b[1]));
}

// split fp32 pair -> bf16 hi pair + bf16 lo (residual) pair
__device__ __forceinline__ uint32_t split2(float a, float b, uint32_t& lo)
{
    __nv_bfloat16 ha = __float2bfloat16(a);
    __nv_bfloat16 hb = __float2bfloat16(b);
    __nv_bfloat162 l2;
    l2.x = __float2bfloat16(a - __bfloat162float(ha));
    l2.y = __float2bfloat16(b - __bfloat162float(hb));
    lo = *reinterpret_cast<uint32_t*>(&l2);
    __nv_bfloat162 h2; h2.x = ha; h2.y = hb;
    return *reinterpret_cast<uint32_t*>(&h2);
}
__device__ __forceinline__ void cvt8(float4 v0, float4 v1, uint4& hi, uint4& lo)
{
    hi.x = split2(v0.x, v0.y, lo.x);
    hi.y = split2(v0.z, v0.w, lo.y);
    hi.z = split2(v1.x, v1.y, lo.z);
    hi.w = split2(v1.z, v1.w, lo.w);
}
#define SW(o) ((o) ^ (((o) >> 3) & 0x70))

// ---------------- token dtype detection + embed ----------------
__global__ void detect_tok_kernel(const int* __restrict__ t)
{
    __shared__ int any;
    if (threadIdx.x == 0) any = 0;
    __syncthreads();
    int local = 0;
    for (int i = threadIdx.x; i < S / 2; i += blockDim.x)
        if (t[2 * i + 1] != 0) local = 1;
    if (local) any = 1;
    __syncthreads();
    if (threadIdx.x == 0) g_tok64 = (any == 0) ? 1 : 0;
}

__global__ void embed_kernel(const int* __restrict__ tok,
                             const float* __restrict__ te,
                             const float* __restrict__ pe,
                             float* __restrict__ x)
{
    const int s = blockIdx.x;
    const int t = g_tok64 ? tok[2 * s] : tok[s];
    const float4* e = (const float4*)(te + (size_t)t * D);
    const float4* p = (const float4*)(pe + (size_t)s * D);
    float4*       o = (float4*)(x + (size_t)s * D);
    for (int i = threadIdx.x; i < D / 4; i += blockDim.x) {
        float4 a = e[i], b = p[i];
        o[i] = make_float4(a.x + b.x, a.y + b.y, a.z + b.z, a.w + b.w);
    }
}

// ---------------- layernorm ----------------
__global__ void ln_kernel(const float* __restrict__ x,
                          const float* __restrict__ g,
                          const float* __restrict__ b,
                          float* __restrict__ out)
{
    __shared__ float r1[8], r2[8];
    __shared__ float s_mean, s_inv;
    const int s   = blockIdx.x;
    const int tid = threadIdx.x;
    const float4* xr = (const float4*)(x + (size_t)s * D);
    float4 v0 = xr[tid];
    float4 v1 = xr[tid + 256];
    float sum = v0.x + v0.y + v0.z + v0.w + v1.x + v1.y + v1.z + v1.w;
    float sq  = v0.x * v0.x + v0.y * v0.y + v0.z * v0.z + v0.w * v0.w
              + v1.x * v1.x + v1.y * v1.y + v1.z * v1.z + v1.w * v1.w;
#pragma unroll
    for (int o = 16; o; o >>= 1) {
        sum += __shfl_xor_sync(0xffffffffu, sum, o);
        sq  += __shfl_xor_sync(0xffffffffu, sq,  o);
    }
    const int w = tid >> 5;
    if ((tid & 31) == 0) { r1[w] = sum; r2[w] = sq; }
    __syncthreads();
    if (tid == 0) {
        float ts = 0.f, tq = 0.f;
#pragma unroll
        for (int i = 0; i < 8; i++) { ts += r1[i]; tq += r2[i]; }
        const float mean = ts / (float)D;
        const float var  = tq / (float)D - mean * mean;
        s_mean = mean;
        s_inv  = rsqrtf(var + LN_EPS);
    }
    __syncthreads();
    const float mean = s_mean, inv = s_inv;
    const float4* gg = (const float4*)g;
    const float4* bb = (const float4*)b;
    float4* oo = (float4*)(out + (size_t)s * D);
    float4 g0 = gg[tid], g1 = gg[tid + 256];
    float4 b0 = bb[tid], b1 = bb[tid + 256];
    float4 o0, o1;
    o0.x = (v0.x - mean) * inv * g0.x + b0.x;
    o0.y = (v0.y - mean) * inv * g0.y + b0.y;
    o0.z = (v0.z - mean) * inv * g0.z + b0.z;
    o0.w = (v0.w - mean) * inv * g0.w + b0.w;
    o1.x = (v1.x - mean) * inv * g1.x + b1.x;
    o1.y = (v1.y - mean) * inv * g1.y + b1.y;
    o1.z = (v1.z - mean) * inv * g1.z + b1.z;
    o1.w = (v1.w - mean) * inv * g1.w + b1.w;
    oo[tid]       = o0;
    oo[tid + 256] = o1;
}

// ---------------- softmax ----------------
__global__ void softmax_kernel(float* __restrict__ sc)
{
    __shared__ float r1[8];
    __shared__ float s_max, s_inv;
    const int tid = threadIdx.x;
    float* r = sc + (size_t)blockIdx.x * S;
    float4 v0 = ((float4*)r)[tid];
    float4 v1 = ((float4*)r)[tid + 256];
    float mx = fmaxf(fmaxf(fmaxf(v0.x, v0.y), fmaxf(v0.z, v0.w)),
                     fmaxf(fmaxf(v1.x, v1.y), fmaxf(v1.z, v1.w)));
#pragma unroll
    for (int o = 16; o; o >>= 1) mx = fmaxf(mx, __shfl_xor_sync(0xffffffffu, mx, o));
    const int w = tid >> 5;
    if ((tid & 31) == 0) r1[w] = mx;
    __syncthreads();
    if (tid == 0) {
        float m = r1[0];
#pragma unroll
        for (int i = 1; i < 8; i++) m = fmaxf(m, r1[i]);
        s_max = m;
    }
    __syncthreads();
    mx = s_max;
    v0.x = expf(v0.x - mx); v0.y = expf(v0.y - mx);
    v0.z = expf(v0.z - mx); v0.w = expf(v0.w - mx);
    v1.x = expf(v1.x - mx); v1.y = expf(v1.y - mx);
    v1.z = expf(v1.z - mx); v1.w = expf(v1.w - mx);
    float sum = v0.x + v0.y + v0.z + v0.w + v1.x + v1.y + v1.z + v1.w;
#pragma unroll
    for (int o = 16; o; o >>= 1) sum += __shfl_xor_sync(0xffffffffu, sum, o);
    __syncthreads();
    if ((tid & 31) == 0) r1[w] = sum;
    __syncthreads();
    if (tid == 0) {
        float t = 0.f;
#pragma unroll
        for (int i = 0; i < 8; i++) t += r1[i];
        s_inv = 1.0f / t;
    }
    __syncthreads();
    const float inv = s_inv;
    v0.x *= inv; v0.y *= inv; v0.z *= inv; v0.w *= inv;
    v1.x *= inv; v1.y *= inv; v1.z *= inv; v1.w *= inv;
    ((float4*)r)[tid]       = v0;
    ((float4*)r)[tid + 256] = v1;
}

// ---------------- mma.sync bf16-split GEMM ----------------
// C[z] = epi(alpha * A[z] @ Bop[z] (+ Res))
// BNMAJOR=true : B gmem is [K][N] (weights) -> transpose-convert into [n][k] tiles
// BNMAJOR=false: B gmem is [N][K] (e.g. K matrix for QK^T) -> direct convert
#define EPI_NONE 0
#define EPI_RES  1
#define EPI_RELU 2

#define GEMM_SMEM 65536   // 4 x 16KB bf16 tiles (Ahi, Alo, Bhi, Blo), 128x64 each

// rows are k-contiguous (A always; B in NT case): 128 rows x 64 k
__device__ __forceinline__ void load_rowk_tile(uint32_t dhi, uint32_t dlo,
                                               const float* __restrict__ src,
                                               int ld, int tid)
{
    const int row   = tid >> 1;
    const int khalf = (tid & 1) * 32;
    const float* p = src + (size_t)row * ld + khalf;
    const uint32_t base = (uint32_t)(row * 128 + khalf * 2);
#pragma unroll
    for (int j = 0; j < 4; j++) {
        float4 v0 = *(const float4*)(p + 8 * j);
        float4 v1 = *(const float4*)(p + 8 * j + 4);
        uint4 hi, lo;
        cvt8(v0, v1, hi, lo);
        const uint32_t off = base + 16 * j;
        const uint32_t swo = SW(off);
        sts128(dhi + swo, hi);
        sts128(dlo + swo, lo);
    }
}

// B gmem [K][N]: transpose-convert into [n][k] tiles, 128 n-rows x 64 k
__device__ __forceinline__ void load_coln_tile(uint32_t dhi, uint32_t dlo,
                                               const float* __restrict__ src,
                                               int ld, int tid)
{
    const int n  = tid & 127;
    const int ks = (tid >> 7) * 2;   // 0 or 2
#pragma unroll
    for (int i = 0; i < 16; i++) {
        const int k = i * 4 + ks;
        const float a = src[(size_t)k * ld + n];
        const float b = src[(size_t)(k + 1) * ld + n];
        uint32_t lo32;
        const uint32_t hi32 = split2(a, b, lo32);
        const uint32_t off = (uint32_t)(n * 128 + k * 2);
        const uint32_t swo = SW(off);
        sts32(dhi + swo, hi32);
        sts32(dlo + swo, lo32);
    }
}

template <int EPI, bool BNMAJOR>
__global__ void __launch_bounds__(256, 2)
tc_gemm(const float* __restrict__ A, int lda, long long sA,
        const float* __restrict__ B, int ldb, long long sB,
        const float* __restrict__ Res,
        float* __restrict__ C, int ldc, long long sC,
        int K, float alpha)
{
    extern __shared__ char smem[];
    const uint32_t sb = smem_u32(smem);
    const int tid = threadIdx.x, wid = tid >> 5, lane = tid & 31;
    const int z = blockIdx.z;
    A += (size_t)z * sA;
    B += (size_t)z * sB;
    C += (size_t)z * sC;
    const int m0 = blockIdx.y * 128;
    const int n0 = blockIdx.x * 128;
    const int wm = (wid & 3) * 32;
    const int wn = (wid >> 2) * 64;

    const uint32_t Ahi = sb, Alo = sb + 16384, Bhi = sb + 32768, Blo = sb + 49152;

    float acc[2][8][4];
#pragma unroll
    for (int i = 0; i < 2; i++)
#pragma unroll
        for (int j = 0; j < 8; j++)
#pragma unroll
            for (int q = 0; q < 4; q++) acc[i][j][q] = 0.f;

    // ldmatrix lane address components
    const int a_row = lane & 15;
    const int a_kc  = (lane >> 4) * 8;
    const int b_row = (lane & 7) + (lane >> 4) * 8;
    const int b_kc  = ((lane >> 3) & 1) * 8;

    for (int k0 = 0; k0 < K; k0 += 64) {
        load_rowk_tile(Ahi, Alo, A + (size_t)m0 * lda + k0, lda, tid);
        if (BNMAJOR) load_coln_tile(Bhi, Blo, B + (size_t)k0 * ldb + n0, ldb, tid);
        else         load_rowk_tile(Bhi, Blo, B + (size_t)n0 * ldb + k0, ldb, tid);
        __syncthreads();

#pragma unroll
        for (int ks = 0; ks < 4; ks++) {
            uint32_t ah[2][4], al[2][4];
#pragma unroll
            for (int mf = 0; mf < 2; mf++) {
                const uint32_t off = (uint32_t)((wm + mf * 16 + a_row) * 128
                                                + (ks * 16 + a_kc) * 2);
                const uint32_t swo = SW(off);
                ldm_x4(ah[mf], Ahi + swo);
                ldm_x4(al[mf], Alo + swo);
            }
#pragma unroll
            for (int p = 0; p < 4; p++) {
                uint32_t bh[4], bl[4];
                const uint32_t off = (uint32_t)((wn + p * 16 + b_row) * 128
                                                + (ks * 16 + b_kc) * 2);
                const uint32_t swo = SW(off);
                ldm_x4(bh, Bhi + swo);
                ldm_x4(bl, Blo + swo);
#pragma unroll
                for (int mf = 0; mf < 2; mf++) {
                    mma_bf16(acc[mf][2 * p],     ah[mf], bh);
                    mma_bf16(acc[mf][2 * p + 1], ah[mf], bh + 2);
                    mma_bf16(acc[mf][2 * p],     al[mf], bh);
                    mma_bf16(acc[mf][2 * p + 1], al[mf], bh + 2);
                    mma_bf16(acc[mf][2 * p],     ah[mf], bl);
                    mma_bf16(acc[mf][2 * p + 1], ah[mf], bl + 2);
                }
            }
        }
        __syncthreads();
    }

    // epilogue
    const int r  = lane >> 2;
    const int c2 = (lane & 3) * 2;
#pragma unroll
    for (int mf = 0; mf < 2; mf++) {
#pragma unroll
        for (int hh = 0; hh < 2; hh++) {
            const int m = m0 + wm + mf * 16 + r + 8 * hh;
            float* crow = C + (size_t)m * ldc + n0 + wn;
            const float* rrow = (EPI == EPI_RES)
                                ? (Res + (size_t)m * ldc + n0 + wn) : nullptr;
#pragma unroll
            for (int nf = 0; nf < 8; nf++) {
                float x0 = acc[mf][nf][2 * hh]     * alpha;
                float x1 = acc[mf][nf][2 * hh + 1] * alpha;
                const int nn = nf * 8 + c2;
                if (EPI == EPI_RES) {
                    const float2 rr = *(const float2*)(rrow + nn);
                    x0 += rr.x; x1 += rr.y;
                } else if (EPI == EPI_RELU) {
                    x0 = fmaxf(x0, 0.f); x1 = fmaxf(x1, 0.f);
                }
                *(float2*)(crow + nn) = make_float2(x0, x1);
            }
        }
    }
}

// ---------------- launch ----------------
extern "C" void kernel_launch(void* const* d_in, const int* in_sizes, int n_in,
                              void* d_out, int out_size)
{
    const int*   tokens = (const int*)d_in[0];
    const float* temb   = (const float*)d_in[1];
    const float* pemb   = (const float*)d_in[2];
    const float* wq     = (const float*)d_in[3];
    const float* wk     = (const float*)d_in[4];
    const float* wv     = (const float*)d_in[5];
    const float* wo     = (const float*)d_in[6];
    const float* wfi    = (const float*)d_in[7];
    const float* wfo    = (const float*)d_in[8];
    const float* ln1g   = (const float*)d_in[9];
    const float* ln1b   = (const float*)d_in[10];
    const float* ln2g   = (const float*)d_in[11];
    const float* ln2b   = (const float*)d_in[12];
    const float* lnfg   = (const float*)d_in[13];
    const float* lnfb   = (const float*)d_in[14];
    const float* wout   = (const float*)d_in[15];
    float*       out    = (float*)d_out;

    float *px, *ph, *pq, *pk, *pv, *pat, *pao, *px2, *ph2, *pff, *px3, *phf;
    cudaGetSymbolAddress((void**)&px,  g_x);
    cudaGetSymbolAddress((void**)&ph,  g_h);
    cudaGetSymbolAddress((void**)&pq,  g_q);
    cudaGetSymbolAddress((void**)&pk,  g_k);
    cudaGetSymbolAddress((void**)&pv,  g_v);
    cudaGetSymbolAddress((void**)&pat, g_at);
    cudaGetSymbolAddress((void**)&pao, g_ao);
    cudaGetSymbolAddress((void**)&px2, g_x2);
    cudaGetSymbolAddress((void**)&ph2, g_h2);
    cudaGetSymbolAddress((void**)&pff, g_ff);
    cudaGetSymbolAddress((void**)&px3, g_x3);
    cudaGetSymbolAddress((void**)&phf, g_hf);

    cudaFuncSetAttribute(tc_gemm<EPI_NONE, true>,
                         cudaFuncAttributeMaxDynamicSharedMemorySize, GEMM_SMEM);
    cudaFuncSetAttribute(tc_gemm<EPI_NONE, false>,
                         cudaFuncAttributeMaxDynamicSharedMemorySize, GEMM_SMEM);
    cudaFuncSetAttribute(tc_gemm<EPI_RES, true>,
                         cudaFuncAttributeMaxDynamicSharedMemorySize, GEMM_SMEM);
    cudaFuncSetAttribute(tc_gemm<EPI_RELU, true>,
                         cudaFuncAttributeMaxDynamicSharedMemorySize, GEMM_SMEM);

    detect_tok_kernel<<<1, 256>>>(tokens);
    embed_kernel<<<S, 256>>>(tokens, temb, pemb, px);

    // attention block
    ln_kernel<<<S, 256>>>(px, ln1g, ln1b, ph);
    const dim3 gDD(D / 128, S / 128, 1);
    tc_gemm<EPI_NONE, true><<<gDD, 256, GEMM_SMEM>>>(ph, D, 0, wq, D, 0, nullptr, pq, D, 0, D, 1.f);
    tc_gemm<EPI_NONE, true><<<gDD, 256, GEMM_SMEM>>>(ph, D, 0, wk, D, 0, nullptr, pk, D, 0, D, 1.f);
    tc_gemm<EPI_NONE, true><<<gDD, 256, GEMM_SMEM>>>(ph, D, 0, wv, D, 0, nullptr, pv, D, 0, D, 1.f);

    // scores[h] = (1/sqrt(HD)) * Q_h @ K_h^T   (B = K slice, [N=S][K=HD])
    tc_gemm<EPI_NONE, false><<<dim3(S / 128, S / 128, H), 256, GEMM_SMEM>>>(
        pq, D, HD, pk, D, HD, nullptr, pat, S, (long long)S * S, HD,
        0.08838834764831845f);
    softmax_kernel<<<H * S, 256>>>(pat);
    // attn_out[h] = P_h @ V_h   (B = V slice, [K=S][N=HD])
    tc_gemm<EPI_NONE, true><<<dim3(1, S / 128, H), 256, GEMM_SMEM>>>(
        pat, S, (long long)S * S, pv, D, HD, nullptr, pao, D, HD, S, 1.f);
    // x2 = x + attn_out @ Wo
    tc_gemm<EPI_RES, true><<<gDD, 256, GEMM_SMEM>>>(pao, D, 0, wo, D, 0, px, px2, D, 0, D, 1.f);

    // FFN block
    ln_kernel<<<S, 256>>>(px2, ln2g, ln2b, ph2);
    tc_gemm<EPI_RELU, true><<<dim3(FF / 128, S / 128, 1), 256, GEMM_SMEM>>>(
        ph2, D, 0, wfi, FF, 0, nullptr, pff, FF, 0, D, 1.f);
    tc_gemm<EPI_RES, true><<<gDD, 256, GEMM_SMEM>>>(
        pff, FF, 0, wfo, D, 0, px2, px3, D, 0, FF, 1.f);

    // final LN + logits
    ln_kernel<<<S, 256>>>(px3, lnfg, lnfb, phf);
    tc_gemm<EPI_NONE, true><<<dim3(VOC / 128, S / 128, 1), 256, GEMM_SMEM>>>(
        phf, D, 0, wout, VOC, 0, nullptr, out, VOC, 0, D, 1.f);
}

// round 4
// speedup vs baseline: 3.1287x; 2.2437x over previous
#include <cuda_runtime.h>
#include <cuda_bf16.h>
#include <stdint.h>
#include <math.h>

typedef __nv_bfloat16 BF16;

// ---------------- dimensions ----------------
#define S   2048
#define D   2048
#define H   16
#define HD  128
#define FF  8192
#define VOC 32000
#define LN_EPS 1e-5f
#define SD  (S * D)
#define DD  (D * D)

// ---------------- scratch ----------------
__device__ float g_x  [SD];
__device__ float g_x2 [SD];
__device__ float g_x3 [SD];
__device__ float g_at [H * S * S];

__device__ BF16 g_hh [SD],  g_hl [SD];
__device__ BF16 g_h2h[SD],  g_h2l[SD];
__device__ BF16 g_hfh[SD],  g_hfl[SD];
__device__ BF16 g_qkvh[3 * SD], g_qkvl[3 * SD];
__device__ BF16 g_vth[SD],  g_vtl[SD];
__device__ BF16 g_ph [H * S * S], g_pl [H * S * S];
__device__ BF16 g_aoh[SD],  g_aol[SD];
__device__ BF16 g_ffh[S * FF], g_ffl[S * FF];

__device__ BF16 g_wqkvTh[3 * DD], g_wqkvTl[3 * DD];
__device__ BF16 g_woTh[DD],       g_woTl[DD];
__device__ BF16 g_wfiTh[D * FF],  g_wfiTl[D * FF];
__device__ BF16 g_wfoTh[D * FF],  g_wfoTl[D * FF];
__device__ BF16 g_woutTh[(size_t)D * VOC], g_woutTl[(size_t)D * VOC];

__device__ int g_tok64;

// ---------------- PTX helpers (plain sm_103-legal) ----------------
__device__ __forceinline__ uint32_t smem_u32(const void* p) {
    uint32_t a;
    asm("{ .reg .u64 t; cvta.to.shared.u64 t, %1; cvt.u32.u64 %0, t; }" : "=r"(a) : "l"(p));
    return a;
}
__device__ __forceinline__ void ldm_x4(uint32_t* r, uint32_t addr) {
    asm volatile("ldmatrix.sync.aligned.m8n8.x4.shared.b16 {%0,%1,%2,%3}, [%4];"
                 : "=r"(r[0]), "=r"(r[1]), "=r"(r[2]), "=r"(r[3]) : "r"(addr));
}
__device__ __forceinline__ void mma_bf16(float* c, const uint32_t* a, const uint32_t* b) {
    asm volatile(
        "mma.sync.aligned.m16n8k16.row.col.f32.bf16.bf16.f32 "
        "{%0,%1,%2,%3}, {%4,%5,%6,%7}, {%8,%9}, {%0,%1,%2,%3};"
        : "+f"(c[0]), "+f"(c[1]), "+f"(c[2]), "+f"(c[3])
        : "r"(a[0]), "r"(a[1]), "r"(a[2]), "r"(a[3]), "r"(b[0]), "r"(b[1]));
}
#define CP16(dst, src) \
    asm volatile("cp.async.cg.shared.global [%0], [%1], 16;" :: "r"(dst), "l"(src) : "memory")
#define CPCOMMIT() asm volatile("cp.async.commit_group;" ::: "memory")
#define CPWAIT0() asm volatile("cp.async.wait_group 0;" ::: "memory")
#define CPWAIT1() asm volatile("cp.async.wait_group 1;" ::: "memory")
#define CPWAIT2() asm volatile("cp.async.wait_group 2;" ::: "memory")

#define SW64(o) ((o) ^ (((o) >> 3) & 0x30))

// split fp32 pair -> bf16 hi pair (ret) + bf16 lo pair (out param)
__device__ __forceinline__ uint32_t split2(float a, float b, uint32_t& lo)
{
    __nv_bfloat16 ha = __float2bfloat16(a);
    __nv_bfloat16 hb = __float2bfloat16(b);
    __nv_bfloat162 l2;
    l2.x = __float2bfloat16(a - __bfloat162float(ha));
    l2.y = __float2bfloat16(b - __bfloat162float(hb));
    lo = *reinterpret_cast<uint32_t*>(&l2);
    __nv_bfloat162 h2; h2.x = ha; h2.y = hb;
    return *reinterpret_cast<uint32_t*>(&h2);
}

// ---------------- token detect + embed ----------------
__global__ void detect_tok_kernel(const int* __restrict__ t)
{
    __shared__ int any;
    if (threadIdx.x == 0) any = 0;
    __syncthreads();
    int local = 0;
    for (int i = threadIdx.x; i < S / 2; i += blockDim.x)
        if (t[2 * i + 1] != 0) local = 1;
    if (local) any = 1;
    __syncthreads();
    if (threadIdx.x == 0) g_tok64 = (any == 0) ? 1 : 0;
}

__global__ void embed_kernel(const int* __restrict__ tok,
                             const float* __restrict__ te,
                             const float* __restrict__ pe,
                             float* __restrict__ x)
{
    const int s = blockIdx.x;
    const int t = g_tok64 ? tok[2 * s] : tok[s];
    const float4* e = (const float4*)(te + (size_t)t * D);
    const float4* p = (const float4*)(pe + (size_t)s * D);
    float4*       o = (float4*)(x + (size_t)s * D);
    for (int i = threadIdx.x; i < D / 4; i += blockDim.x) {
        float4 a = e[i], b = p[i];
        o[i] = make_float4(a.x + b.x, a.y + b.y, a.z + b.z, a.w + b.w);
    }
}

// ---------------- weight convert + transpose: fp32 [K][N] -> bf16 hi/lo [N][K] ----------------
__global__ void convT_kernel(const float* __restrict__ src, int K, int N,
                             BF16* __restrict__ dhi, BF16* __restrict__ dlo)
{
    __shared__ float t[32][33];
    const int n0 = blockIdx.x * 32, k0 = blockIdx.y * 32;
    const int tx = threadIdx.x & 31, ty = threadIdx.x >> 5;
#pragma unroll
    for (int r = 0; r < 4; r++)
        t[ty + 8 * r][tx] = src[(size_t)(k0 + ty + 8 * r) * N + n0 + tx];
    __syncthreads();
#pragma unroll
    for (int r = 0; r < 4; r++) {
        const int n = n0 + ty + 8 * r, k = k0 + tx;
        const float v = t[tx][ty + 8 * r];
        const BF16 hv = __float2bfloat16(v);
        dhi[(size_t)n * K + k] = hv;
        dlo[(size_t)n * K + k] = __float2bfloat16(v - __bfloat162float(hv));
    }
}

// ---------------- bf16 transpose for V: [S][D] head slice -> [H][HD][S] ----------------
__global__ void vtrans_kernel(const BF16* __restrict__ vh, const BF16* __restrict__ vl,
                              BF16* __restrict__ vth, BF16* __restrict__ vtl)
{
    __shared__ BF16 th[32][33], tl[32][33];
    const int h = blockIdx.z;
    const int d0 = blockIdx.x * 32, s0 = blockIdx.y * 32;
    const int tx = threadIdx.x & 31, ty = threadIdx.x >> 5;
#pragma unroll
    for (int r = 0; r < 4; r++) {
        const size_t src = (size_t)(s0 + ty + 8 * r) * D + h * HD + d0 + tx;
        th[ty + 8 * r][tx] = vh[src];
        tl[ty + 8 * r][tx] = vl[src];
    }
    __syncthreads();
#pragma unroll
    for (int r = 0; r < 4; r++) {
        const size_t dst = ((size_t)h * HD + d0 + ty + 8 * r) * S + s0 + tx;
        vth[dst] = th[tx][ty + 8 * r];
        vtl[dst] = tl[tx][ty + 8 * r];
    }
}

// ---------------- layernorm: fp32 in -> bf16 hi/lo out ----------------
__global__ void ln_kernel(const float* __restrict__ x,
                          const float* __restrict__ g,
                          const float* __restrict__ b,
                          BF16* __restrict__ oh, BF16* __restrict__ ol)
{
    __shared__ float r1[8], r2[8];
    __shared__ float s_mean, s_inv;
    const int s   = blockIdx.x;
    const int tid = threadIdx.x;
    const float4* xr = (const float4*)(x + (size_t)s * D);
    float4 v0 = xr[tid];
    float4 v1 = xr[tid + 256];
    float sum = v0.x + v0.y + v0.z + v0.w + v1.x + v1.y + v1.z + v1.w;
    float sq  = v0.x * v0.x + v0.y * v0.y + v0.z * v0.z + v0.w * v0.w
              + v1.x * v1.x + v1.y * v1.y + v1.z * v1.z + v1.w * v1.w;
#pragma unroll
    for (int o = 16; o; o >>= 1) {
        sum += __shfl_xor_sync(0xffffffffu, sum, o);
        sq  += __shfl_xor_sync(0xffffffffu, sq,  o);
    }
    const int w = tid >> 5;
    if ((tid & 31) == 0) { r1[w] = sum; r2[w] = sq; }
    __syncthreads();
    if (tid == 0) {
        float ts = 0.f, tq = 0.f;
#pragma unroll
        for (int i = 0; i < 8; i++) { ts += r1[i]; tq += r2[i]; }
        const float mean = ts / (float)D;
        const float var  = tq / (float)D - mean * mean;
        s_mean = mean;
        s_inv  = rsqrtf(var + LN_EPS);
    }
    __syncthreads();
    const float mean = s_mean, inv = s_inv;
    const float4* gg = (const float4*)g;
    const float4* bb = (const float4*)b;
    float4 g0 = gg[tid], g1 = gg[tid + 256];
    float4 b0 = bb[tid], b1 = bb[tid + 256];
    float o00 = (v0.x - mean) * inv * g0.x + b0.x;
    float o01 = (v0.y - mean) * inv * g0.y + b0.y;
    float o02 = (v0.z - mean) * inv * g0.z + b0.z;
    float o03 = (v0.w - mean) * inv * g0.w + b0.w;
    float o10 = (v1.x - mean) * inv * g1.x + b1.x;
    float o11 = (v1.y - mean) * inv * g1.y + b1.y;
    float o12 = (v1.z - mean) * inv * g1.z + b1.z;
    float o13 = (v1.w - mean) * inv * g1.w + b1.w;
    uint32_t l0, l1, l2, l3;
    const uint32_t h0 = split2(o00, o01, l0);
    const uint32_t h1 = split2(o02, o03, l1);
    const uint32_t h2 = split2(o10, o11, l2);
    const uint32_t h3 = split2(o12, o13, l3);
    const size_t e0 = (size_t)s * D + tid * 4;
    *(uint2*)(oh + e0)        = make_uint2(h0, h1);
    *(uint2*)(ol + e0)        = make_uint2(l0, l1);
    *(uint2*)(oh + e0 + 1024) = make_uint2(h2, h3);
    *(uint2*)(ol + e0 + 1024) = make_uint2(l2, l3);
}

// ---------------- softmax: fp32 rows -> bf16 hi/lo prob rows ----------------
__global__ void softmax_kernel(const float* __restrict__ sc,
                               BF16* __restrict__ ph, BF16* __restrict__ pl)
{
    __shared__ float r1[8];
    __shared__ float s_max, s_inv;
    const int tid = threadIdx.x;
    const float* r = sc + (size_t)blockIdx.x * S;
    float4 v0 = ((const float4*)r)[tid];
    float4 v1 = ((const float4*)r)[tid + 256];
    float mx = fmaxf(fmaxf(fmaxf(v0.x, v0.y), fmaxf(v0.z, v0.w)),
                     fmaxf(fmaxf(v1.x, v1.y), fmaxf(v1.z, v1.w)));
#pragma unroll
    for (int o = 16; o; o >>= 1) mx = fmaxf(mx, __shfl_xor_sync(0xffffffffu, mx, o));
    const int w = tid >> 5;
    if ((tid & 31) == 0) r1[w] = mx;
    __syncthreads();
    if (tid == 0) {
        float m = r1[0];
#pragma unroll
        for (int i = 1; i < 8; i++) m = fmaxf(m, r1[i]);
        s_max = m;
    }
    __syncthreads();
    mx = s_max;
    v0.x = expf(v0.x - mx); v0.y = expf(v0.y - mx);
    v0.z = expf(v0.z - mx); v0.w = expf(v0.w - mx);
    v1.x = expf(v1.x - mx); v1.y = expf(v1.y - mx);
    v1.z = expf(v1.z - mx); v1.w = expf(v1.w - mx);
    float sum = v0.x + v0.y + v0.z + v0.w + v1.x + v1.y + v1.z + v1.w;
#pragma unroll
    for (int o = 16; o; o >>= 1) sum += __shfl_xor_sync(0xffffffffu, sum, o);
    __syncthreads();
    if ((tid & 31) == 0) r1[w] = sum;
    __syncthreads();
    if (tid == 0) {
        float t = 0.f;
#pragma unroll
        for (int i = 0; i < 8; i++) t += r1[i];
        s_inv = 1.0f / t;
    }
    __syncthreads();
    const float inv = s_inv;
    v0.x *= inv; v0.y *= inv; v0.z *= inv; v0.w *= inv;
    v1.x *= inv; v1.y *= inv; v1.z *= inv; v1.w *= inv;
    uint32_t l0, l1, l2, l3;
    const uint32_t h0 = split2(v0.x, v0.y, l0);
    const uint32_t h1 = split2(v0.z, v0.w, l1);
    const uint32_t h2 = split2(v1.x, v1.y, l2);
    const uint32_t h3 = split2(v1.z, v1.w, l3);
    const size_t e0 = (size_t)blockIdx.x * S + tid * 4;
    *(uint2*)(ph + e0)        = make_uint2(h0, h1);
    *(uint2*)(pl + e0)        = make_uint2(l0, l1);
    *(uint2*)(ph + e0 + 1024) = make_uint2(h2, h3);
    *(uint2*)(pl + e0 + 1024) = make_uint2(l2, l3);
}

// ---------------- cp.async pipelined bf16-split GEMM ----------------
// C[z] = epi(alpha * A[z] @ B[z]^T (+ Res))
// A: bf16 hi/lo [M][K] row-major (lda, z-stride sA elements)
// B: bf16 hi/lo [N][K] row-major (ldb, z-stride sB)
// OUT: 0 = fp32, 1 = fp32+Res, 2 = bf16 hi/lo split, 3 = bf16 split after relu
#define OUT_F32    0
#define OUT_F32RES 1
#define OUT_BF16   2
#define OUT_RELU   3

#define STAGES 3
#define STAGE_BYTES 32768
#define GEMM_SMEM (STAGES * STAGE_BYTES)

template <int OUT>
__global__ void __launch_bounds__(256, 2)
tc_gemm(const BF16* __restrict__ Ah, const BF16* __restrict__ Al, int lda, long long sA,
        const BF16* __restrict__ Bh, const BF16* __restrict__ Bl, int ldb, long long sB,
        const float* __restrict__ Res,
        float* __restrict__ Cf, BF16* __restrict__ Chi, BF16* __restrict__ Clo,
        int ldc, long long sC, int K, float alpha)
{
    extern __shared__ char smem[];
    const uint32_t sb = smem_u32(smem);
    const int tid = threadIdx.x, wid = tid >> 5, lane = tid & 31;
    const int z = blockIdx.z;
    Ah += (size_t)z * sA;  Al += (size_t)z * sA;
    Bh += (size_t)z * sB;  Bl += (size_t)z * sB;
    const int m0 = blockIdx.y * 128;
    const int n0 = blockIdx.x * 128;
    const int wm = (wid & 3) * 32;
    const int wn = (wid >> 2) * 64;

    // loader thread mapping: rowL in [0,64), cL = 16B chunk in [0,4)
    const int rowL = tid >> 2;
    const int cL   = tid & 3;
    const uint32_t o0 = SW64((uint32_t)(rowL * 64 + cL * 16));
    const uint32_t o1 = SW64((uint32_t)((rowL + 64) * 64 + cL * 16));
    const BF16* aht = Ah + (size_t)(m0 + rowL) * lda + cL * 8;
    const BF16* alt = Al + (size_t)(m0 + rowL) * lda + cL * 8;
    const BF16* bht = Bh + (size_t)(n0 + rowL) * ldb + cL * 8;
    const BF16* blt = Bl + (size_t)(n0 + rowL) * ldb + cL * 8;
    const size_t a64 = (size_t)64 * lda;
    const size_t b64 = (size_t)64 * ldb;

    auto issue = [&](int idx, int s) {
        const uint32_t st = sb + s * STAGE_BYTES;
        const BF16* a1 = aht + idx * 32;
        const BF16* a2 = alt + idx * 32;
        const BF16* b1 = bht + idx * 32;
        const BF16* b2 = blt + idx * 32;
        CP16(st + o0,         a1);
        CP16(st + 8192  + o0, a2);
        CP16(st + 16384 + o0, b1);
        CP16(st + 24576 + o0, b2);
        CP16(st + o1,         a1 + a64);
        CP16(st + 8192  + o1, a2 + a64);
        CP16(st + 16384 + o1, b1 + b64);
        CP16(st + 24576 + o1, b2 + b64);
        CPCOMMIT();
    };

    float acc[2][8][4];
#pragma unroll
    for (int i = 0; i < 2; i++)
#pragma unroll
        for (int j = 0; j < 8; j++)
#pragma unroll
            for (int q = 0; q < 4; q++) acc[i][j][q] = 0.f;

    // ldmatrix lane address components
    const int a_row = lane & 15;
    const int a_kc  = (lane >> 4) * 8;
    const int b_row = (lane & 7) + (lane >> 4) * 8;
    const int b_kc  = ((lane >> 3) & 1) * 8;

    const int nch = K >> 5;
    issue(0, 0);
    issue(1, 1);

    for (int i = 0; i < nch; i++) {
        if (i + 2 < nch) { issue(i + 2, (i + 2) % STAGES); CPWAIT2(); }
        else if (i + 1 < nch) { CPWAIT1(); }
        else { CPWAIT0(); }
        __syncthreads();

        const uint32_t st  = sb + (i % STAGES) * STAGE_BYTES;
        const uint32_t AhS = st, AlS = st + 8192, BhS = st + 16384, BlS = st + 24576;
#pragma unroll
        for (int ks = 0; ks < 2; ks++) {
            uint32_t ah[2][4], al[2][4];
#pragma unroll
            for (int mf = 0; mf < 2; mf++) {
                const uint32_t swo = SW64((uint32_t)((wm + mf * 16 + a_row) * 64
                                                     + (ks * 16 + a_kc) * 2));
                ldm_x4(ah[mf], AhS + swo);
                ldm_x4(al[mf], AlS + swo);
            }
#pragma unroll
            for (int p = 0; p < 4; p++) {
                uint32_t bh[4], bl[4];
                const uint32_t swo = SW64((uint32_t)((wn + p * 16 + b_row) * 64
                                                     + (ks * 16 + b_kc) * 2));
                ldm_x4(bh, BhS + swo);
                ldm_x4(bl, BlS + swo);
#pragma unroll
                for (int mf = 0; mf < 2; mf++) {
                    mma_bf16(acc[mf][2 * p],     ah[mf], bh);
                    mma_bf16(acc[mf][2 * p + 1], ah[mf], bh + 2);
                    mma_bf16(acc[mf][2 * p],     al[mf], bh);
                    mma_bf16(acc[mf][2 * p + 1], al[mf], bh + 2);
                    mma_bf16(acc[mf][2 * p],     ah[mf], bl);
                    mma_bf16(acc[mf][2 * p + 1], ah[mf], bl + 2);
                }
            }
        }
        __syncthreads();
    }

    // ---------------- epilogue ----------------
    const int r  = lane >> 2;
    const int c2 = (lane & 3) * 2;
#pragma unroll
    for (int mf = 0; mf < 2; mf++) {
#pragma unroll
        for (int hh = 0; hh < 2; hh++) {
            const int m = m0 + wm + mf * 16 + r + 8 * hh;
            const size_t rofs = (size_t)z * sC + (size_t)m * ldc + n0 + wn;
#pragma unroll
            for (int nf = 0; nf < 8; nf++) {
                float x0 = acc[mf][nf][2 * hh]     * alpha;
                float x1 = acc[mf][nf][2 * hh + 1] * alpha;
                const int nn = nf * 8 + c2;
                if (OUT == OUT_F32RES) {
                    const float2 rr = *(const float2*)(Res + (size_t)m * ldc + n0 + wn + nn);
                    x0 += rr.x; x1 += rr.y;
                } else if (OUT == OUT_RELU) {
                    x0 = fmaxf(x0, 0.f); x1 = fmaxf(x1, 0.f);
                }
                if (OUT == OUT_F32 || OUT == OUT_F32RES) {
                    *(float2*)(Cf + rofs + nn) = make_float2(x0, x1);
                } else {
                    uint32_t lo;
                    const uint32_t hi = split2(x0, x1, lo);
                    *(uint32_t*)(Chi + rofs + nn) = hi;
                    *(uint32_t*)(Clo + rofs + nn) = lo;
                }
            }
        }
    }
}

// ---------------- launch ----------------
extern "C" void kernel_launch(void* const* d_in, const int* in_sizes, int n_in,
                              void* d_out, int out_size)
{
    const int*   tokens = (const int*)d_in[0];
    const float* temb   = (const float*)d_in[1];
    const float* pemb   = (const float*)d_in[2];
    const float* wq     = (const float*)d_in[3];
    const float* wk     = (const float*)d_in[4];
    const float* wv     = (const float*)d_in[5];
    const float* wo     = (const float*)d_in[6];
    const float* wfi    = (const float*)d_in[7];
    const float* wfo    = (const float*)d_in[8];
    const float* ln1g   = (const float*)d_in[9];
    const float* ln1b   = (const float*)d_in[10];
    const float* ln2g   = (const float*)d_in[11];
    const float* ln2b   = (const float*)d_in[12];
    const float* lnfg   = (const float*)d_in[13];
    const float* lnfb   = (const float*)d_in[14];
    const float* wout   = (const float*)d_in[15];
    float*       out    = (float*)d_out;

    float *px, *px2, *px3, *pat;
    BF16 *phh, *phl, *ph2h, *ph2l, *phfh, *phfl;
    BF16 *pqkvh, *pqkvl, *pvth, *pvtl, *pph, *ppl, *paoh, *paol, *pffh, *pffl;
    BF16 *pwqkvTh, *pwqkvTl, *pwoTh, *pwoTl, *pwfiTh, *pwfiTl, *pwfoTh, *pwfoTl, *pwoutTh, *pwoutTl;
    cudaGetSymbolAddress((void**)&px,   g_x);
    cudaGetSymbolAddress((void**)&px2,  g_x2);
    cudaGetSymbolAddress((void**)&px3,  g_x3);
    cudaGetSymbolAddress((void**)&pat,  g_at);
    cudaGetSymbolAddress((void**)&phh,  g_hh);
    cudaGetSymbolAddress((void**)&phl,  g_hl);
    cudaGetSymbolAddress((void**)&ph2h, g_h2h);
    cudaGetSymbolAddress((void**)&ph2l, g_h2l);
    cudaGetSymbolAddress((void**)&phfh, g_hfh);
    cudaGetSymbolAddress((void**)&phfl, g_hfl);
    cudaGetSymbolAddress((void**)&pqkvh, g_qkvh);
    cudaGetSymbolAddress((void**)&pqkvl, g_qkvl);
    cudaGetSymbolAddress((void**)&pvth, g_vth);
    cudaGetSymbolAddress((void**)&pvtl, g_vtl);
    cudaGetSymbolAddress((void**)&pph,  g_ph);
    cudaGetSymbolAddress((void**)&ppl,  g_pl);
    cudaGetSymbolAddress((void**)&paoh, g_aoh);
    cudaGetSymbolAddress((void**)&paol, g_aol);
    cudaGetSymbolAddress((void**)&pffh, g_ffh);
    cudaGetSymbolAddress((void**)&pffl, g_ffl);
    cudaGetSymbolAddress((void**)&pwqkvTh, g_wqkvTh);
    cudaGetSymbolAddress((void**)&pwqkvTl, g_wqkvTl);
    cudaGetSymbolAddress((void**)&pwoTh, g_woTh);
    cudaGetSymbolAddress((void**)&pwoTl, g_woTl);
    cudaGetSymbolAddress((void**)&pwfiTh, g_wfiTh);
    cudaGetSymbolAddress((void**)&pwfiTl, g_wfiTl);
    cudaGetSymbolAddress((void**)&pwfoTh, g_wfoTh);
    cudaGetSymbolAddress((void**)&pwfoTl, g_wfoTl);
    cudaGetSymbolAddress((void**)&pwoutTh, g_woutTh);
    cudaGetSymbolAddress((void**)&pwoutTl, g_woutTl);

    cudaFuncSetAttribute(tc_gemm<OUT_F32>,
                         cudaFuncAttributeMaxDynamicSharedMemorySize, GEMM_SMEM);
    cudaFuncSetAttribute(tc_gemm<OUT_F32RES>,
                         cudaFuncAttributeMaxDynamicSharedMemorySize, GEMM_SMEM);
    cudaFuncSetAttribute(tc_gemm<OUT_BF16>,
                         cudaFuncAttributeMaxDynamicSharedMemorySize, GEMM_SMEM);
    cudaFuncSetAttribute(tc_gemm<OUT_RELU>,
                         cudaFuncAttributeMaxDynamicSharedMemorySize, GEMM_SMEM);

    detect_tok_kernel<<<1, 256>>>(tokens);
    embed_kernel<<<S, 256>>>(tokens, temb, pemb, px);

    // weight conversions (transpose + bf16 split)
    convT_kernel<<<dim3(D / 32, D / 32), 256>>>(wq, D, D, pwqkvTh,          pwqkvTl);
    convT_kernel<<<dim3(D / 32, D / 32), 256>>>(wk, D, D, pwqkvTh + DD,     pwqkvTl + DD);
    convT_kernel<<<dim3(D / 32, D / 32), 256>>>(wv, D, D, pwqkvTh + 2 * DD, pwqkvTl + 2 * DD);
    convT_kernel<<<dim3(D / 32, D / 32), 256>>>(wo, D, D, pwoTh, pwoTl);
    convT_kernel<<<dim3(FF / 32, D / 32), 256>>>(wfi, D, FF, pwfiTh, pwfiTl);
    convT_kernel<<<dim3(D / 32, FF / 32), 256>>>(wfo, FF, D, pwfoTh, pwfoTl);
    convT_kernel<<<dim3(VOC / 32, D / 32), 256>>>(wout, D, VOC, pwoutTh, pwoutTl);

    // attention block
    ln_kernel<<<S, 256>>>(px, ln1g, ln1b, phh, phl);
    // fused QKV: z in {0,1,2}
    tc_gemm<OUT_BF16><<<dim3(D / 128, S / 128, 3), 256, GEMM_SMEM>>>(
        phh, phl, D, 0, pwqkvTh, pwqkvTl, D, DD, nullptr,
        nullptr, pqkvh, pqkvl, D, SD, D, 1.f);
    vtrans_kernel<<<dim3(HD / 32, S / 32, H), 256>>>(pqkvh + 2 * SD, pqkvl + 2 * SD, pvth, pvtl);
    // scores = (1/sqrt(hd)) Q K^T  per head
    tc_gemm<OUT_F32><<<dim3(S / 128, S / 128, H), 256, GEMM_SMEM>>>(
        pqkvh, pqkvl, D, HD, pqkvh + SD, pqkvl + SD, D, HD, nullptr,
        pat, nullptr, nullptr, S, (long long)S * S, HD, 0.08838834764831845f);
    softmax_kernel<<<H * S, 256>>>(pat, pph, ppl);
    // attn_out = P @ V  per head  (B = V^T slices [HD][S])
    tc_gemm<OUT_BF16><<<dim3(1, S / 128, H), 256, GEMM_SMEM>>>(
        pph, ppl, S, (long long)S * S, pvth, pvtl, S, (long long)HD * S, nullptr,
        nullptr, paoh, paol, D, HD, S, 1.f);
    // x2 = x + attn_out @ Wo
    tc_gemm<OUT_F32RES><<<dim3(D / 128, S / 128, 1), 256, GEMM_SMEM>>>(
        paoh, paol, D, 0, pwoTh, pwoTl, D, 0, px,
        px2, nullptr, nullptr, D, 0, D, 1.f);

    // FFN block
    ln_kernel<<<S, 256>>>(px2, ln2g, ln2b, ph2h, ph2l);
    tc_gemm<OUT_RELU><<<dim3(FF / 128, S / 128, 1), 256, GEMM_SMEM>>>(
        ph2h, ph2l, D, 0, pwfiTh, pwfiTl, D, 0, nullptr,
        nullptr, pffh, pffl, FF, 0, D, 1.f);
    tc_gemm<OUT_F32RES><<<dim3(D / 128, S / 128, 1), 256, GEMM_SMEM>>>(
        pffh, pffl, FF, 0, pwfoTh, pwfoTl, FF, 0, px2,
        px3, nullptr, nullptr, D, 0, FF, 1.f);

    // final LN + logits
    ln_kernel<<<S, 256>>>(px3, lnfg, lnfb, phfh, phfl);
    tc_gemm<OUT_F32><<<dim3(VOC / 128, S / 128, 1), 256, GEMM_SMEM>>>(
        phfh, phfl, D, 0, pwoutTh, pwoutTl, D, 0, nullptr,
        out, nullptr, nullptr, VOC, 0, D, 1.f);
}

// round 5
// speedup vs baseline: 3.2371x; 1.0346x over previous
#include <cuda_runtime.h>
#include <cuda_bf16.h>
#include <stdint.h>
#include <math.h>

typedef __nv_bfloat16 BF16;

// ---------------- dimensions ----------------
#define S   2048
#define D   2048
#define H   16
#define HD  128
#define FF  8192
#define VOC 32000
#define LN_EPS 1e-5f
#define SD  (S * D)
#define DD  (D * D)

// ---------------- scratch ----------------
__device__ float g_x  [SD];
__device__ float g_x2 [SD];
__device__ float g_x3 [SD];
__device__ float g_at [H * S * S];

__device__ BF16 g_hh [SD],  g_hl [SD];
__device__ BF16 g_h2h[SD],  g_h2l[SD];
__device__ BF16 g_hfh[SD],  g_hfl[SD];
__device__ BF16 g_qkvh[3 * SD], g_qkvl[3 * SD];
__device__ BF16 g_vth[SD],  g_vtl[SD];
__device__ BF16 g_ph [H * S * S], g_pl [H * S * S];
__device__ BF16 g_aoh[SD],  g_aol[SD];
__device__ BF16 g_ffh[S * FF], g_ffl[S * FF];

__device__ BF16 g_wqkvTh[3 * DD], g_wqkvTl[3 * DD];
__device__ BF16 g_woTh[DD],       g_woTl[DD];
__device__ BF16 g_wfiTh[D * FF],  g_wfiTl[D * FF];
__device__ BF16 g_wfoTh[D * FF],  g_wfoTl[D * FF];
__device__ BF16 g_woutTh[(size_t)D * VOC], g_woutTl[(size_t)D * VOC];

__device__ int g_tok64;

// ---------------- PTX helpers (plain sm_103-legal) ----------------
__device__ __forceinline__ uint32_t smem_u32(const void* p) {
    uint32_t a;
    asm("{ .reg .u64 t; cvta.to.shared.u64 t, %1; cvt.u32.u64 %0, t; }" : "=r"(a) : "l"(p));
    return a;
}
__device__ __forceinline__ void ldm_x4(uint32_t* r, uint32_t addr) {
    asm volatile("ldmatrix.sync.aligned.m8n8.x4.shared.b16 {%0,%1,%2,%3}, [%4];"
                 : "=r"(r[0]), "=r"(r[1]), "=r"(r[2]), "=r"(r[3]) : "r"(addr));
}
__device__ __forceinline__ void mma_bf16(float* c, const uint32_t* a, const uint32_t* b) {
    asm volatile(
        "mma.sync.aligned.m16n8k16.row.col.f32.bf16.bf16.f32 "
        "{%0,%1,%2,%3}, {%4,%5,%6,%7}, {%8,%9}, {%0,%1,%2,%3};"
        : "+f"(c[0]), "+f"(c[1]), "+f"(c[2]), "+f"(c[3])
        : "r"(a[0]), "r"(a[1]), "r"(a[2]), "r"(a[3]), "r"(b[0]), "r"(b[1]));
}
#define CP16(dst, src) \
    asm volatile("cp.async.cg.shared.global [%0], [%1], 16;" :: "r"(dst), "l"(src) : "memory")
#define CPCOMMIT() asm volatile("cp.async.commit_group;" ::: "memory")
#define CPWAIT0() asm volatile("cp.async.wait_group 0;" ::: "memory")
#define CPWAIT1() asm volatile("cp.async.wait_group 1;" ::: "memory")

#define SW64(o) ((o) ^ (((o) >> 3) & 0x30))

// split fp32 pair -> bf16 hi pair (ret) + bf16 lo pair (out param)
__device__ __forceinline__ uint32_t split2(float a, float b, uint32_t& lo)
{
    __nv_bfloat16 ha = __float2bfloat16(a);
    __nv_bfloat16 hb = __float2bfloat16(b);
    __nv_bfloat162 l2;
    l2.x = __float2bfloat16(a - __bfloat162float(ha));
    l2.y = __float2bfloat16(b - __bfloat162float(hb));
    lo = *reinterpret_cast<uint32_t*>(&l2);
    __nv_bfloat162 h2; h2.x = ha; h2.y = hb;
    return *reinterpret_cast<uint32_t*>(&h2);
}

// ---------------- token detect + embed ----------------
__global__ void detect_tok_kernel(const int* __restrict__ t)
{
    __shared__ int any;
    if (threadIdx.x == 0) any = 0;
    __syncthreads();
    int local = 0;
    for (int i = threadIdx.x; i < S / 2; i += blockDim.x)
        if (t[2 * i + 1] != 0) local = 1;
    if (local) any = 1;
    __syncthreads();
    if (threadIdx.x == 0) g_tok64 = (any == 0) ? 1 : 0;
}

__global__ void embed_kernel(const int* __restrict__ tok,
                             const float* __restrict__ te,
                             const float* __restrict__ pe,
                             float* __restrict__ x)
{
    const int s = blockIdx.x;
    const int t = g_tok64 ? tok[2 * s] : tok[s];
    const float4* e = (const float4*)(te + (size_t)t * D);
    const float4* p = (const float4*)(pe + (size_t)s * D);
    float4*       o = (float4*)(x + (size_t)s * D);
    for (int i = threadIdx.x; i < D / 4; i += blockDim.x) {
        float4 a = e[i], b = p[i];
        o[i] = make_float4(a.x + b.x, a.y + b.y, a.z + b.z, a.w + b.w);
    }
}

// ---------------- weight convert + transpose: fp32 [K][N] -> bf16 hi/lo [N][K] ----------------
__global__ void convT_kernel(const float* __restrict__ src, int K, int N,
                             BF16* __restrict__ dhi, BF16* __restrict__ dlo)
{
    __shared__ float t[32][33];
    const int n0 = blockIdx.x * 32, k0 = blockIdx.y * 32;
    const int tx = threadIdx.x & 31, ty = threadIdx.x >> 5;
#pragma unroll
    for (int r = 0; r < 4; r++)
        t[ty + 8 * r][tx] = src[(size_t)(k0 + ty + 8 * r) * N + n0 + tx];
    __syncthreads();
#pragma unroll
    for (int r = 0; r < 4; r++) {
        const int n = n0 + ty + 8 * r, k = k0 + tx;
        const float v = t[tx][ty + 8 * r];
        const BF16 hv = __float2bfloat16(v);
        dhi[(size_t)n * K + k] = hv;
        dlo[(size_t)n * K + k] = __float2bfloat16(v - __bfloat162float(hv));
    }
}

// ---------------- bf16 transpose for V: [S][D] head slice -> [H][HD][S] ----------------
__global__ void vtrans_kernel(const BF16* __restrict__ vh, const BF16* __restrict__ vl,
                              BF16* __restrict__ vth, BF16* __restrict__ vtl)
{
    __shared__ BF16 th[32][33], tl[32][33];
    const int h = blockIdx.z;
    const int d0 = blockIdx.x * 32, s0 = blockIdx.y * 32;
    const int tx = threadIdx.x & 31, ty = threadIdx.x >> 5;
#pragma unroll
    for (int r = 0; r < 4; r++) {
        const size_t src = (size_t)(s0 + ty + 8 * r) * D + h * HD + d0 + tx;
        th[ty + 8 * r][tx] = vh[src];
        tl[ty + 8 * r][tx] = vl[src];
    }
    __syncthreads();
#pragma unroll
    for (int r = 0; r < 4; r++) {
        const size_t dst = ((size_t)h * HD + d0 + ty + 8 * r) * S + s0 + tx;
        vth[dst] = th[tx][ty + 8 * r];
        vtl[dst] = tl[tx][ty + 8 * r];
    }
}

// ---------------- layernorm: fp32 in -> bf16 hi/lo out ----------------
__global__ void ln_kernel(const float* __restrict__ x,
                          const float* __restrict__ g,
                          const float* __restrict__ b,
                          BF16* __restrict__ oh, BF16* __restrict__ ol)
{
    __shared__ float r1[8], r2[8];
    __shared__ float s_mean, s_inv;
    const int s   = blockIdx.x;
    const int tid = threadIdx.x;
    const float4* xr = (const float4*)(x + (size_t)s * D);
    float4 v0 = xr[tid];
    float4 v1 = xr[tid + 256];
    float sum = v0.x + v0.y + v0.z + v0.w + v1.x + v1.y + v1.z + v1.w;
    float sq  = v0.x * v0.x + v0.y * v0.y + v0.z * v0.z + v0.w * v0.w
              + v1.x * v1.x + v1.y * v1.y + v1.z * v1.z + v1.w * v1.w;
#pragma unroll
    for (int o = 16; o; o >>= 1) {
        sum += __shfl_xor_sync(0xffffffffu, sum, o);
        sq  += __shfl_xor_sync(0xffffffffu, sq,  o);
    }
    const int w = tid >> 5;
    if ((tid & 31) == 0) { r1[w] = sum; r2[w] = sq; }
    __syncthreads();
    if (tid == 0) {
        float ts = 0.f, tq = 0.f;
#pragma unroll
        for (int i = 0; i < 8; i++) { ts += r1[i]; tq += r2[i]; }
        const float mean = ts / (float)D;
        const float var  = tq / (float)D - mean * mean;
        s_mean = mean;
        s_inv  = rsqrtf(var + LN_EPS);
    }
    __syncthreads();
    const float mean = s_mean, inv = s_inv;
    const float4* gg = (const float4*)g;
    const float4* bb = (const float4*)b;
    float4 g0 = gg[tid], g1 = gg[tid + 256];
    float4 b0 = bb[tid], b1 = bb[tid + 256];
    float o00 = (v0.x - mean) * inv * g0.x + b0.x;
    float o01 = (v0.y - mean) * inv * g0.y + b0.y;
    float o02 = (v0.z - mean) * inv * g0.z + b0.z;
    float o03 = (v0.w - mean) * inv * g0.w + b0.w;
    float o10 = (v1.x - mean) * inv * g1.x + b1.x;
    float o11 = (v1.y - mean) * inv * g1.y + b1.y;
    float o12 = (v1.z - mean) * inv * g1.z + b1.z;
    float o13 = (v1.w - mean) * inv * g1.w + b1.w;
    uint32_t l0, l1, l2, l3;
    const uint32_t h0 = split2(o00, o01, l0);
    const uint32_t h1 = split2(o02, o03, l1);
    const uint32_t h2 = split2(o10, o11, l2);
    const uint32_t h3 = split2(o12, o13, l3);
    const size_t e0 = (size_t)s * D + tid * 4;
    *(uint2*)(oh + e0)        = make_uint2(h0, h1);
    *(uint2*)(ol + e0)        = make_uint2(l0, l1);
    *(uint2*)(oh + e0 + 1024) = make_uint2(h2, h3);
    *(uint2*)(ol + e0 + 1024) = make_uint2(l2, l3);
}

// ---------------- softmax: fp32 rows -> bf16 hi/lo prob rows ----------------
__global__ void softmax_kernel(const float* __restrict__ sc,
                               BF16* __restrict__ ph, BF16* __restrict__ pl)
{
    __shared__ float r1[8];
    __shared__ float s_max, s_inv;
    const int tid = threadIdx.x;
    const float* r = sc + (size_t)blockIdx.x * S;
    float4 v0 = ((const float4*)r)[tid];
    float4 v1 = ((const float4*)r)[tid + 256];
    float mx = fmaxf(fmaxf(fmaxf(v0.x, v0.y), fmaxf(v0.z, v0.w)),
                     fmaxf(fmaxf(v1.x, v1.y), fmaxf(v1.z, v1.w)));
#pragma unroll
    for (int o = 16; o; o >>= 1) mx = fmaxf(mx, __shfl_xor_sync(0xffffffffu, mx, o));
    const int w = tid >> 5;
    if ((tid & 31) == 0) r1[w] = mx;
    __syncthreads();
    if (tid == 0) {
        float m = r1[0];
#pragma unroll
        for (int i = 1; i < 8; i++) m = fmaxf(m, r1[i]);
        s_max = m;
    }
    __syncthreads();
    mx = s_max;
    v0.x = expf(v0.x - mx); v0.y = expf(v0.y - mx);
    v0.z = expf(v0.z - mx); v0.w = expf(v0.w - mx);
    v1.x = expf(v1.x - mx); v1.y = expf(v1.y - mx);
    v1.z = expf(v1.z - mx); v1.w = expf(v1.w - mx);
    float sum = v0.x + v0.y + v0.z + v0.w + v1.x + v1.y + v1.z + v1.w;
#pragma unroll
    for (int o = 16; o; o >>= 1) sum += __shfl_xor_sync(0xffffffffu, sum, o);
    __syncthreads();
    if ((tid & 31) == 0) r1[w] = sum;
    __syncthreads();
    if (tid == 0) {
        float t = 0.f;
#pragma unroll
        for (int i = 0; i < 8; i++) t += r1[i];
        s_inv = 1.0f / t;
    }
    __syncthreads();
    const float inv = s_inv;
    v0.x *= inv; v0.y *= inv; v0.z *= inv; v0.w *= inv;
    v1.x *= inv; v1.y *= inv; v1.z *= inv; v1.w *= inv;
    uint32_t l0, l1, l2, l3;
    const uint32_t h0 = split2(v0.x, v0.y, l0);
    const uint32_t h1 = split2(v0.z, v0.w, l1);
    const uint32_t h2 = split2(v1.x, v1.y, l2);
    const uint32_t h3 = split2(v1.z, v1.w, l3);
    const size_t e0 = (size_t)blockIdx.x * S + tid * 4;
    *(uint2*)(ph + e0)        = make_uint2(h0, h1);
    *(uint2*)(pl + e0)        = make_uint2(l0, l1);
    *(uint2*)(ph + e0 + 1024) = make_uint2(h2, h3);
    *(uint2*)(pl + e0 + 1024) = make_uint2(l2, l3);
}

// ---------------- cp.async pipelined bf16-split GEMM ----------------
// C[z] = epi(alpha * A[z] @ B[z]^T (+ Res))
// grid: blockIdx.x = M tile (fast-varying -> consecutive CTAs share B tile),
//       blockIdx.y = N tile, blockIdx.z = batch
#define OUT_F32    0
#define OUT_F32RES 1
#define OUT_BF16   2
#define OUT_RELU   3

#define STAGES 3
#define STAGE_BYTES 32768
#define GEMM_SMEM (STAGES * STAGE_BYTES)

template <int OUT>
__global__ void __launch_bounds__(256, 2)
tc_gemm(const BF16* __restrict__ Ah, const BF16* __restrict__ Al, int lda, long long sA,
        const BF16* __restrict__ Bh, const BF16* __restrict__ Bl, int ldb, long long sB,
        const float* __restrict__ Res,
        float* __restrict__ Cf, BF16* __restrict__ Chi, BF16* __restrict__ Clo,
        int ldc, long long sC, int K, float alpha)
{
    extern __shared__ char smem[];
    const uint32_t sb = smem_u32(smem);
    const int tid = threadIdx.x, wid = tid >> 5, lane = tid & 31;
    const int z = blockIdx.z;
    Ah += (size_t)z * sA;  Al += (size_t)z * sA;
    Bh += (size_t)z * sB;  Bl += (size_t)z * sB;
    const int m0 = blockIdx.x * 128;   // M fast-varying
    const int n0 = blockIdx.y * 128;
    const int wm = (wid & 3) * 32;
    const int wn = (wid >> 2) * 64;

    // loader thread mapping: rowL in [0,64), cL = 16B chunk in [0,4)
    const int rowL = tid >> 2;
    const int cL   = tid & 3;
    const uint32_t o0 = SW64((uint32_t)(rowL * 64 + cL * 16));
    const uint32_t o1 = SW64((uint32_t)((rowL + 64) * 64 + cL * 16));
    const BF16* aht = Ah + (size_t)(m0 + rowL) * lda + cL * 8;
    const BF16* alt = Al + (size_t)(m0 + rowL) * lda + cL * 8;
    const BF16* bht = Bh + (size_t)(n0 + rowL) * ldb + cL * 8;
    const BF16* blt = Bl + (size_t)(n0 + rowL) * ldb + cL * 8;
    const size_t a64 = (size_t)64 * lda;
    const size_t b64 = (size_t)64 * ldb;

    auto issue = [&](int idx, int s) {
        const uint32_t st = sb + s * STAGE_BYTES;
        const BF16* a1 = aht + idx * 32;
        const BF16* a2 = alt + idx * 32;
        const BF16* b1 = bht + idx * 32;
        const BF16* b2 = blt + idx * 32;
        CP16(st + o0,         a1);
        CP16(st + 8192  + o0, a2);
        CP16(st + 16384 + o0, b1);
        CP16(st + 24576 + o0, b2);
        CP16(st + o1,         a1 + a64);
        CP16(st + 8192  + o1, a2 + a64);
        CP16(st + 16384 + o1, b1 + b64);
        CP16(st + 24576 + o1, b2 + b64);
        CPCOMMIT();
    };

    float acc[2][8][4];
#pragma unroll
    for (int i = 0; i < 2; i++)
#pragma unroll
        for (int j = 0; j < 8; j++)
#pragma unroll
            for (int q = 0; q < 4; q++) acc[i][j][q] = 0.f;

    // ldmatrix lane address components
    const int a_row = lane & 15;
    const int a_kc  = (lane >> 4) * 8;
    const int b_row = (lane & 7) + (lane >> 4) * 8;
    const int b_kc  = ((lane >> 3) & 1) * 8;

    const int nch = K >> 5;
    issue(0, 0);
    issue(1, 1);

    for (int i = 0; i < nch; i++) {
        if (i + 1 < nch) { CPWAIT1(); } else { CPWAIT0(); }
        __syncthreads();                       // single barrier per chunk:
        if (i + 2 < nch) issue(i + 2, (i + 2) % STAGES);  // overwrites stage (i-1)%3, safe post-sync

        const uint32_t st  = sb + (i % STAGES) * STAGE_BYTES;
        const uint32_t AhS = st, AlS = st + 8192, BhS = st + 16384, BlS = st + 24576;
#pragma unroll
        for (int ks = 0; ks < 2; ks++) {
            uint32_t ah[2][4], al[2][4];
#pragma unroll
            for (int mf = 0; mf < 2; mf++) {
                const uint32_t swo = SW64((uint32_t)((wm + mf * 16 + a_row) * 64
                                                     + (ks * 16 + a_kc) * 2));
                ldm_x4(ah[mf], AhS + swo);
                ldm_x4(al[mf], AlS + swo);
            }
#pragma unroll
            for (int p = 0; p < 4; p++) {
                uint32_t bh[4], bl[4];
                const uint32_t swo = SW64((uint32_t)((wn + p * 16 + b_row) * 64
                                                     + (ks * 16 + b_kc) * 2));
                ldm_x4(bh, BhS + swo);
                ldm_x4(bl, BlS + swo);
#pragma unroll
                for (int mf = 0; mf < 2; mf++) {
                    mma_bf16(acc[mf][2 * p],     ah[mf], bh);
                    mma_bf16(acc[mf][2 * p + 1], ah[mf], bh + 2);
                    mma_bf16(acc[mf][2 * p],     al[mf], bh);
                    mma_bf16(acc[mf][2 * p + 1], al[mf], bh + 2);
                    mma_bf16(acc[mf][2 * p],     ah[mf], bl);
                    mma_bf16(acc[mf][2 * p + 1], ah[mf], bl + 2);
                }
            }
        }
    }

    // ---------------- epilogue ----------------
    const int r  = lane >> 2;
    const int c2 = (lane & 3) * 2;
#pragma unroll
    for (int mf = 0; mf < 2; mf++) {
#pragma unroll
        for (int hh = 0; hh < 2; hh++) {
            const int m = m0 + wm + mf * 16 + r + 8 * hh;
            const size_t rofs = (size_t)z * sC + (size_t)m * ldc + n0 + wn;
#pragma unroll
            for (int nf = 0; nf < 8; nf++) {
                float x0 = acc[mf][nf][2 * hh]     * alpha;
                float x1 = acc[mf][nf][2 * hh + 1] * alpha;
                const int nn = nf * 8 + c2;
                if (OUT == OUT_F32RES) {
                    const float2 rr = *(const float2*)(Res + (size_t)m * ldc + n0 + wn + nn);
                    x0 += rr.x; x1 += rr.y;
                } else if (OUT == OUT_RELU) {
                    x0 = fmaxf(x0, 0.f); x1 = fmaxf(x1, 0.f);
                }
                if (OUT == OUT_F32 || OUT == OUT_F32RES) {
                    *(float2*)(Cf + rofs + nn) = make_float2(x0, x1);
                } else {
                    uint32_t lo;
                    const uint32_t hi = split2(x0, x1, lo);
                    *(uint32_t*)(Chi + rofs + nn) = hi;
                    *(uint32_t*)(Clo + rofs + nn) = lo;
                }
            }
        }
    }
}

// ---------------- launch ----------------
extern "C" void kernel_launch(void* const* d_in, const int* in_sizes, int n_in,
                              void* d_out, int out_size)
{
    const int*   tokens = (const int*)d_in[0];
    const float* temb   = (const float*)d_in[1];
    const float* pemb   = (const float*)d_in[2];
    const float* wq     = (const float*)d_in[3];
    const float* wk     = (const float*)d_in[4];
    const float* wv     = (const float*)d_in[5];
    const float* wo     = (const float*)d_in[6];
    const float* wfi    = (const float*)d_in[7];
    const float* wfo    = (const float*)d_in[8];
    const float* ln1g   = (const float*)d_in[9];
    const float* ln1b   = (const float*)d_in[10];
    const float* ln2g   = (const float*)d_in[11];
    const float* ln2b   = (const float*)d_in[12];
    const float* lnfg   = (const float*)d_in[13];
    const float* lnfb   = (const float*)d_in[14];
    const float* wout   = (const float*)d_in[15];
    float*       out    = (float*)d_out;

    float *px, *px2, *px3, *pat;
    BF16 *phh, *phl, *ph2h, *ph2l, *phfh, *phfl;
    BF16 *pqkvh, *pqkvl, *pvth, *pvtl, *pph, *ppl, *paoh, *paol, *pffh, *pffl;
    BF16 *pwqkvTh, *pwqkvTl, *pwoTh, *pwoTl, *pwfiTh, *pwfiTl, *pwfoTh, *pwfoTl, *pwoutTh, *pwoutTl;
    cudaGetSymbolAddress((void**)&px,   g_x);
    cudaGetSymbolAddress((void**)&px2,  g_x2);
    cudaGetSymbolAddress((void**)&px3,  g_x3);
    cudaGetSymbolAddress((void**)&pat,  g_at);
    cudaGetSymbolAddress((void**)&phh,  g_hh);
    cudaGetSymbolAddress((void**)&phl,  g_hl);
    cudaGetSymbolAddress((void**)&ph2h, g_h2h);
    cudaGetSymbolAddress((void**)&ph2l, g_h2l);
    cudaGetSymbolAddress((void**)&phfh, g_hfh);
    cudaGetSymbolAddress((void**)&phfl, g_hfl);
    cudaGetSymbolAddress((void**)&pqkvh, g_qkvh);
    cudaGetSymbolAddress((void**)&pqkvl, g_qkvl);
    cudaGetSymbolAddress((void**)&pvth, g_vth);
    cudaGetSymbolAddress((void**)&pvtl, g_vtl);
    cudaGetSymbolAddress((void**)&pph,  g_ph);
    cudaGetSymbolAddress((void**)&ppl,  g_pl);
    cudaGetSymbolAddress((void**)&paoh, g_aoh);
    cudaGetSymbolAddress((void**)&paol, g_aol);
    cudaGetSymbolAddress((void**)&pffh, g_ffh);
    cudaGetSymbolAddress((void**)&pffl, g_ffl);
    cudaGetSymbolAddress((void**)&pwqkvTh, g_wqkvTh);
    cudaGetSymbolAddress((void**)&pwqkvTl, g_wqkvTl);
    cudaGetSymbolAddress((void**)&pwoTh, g_woTh);
    cudaGetSymbolAddress((void**)&pwoTl, g_woTl);
    cudaGetSymbolAddress((void**)&pwfiTh, g_wfiTh);
    cudaGetSymbolAddress((void**)&pwfiTl, g_wfiTl);
    cudaGetSymbolAddress((void**)&pwfoTh, g_wfoTh);
    cudaGetSymbolAddress((void**)&pwfoTl, g_wfoTl);
    cudaGetSymbolAddress((void**)&pwoutTh, g_woutTh);
    cudaGetSymbolAddress((void**)&pwoutTl, g_woutTl);

    cudaFuncSetAttribute(tc_gemm<OUT_F32>,
                         cudaFuncAttributeMaxDynamicSharedMemorySize, GEMM_SMEM);
    cudaFuncSetAttribute(tc_gemm<OUT_F32RES>,
                         cudaFuncAttributeMaxDynamicSharedMemorySize, GEMM_SMEM);
    cudaFuncSetAttribute(tc_gemm<OUT_BF16>,
                         cudaFuncAttributeMaxDynamicSharedMemorySize, GEMM_SMEM);
    cudaFuncSetAttribute(tc_gemm<OUT_RELU>,
                         cudaFuncAttributeMaxDynamicSharedMemorySize, GEMM_SMEM);

    // ---- side stream for weight conversions not needed until later ----
    cudaStream_t s2;
    cudaStreamCreateWithFlags(&s2, cudaStreamNonBlocking);
    cudaEvent_t evFork, evWo, evWfi, evWfo, evWout;
    cudaEventCreateWithFlags(&evFork, cudaEventDisableTiming);
    cudaEventCreateWithFlags(&evWo,   cudaEventDisableTiming);
    cudaEventCreateWithFlags(&evWfi,  cudaEventDisableTiming);
    cudaEventCreateWithFlags(&evWfo,  cudaEventDisableTiming);
    cudaEventCreateWithFlags(&evWout, cudaEventDisableTiming);

    detect_tok_kernel<<<1, 256>>>(tokens);
    cudaEventRecord(evFork, 0);
    cudaStreamWaitEvent(s2, evFork, 0);

    // side stream: conversions consumed only after the attention phase
    convT_kernel<<<dim3(D / 32, D / 32), 256, 0, s2>>>(wo, D, D, pwoTh, pwoTl);
    cudaEventRecord(evWo, s2);
    convT_kernel<<<dim3(FF / 32, D / 32), 256, 0, s2>>>(wfi, D, FF, pwfiTh, pwfiTl);
    cudaEventRecord(evWfi, s2);
    convT_kernel<<<dim3(D / 32, FF / 32), 256, 0, s2>>>(wfo, FF, D, pwfoTh, pwfoTl);
    cudaEventRecord(evWfo, s2);
    convT_kernel<<<dim3(VOC / 32, D / 32), 256, 0, s2>>>(wout, D, VOC, pwoutTh, pwoutTl);
    cudaEventRecord(evWout, s2);

    // main stream
    embed_kernel<<<S, 256>>>(tokens, temb, pemb, px);
    convT_kernel<<<dim3(D / 32, D / 32), 256>>>(wq, D, D, pwqkvTh,          pwqkvTl);
    convT_kernel<<<dim3(D / 32, D / 32), 256>>>(wk, D, D, pwqkvTh + DD,     pwqkvTl + DD);
    convT_kernel<<<dim3(D / 32, D / 32), 256>>>(wv, D, D, pwqkvTh + 2 * DD, pwqkvTl + 2 * DD);

    // attention block
    ln_kernel<<<S, 256>>>(px, ln1g, ln1b, phh, phl);
    tc_gemm<OUT_BF16><<<dim3(S / 128, D / 128, 3), 256, GEMM_SMEM>>>(
        phh, phl, D, 0, pwqkvTh, pwqkvTl, D, DD, nullptr,
        nullptr, pqkvh, pqkvl, D, SD, D, 1.f);
    vtrans_kernel<<<dim3(HD / 32, S / 32, H), 256>>>(pqkvh + 2 * SD, pqkvl + 2 * SD, pvth, pvtl);
    tc_gemm<OUT_F32><<<dim3(S / 128, S / 128, H), 256, GEMM_SMEM>>>(
        pqkvh, pqkvl, D, HD, pqkvh + SD, pqkvl + SD, D, HD, nullptr,
        pat, nullptr, nullptr, S, (long long)S * S, HD, 0.08838834764831845f);
    softmax_kernel<<<H * S, 256>>>(pat, pph, ppl);
    tc_gemm<OUT_BF16><<<dim3(S / 128, 1, H), 256, GEMM_SMEM>>>(
        pph, ppl, S, (long long)S * S, pvth, pvtl, S, (long long)HD * S, nullptr,
        nullptr, paoh, paol, D, HD, S, 1.f);
    cudaStreamWaitEvent(0, evWo, 0);
    tc_gemm<OUT_F32RES><<<dim3(S / 128, D / 128, 1), 256, GEMM_SMEM>>>(
        paoh, paol, D, 0, pwoTh, pwoTl, D, 0, px,
        px2, nullptr, nullptr, D, 0, D, 1.f);

    // FFN block
    ln_kernel<<<S, 256>>>(px2, ln2g, ln2b, ph2h, ph2l);
    cudaStreamWaitEvent(0, evWfi, 0);
    tc_gemm<OUT_RELU><<<dim3(S / 128, FF / 128, 1), 256, GEMM_SMEM>>>(
        ph2h, ph2l, D, 0, pwfiTh, pwfiTl, D, 0, nullptr,
        nullptr, pffh, pffl, FF, 0, D, 1.f);
    cudaStreamWaitEvent(0, evWfo, 0);
    tc_gemm<OUT_F32RES><<<dim3(S / 128, D / 128, 1), 256, GEMM_SMEM>>>(
        pffh, pffl, FF, 0, pwfoTh, pwfoTl, FF, 0, px2,
        px3, nullptr, nullptr, D, 0, FF, 1.f);

    // final LN + logits
    ln_kernel<<<S, 256>>>(px3, lnfg, lnfb, phfh, phfl);
    cudaStreamWaitEvent(0, evWout, 0);
    tc_gemm<OUT_F32><<<dim3(S / 128, VOC / 128, 1), 256, GEMM_SMEM>>>(
        phfh, phfl, D, 0, pwoutTh, pwoutTl, D, 0, nullptr,
        out, nullptr, nullptr, VOC, 0, D, 1.f);
}

// round 6
// speedup vs baseline: 4.5271x; 1.3985x over previous
#include <cuda_runtime.h>
#include <cuda_bf16.h>
#include <cuda_fp16.h>
#include <stdint.h>
#include <math.h>

typedef __nv_bfloat16 BF16;
typedef __half        HALF;

// ---------------- dimensions ----------------
#define S   2048
#define D   2048
#define H   16
#define HD  128
#define FF  8192
#define VOC 32000
#define LN_EPS 1e-5f
#define SD  (S * D)
#define DD  (D * D)

// ---------------- scratch ----------------
__device__ float g_x  [SD];
__device__ float g_x2 [SD];
__device__ float g_x3 [SD];
__device__ float g_at [H * S * S];

// fp16 activation splits (A-side of 2-pass GEMMs)
__device__ HALF g_hh [SD],  g_hl [SD];
__device__ HALF g_h2h[SD],  g_h2l[SD];
__device__ HALF g_hfh[SD],  g_hfl[SD];
__device__ HALF g_aoh[SD],  g_aol[SD];
__device__ HALF g_ffh[S * FF], g_ffl[S * FF];

// bf16 splits (attention-internal 3-pass operands)
__device__ BF16 g_qkvh[3 * SD], g_qkvl[3 * SD];
__device__ BF16 g_vth[SD],  g_vtl[SD];
__device__ BF16 g_ph [H * S * S], g_pl [H * S * S];

// fp16 weights, hi only (B-side of 2-pass)
__device__ HALF g_wqkvTh[3 * DD];
__device__ HALF g_woTh[DD];
__device__ HALF g_wfiTh[D * FF];
__device__ HALF g_wfoTh[D * FF];
__device__ HALF g_woutTh[(size_t)D * VOC];

__device__ int g_tok64;

// ---------------- PTX helpers (plain sm_103-legal) ----------------
__device__ __forceinline__ uint32_t smem_u32(const void* p) {
    uint32_t a;
    asm("{ .reg .u64 t; cvta.to.shared.u64 t, %1; cvt.u32.u64 %0, t; }" : "=r"(a) : "l"(p));
    return a;
}
__device__ __forceinline__ void ldm_x4(uint32_t* r, uint32_t addr) {
    asm volatile("ldmatrix.sync.aligned.m8n8.x4.shared.b16 {%0,%1,%2,%3}, [%4];"
                 : "=r"(r[0]), "=r"(r[1]), "=r"(r[2]), "=r"(r[3]) : "r"(addr));
}
__device__ __forceinline__ void mma_bf16(float* c, const uint32_t* a, const uint32_t* b) {
    asm volatile(
        "mma.sync.aligned.m16n8k16.row.col.f32.bf16.bf16.f32 "
        "{%0,%1,%2,%3}, {%4,%5,%6,%7}, {%8,%9}, {%0,%1,%2,%3};"
        : "+f"(c[0]), "+f"(c[1]), "+f"(c[2]), "+f"(c[3])
        : "r"(a[0]), "r"(a[1]), "r"(a[2]), "r"(a[3]), "r"(b[0]), "r"(b[1]));
}
__device__ __forceinline__ void mma_fp16(float* c, const uint32_t* a, const uint32_t* b) {
    asm volatile(
        "mma.sync.aligned.m16n8k16.row.col.f32.f16.f16.f32 "
        "{%0,%1,%2,%3}, {%4,%5,%6,%7}, {%8,%9}, {%0,%1,%2,%3};"
        : "+f"(c[0]), "+f"(c[1]), "+f"(c[2]), "+f"(c[3])
        : "r"(a[0]), "r"(a[1]), "r"(a[2]), "r"(a[3]), "r"(b[0]), "r"(b[1]));
}
#define CP16(dst, src) \
    asm volatile("cp.async.cg.shared.global [%0], [%1], 16;" :: "r"(dst), "l"(src) : "memory")
#define CPCOMMIT() asm volatile("cp.async.commit_group;" ::: "memory")
#define CPWAIT0() asm volatile("cp.async.wait_group 0;" ::: "memory")
#define CPWAIT1() asm volatile("cp.async.wait_group 1;" ::: "memory")

#define SW64(o) ((o) ^ (((o) >> 3) & 0x30))

// split fp32 pair -> bf16 hi pair (ret) + bf16 lo pair (out param)
__device__ __forceinline__ uint32_t split2b(float a, float b, uint32_t& lo)
{
    BF16 ha = __float2bfloat16(a);
    BF16 hb = __float2bfloat16(b);
    __nv_bfloat162 l2;
    l2.x = __float2bfloat16(a - __bfloat162float(ha));
    l2.y = __float2bfloat16(b - __bfloat162float(hb));
    lo = *reinterpret_cast<uint32_t*>(&l2);
    __nv_bfloat162 h2; h2.x = ha; h2.y = hb;
    return *reinterpret_cast<uint32_t*>(&h2);
}
// split fp32 pair -> fp16 hi pair + fp16 lo pair
__device__ __forceinline__ uint32_t split2h(float a, float b, uint32_t& lo)
{
    HALF ha = __float2half_rn(a);
    HALF hb = __float2half_rn(b);
    __half2 l2 = __halves2half2(__float2half_rn(a - __half2float(ha)),
                                __float2half_rn(b - __half2float(hb)));
    lo = *reinterpret_cast<uint32_t*>(&l2);
    __half2 h2 = __halves2half2(ha, hb);
    return *reinterpret_cast<uint32_t*>(&h2);
}

// ---------------- token detect + embed ----------------
__global__ void detect_tok_kernel(const int* __restrict__ t)
{
    __shared__ int any;
    if (threadIdx.x == 0) any = 0;
    __syncthreads();
    int local = 0;
    for (int i = threadIdx.x; i < S / 2; i += blockDim.x)
        if (t[2 * i + 1] != 0) local = 1;
    if (local) any = 1;
    __syncthreads();
    if (threadIdx.x == 0) g_tok64 = (any == 0) ? 1 : 0;
}

__global__ void embed_kernel(const int* __restrict__ tok,
                             const float* __restrict__ te,
                             const float* __restrict__ pe,
                             float* __restrict__ x)
{
    const int s = blockIdx.x;
    const int t = g_tok64 ? tok[2 * s] : tok[s];
    const float4* e = (const float4*)(te + (size_t)t * D);
    const float4* p = (const float4*)(pe + (size_t)s * D);
    float4*       o = (float4*)(x + (size_t)s * D);
    for (int i = threadIdx.x; i < D / 4; i += blockDim.x) {
        float4 a = e[i], b = p[i];
        o[i] = make_float4(a.x + b.x, a.y + b.y, a.z + b.z, a.w + b.w);
    }
}

// ---------------- weight convert + transpose: fp32 [K][N] -> fp16 hi [N][K] ----------------
__global__ void convT_kernel(const float* __restrict__ src, int K, int N,
                             HALF* __restrict__ dhi)
{
    __shared__ float t[32][33];
    const int n0 = blockIdx.x * 32, k0 = blockIdx.y * 32;
    const int tx = threadIdx.x & 31, ty = threadIdx.x >> 5;
#pragma unroll
    for (int r = 0; r < 4; r++)
        t[ty + 8 * r][tx] = src[(size_t)(k0 + ty + 8 * r) * N + n0 + tx];
    __syncthreads();
#pragma unroll
    for (int r = 0; r < 4; r++) {
        const int n = n0 + ty + 8 * r, k = k0 + tx;
        dhi[(size_t)n * K + k] = __float2half_rn(t[tx][ty + 8 * r]);
    }
}

// ---------------- bf16 transpose for V: [S][D] head slice -> [H][HD][S] ----------------
__global__ void vtrans_kernel(const BF16* __restrict__ vh, const BF16* __restrict__ vl,
                              BF16* __restrict__ vth, BF16* __restrict__ vtl)
{
    __shared__ BF16 th[32][33], tl[32][33];
    const int h = blockIdx.z;
    const int d0 = blockIdx.x * 32, s0 = blockIdx.y * 32;
    const int tx = threadIdx.x & 31, ty = threadIdx.x >> 5;
#pragma unroll
    for (int r = 0; r < 4; r++) {
        const size_t src = (size_t)(s0 + ty + 8 * r) * D + h * HD + d0 + tx;
        th[ty + 8 * r][tx] = vh[src];
        tl[ty + 8 * r][tx] = vl[src];
    }
    __syncthreads();
#pragma unroll
    for (int r = 0; r < 4; r++) {
        const size_t dst = ((size_t)h * HD + d0 + ty + 8 * r) * S + s0 + tx;
        vth[dst] = th[tx][ty + 8 * r];
        vtl[dst] = tl[tx][ty + 8 * r];
    }
}

// ---------------- layernorm: fp32 in -> fp16 hi/lo out ----------------
__global__ void ln_kernel(const float* __restrict__ x,
                          const float* __restrict__ g,
                          const float* __restrict__ b,
                          HALF* __restrict__ oh, HALF* __restrict__ ol)
{
    __shared__ float r1[8], r2[8];
    __shared__ float s_mean, s_inv;
    const int s   = blockIdx.x;
    const int tid = threadIdx.x;
    const float4* xr = (const float4*)(x + (size_t)s * D);
    float4 v0 = xr[tid];
    float4 v1 = xr[tid + 256];
    float sum = v0.x + v0.y + v0.z + v0.w + v1.x + v1.y + v1.z + v1.w;
    float sq  = v0.x * v0.x + v0.y * v0.y + v0.z * v0.z + v0.w * v0.w
              + v1.x * v1.x + v1.y * v1.y + v1.z * v1.z + v1.w * v1.w;
#pragma unroll
    for (int o = 16; o; o >>= 1) {
        sum += __shfl_xor_sync(0xffffffffu, sum, o);
        sq  += __shfl_xor_sync(0xffffffffu, sq,  o);
    }
    const int w = tid >> 5;
    if ((tid & 31) == 0) { r1[w] = sum; r2[w] = sq; }
    __syncthreads();
    if (tid == 0) {
        float ts = 0.f, tq = 0.f;
#pragma unroll
        for (int i = 0; i < 8; i++) { ts += r1[i]; tq += r2[i]; }
        const float mean = ts / (float)D;
        const float var  = tq / (float)D - mean * mean;
        s_mean = mean;
        s_inv  = rsqrtf(var + LN_EPS);
    }
    __syncthreads();
    const float mean = s_mean, inv = s_inv;
    const float4* gg = (const float4*)g;
    const float4* bb = (const float4*)b;
    float4 g0 = gg[tid], g1 = gg[tid + 256];
    float4 b0 = bb[tid], b1 = bb[tid + 256];
    float o00 = (v0.x - mean) * inv * g0.x + b0.x;
    float o01 = (v0.y - mean) * inv * g0.y + b0.y;
    float o02 = (v0.z - mean) * inv * g0.z + b0.z;
    float o03 = (v0.w - mean) * inv * g0.w + b0.w;
    float o10 = (v1.x - mean) * inv * g1.x + b1.x;
    float o11 = (v1.y - mean) * inv * g1.y + b1.y;
    float o12 = (v1.z - mean) * inv * g1.z + b1.z;
    float o13 = (v1.w - mean) * inv * g1.w + b1.w;
    uint32_t l0, l1, l2, l3;
    const uint32_t h0 = split2h(o00, o01, l0);
    const uint32_t h1 = split2h(o02, o03, l1);
    const uint32_t h2 = split2h(o10, o11, l2);
    const uint32_t h3 = split2h(o12, o13, l3);
    const size_t e0 = (size_t)s * D + tid * 4;
    *(uint2*)(oh + e0)        = make_uint2(h0, h1);
    *(uint2*)(ol + e0)        = make_uint2(l0, l1);
    *(uint2*)(oh + e0 + 1024) = make_uint2(h2, h3);
    *(uint2*)(ol + e0 + 1024) = make_uint2(l2, l3);
}

// ---------------- softmax: fp32 rows -> bf16 hi/lo prob rows ----------------
__global__ void softmax_kernel(const float* __restrict__ sc,
                               BF16* __restrict__ ph, BF16* __restrict__ pl)
{
    __shared__ float r1[8];
    __shared__ float s_max, s_inv;
    const int tid = threadIdx.x;
    const float* r = sc + (size_t)blockIdx.x * S;
    float4 v0 = ((const float4*)r)[tid];
    float4 v1 = ((const float4*)r)[tid + 256];
    float mx = fmaxf(fmaxf(fmaxf(v0.x, v0.y), fmaxf(v0.z, v0.w)),
                     fmaxf(fmaxf(v1.x, v1.y), fmaxf(v1.z, v1.w)));
#pragma unroll
    for (int o = 16; o; o >>= 1) mx = fmaxf(mx, __shfl_xor_sync(0xffffffffu, mx, o));
    const int w = tid >> 5;
    if ((tid & 31) == 0) r1[w] = mx;
    __syncthreads();
    if (tid == 0) {
        float m = r1[0];
#pragma unroll
        for (int i = 1; i < 8; i++) m = fmaxf(m, r1[i]);
        s_max = m;
    }
    __syncthreads();
    mx = s_max;
    v0.x = expf(v0.x - mx); v0.y = expf(v0.y - mx);
    v0.z = expf(v0.z - mx); v0.w = expf(v0.w - mx);
    v1.x = expf(v1.x - mx); v1.y = expf(v1.y - mx);
    v1.z = expf(v1.z - mx); v1.w = expf(v1.w - mx);
    float sum = v0.x + v0.y + v0.z + v0.w + v1.x + v1.y + v1.z + v1.w;
#pragma unroll
    for (int o = 16; o; o >>= 1) sum += __shfl_xor_sync(0xffffffffu, sum, o);
    __syncthreads();
    if ((tid & 31) == 0) r1[w] = sum;
    __syncthreads();
    if (tid == 0) {
        float t = 0.f;
#pragma unroll
        for (int i = 0; i < 8; i++) t += r1[i];
        s_inv = 1.0f / t;
    }
    __syncthreads();
    const float inv = s_inv;
    v0.x *= inv; v0.y *= inv; v0.z *= inv; v0.w *= inv;
    v1.x *= inv; v1.y *= inv; v1.z *= inv; v1.w *= inv;
    uint32_t l0, l1, l2, l3;
    const uint32_t h0 = split2b(v0.x, v0.y, l0);
    const uint32_t h1 = split2b(v0.z, v0.w, l1);
    const uint32_t h2 = split2b(v1.x, v1.y, l2);
    const uint32_t h3 = split2b(v1.z, v1.w, l3);
    const size_t e0 = (size_t)blockIdx.x * S + tid * 4;
    *(uint2*)(ph + e0)        = make_uint2(h0, h1);
    *(uint2*)(pl + e0)        = make_uint2(l0, l1);
    *(uint2*)(ph + e0 + 1024) = make_uint2(h2, h3);
    *(uint2*)(pl + e0 + 1024) = make_uint2(l2, l3);
}

// ---------------- cp.async pipelined split GEMM ----------------
// C[z] = epi(alpha * A[z] @ B[z]^T (+ Res))
// PASSES==3: bf16 operands, 3 passes (AhBh + AlBh + AhBl) -> ~eps^2 accuracy
// PASSES==2: fp16 operands, 2 passes ((Ah+Al)Bh) -> B half-ulp accuracy; Bl unused
#define OUT_F32       0
#define OUT_F32RES    1
#define OUT_PAIR_BF16 2
#define OUT_PAIR_FP16 3
#define OUT_RELU_FP16 4

#define STAGES 3
#define GEMM_SMEM3 (3 * 32768)
#define GEMM_SMEM2 (3 * 24576)

template <int OUT, int PASSES>
__global__ void __launch_bounds__(256, 2)
tc_gemm(const uint16_t* __restrict__ Ah, const uint16_t* __restrict__ Al, int lda, long long sA,
        const uint16_t* __restrict__ Bh, const uint16_t* __restrict__ Bl, int ldb, long long sB,
        const float* __restrict__ Res,
        float* __restrict__ Cf, uint16_t* __restrict__ Chi, uint16_t* __restrict__ Clo,
        int ldc, long long sC, int K, float alpha)
{
    constexpr int STAGE_BYTES = (PASSES == 3) ? 32768 : 24576;
    extern __shared__ char smem[];
    const uint32_t sb = smem_u32(smem);
    const int tid = threadIdx.x, wid = tid >> 5, lane = tid & 31;
    const int z = blockIdx.z;
    Ah += (size_t)z * sA;  Al += (size_t)z * sA;
    Bh += (size_t)z * sB;
    if (PASSES == 3) Bl += (size_t)z * sB;
    const int m0 = blockIdx.x * 128;   // M fast-varying
    const int n0 = blockIdx.y * 128;
    const int wm = (wid & 3) * 32;
    const int wn = (wid >> 2) * 64;

    // loader thread mapping: rowL in [0,64), cL = 16B chunk in [0,4)
    const int rowL = tid >> 2;
    const int cL   = tid & 3;
    const uint32_t o0 = SW64((uint32_t)(rowL * 64 + cL * 16));
    const uint32_t o1 = SW64((uint32_t)((rowL + 64) * 64 + cL * 16));
    const uint16_t* aht = Ah + (size_t)(m0 + rowL) * lda + cL * 8;
    const uint16_t* alt = Al + (size_t)(m0 + rowL) * lda + cL * 8;
    const uint16_t* bht = Bh + (size_t)(n0 + rowL) * ldb + cL * 8;
    const uint16_t* blt = (PASSES == 3) ? (Bl + (size_t)(n0 + rowL) * ldb + cL * 8) : nullptr;
    const size_t a64 = (size_t)64 * lda;
    const size_t b64 = (size_t)64 * ldb;

    auto issue = [&](int idx, int s) {
        const uint32_t st = sb + s * STAGE_BYTES;
        const uint16_t* a1 = aht + idx * 32;
        const uint16_t* a2 = alt + idx * 32;
        const uint16_t* b1 = bht + idx * 32;
        CP16(st + o0,         a1);
        CP16(st + 8192  + o0, a2);
        CP16(st + 16384 + o0, b1);
        CP16(st + o1,         a1 + a64);
        CP16(st + 8192  + o1, a2 + a64);
        CP16(st + 16384 + o1, b1 + b64);
        if (PASSES == 3) {
            const uint16_t* b2 = blt + idx * 32;
            CP16(st + 24576 + o0, b2);
            CP16(st + 24576 + o1, b2 + b64);
        }
        CPCOMMIT();
    };

    float acc[2][8][4];
#pragma unroll
    for (int i = 0; i < 2; i++)
#pragma unroll
        for (int j = 0; j < 8; j++)
#pragma unroll
            for (int q = 0; q < 4; q++) acc[i][j][q] = 0.f;

    // ldmatrix lane address components
    const int a_row = lane & 15;
    const int a_kc  = (lane >> 4) * 8;
    const int b_row = (lane & 7) + (lane >> 4) * 8;
    const int b_kc  = ((lane >> 3) & 1) * 8;

    const int nch = K >> 5;
    issue(0, 0);
    issue(1, 1);

    for (int i = 0; i < nch; i++) {
        if (i + 1 < nch) { CPWAIT1(); } else { CPWAIT0(); }
        __syncthreads();                       // single barrier per chunk
        if (i + 2 < nch) issue(i + 2, (i + 2) % STAGES);

        const uint32_t st  = sb + (i % STAGES) * STAGE_BYTES;
        const uint32_t AhS = st, AlS = st + 8192, BhS = st + 16384, BlS = st + 24576;
#pragma unroll
        for (int ks = 0; ks < 2; ks++) {
            uint32_t ah[2][4], al[2][4];
#pragma unroll
            for (int mf = 0; mf < 2; mf++) {
                const uint32_t swo = SW64((uint32_t)((wm + mf * 16 + a_row) * 64
                                                     + (ks * 16 + a_kc) * 2));
                ldm_x4(ah[mf], AhS + swo);
                ldm_x4(al[mf], AlS + swo);
            }
#pragma unroll
            for (int p = 0; p < 4; p++) {
                uint32_t bh[4];
                const uint32_t swo = SW64((uint32_t)((wn + p * 16 + b_row) * 64
                                                     + (ks * 16 + b_kc) * 2));
                ldm_x4(bh, BhS + swo);
                if (PASSES == 3) {
                    uint32_t bl[4];
                    ldm_x4(bl, BlS + swo);
#pragma unroll
                    for (int mf = 0; mf < 2; mf++) {
                        mma_bf16(acc[mf][2 * p],     ah[mf], bh);
                        mma_bf16(acc[mf][2 * p + 1], ah[mf], bh + 2);
                        mma_bf16(acc[mf][2 * p],     al[mf], bh);
                        mma_bf16(acc[mf][2 * p + 1], al[mf], bh + 2);
                        mma_bf16(acc[mf][2 * p],     ah[mf], bl);
                        mma_bf16(acc[mf][2 * p + 1], ah[mf], bl + 2);
                    }
                } else {
#pragma unroll
                    for (int mf = 0; mf < 2; mf++) {
                        mma_fp16(acc[mf][2 * p],     ah[mf], bh);
                        mma_fp16(acc[mf][2 * p + 1], ah[mf], bh + 2);
                        mma_fp16(acc[mf][2 * p],     al[mf], bh);
                        mma_fp16(acc[mf][2 * p + 1], al[mf], bh + 2);
                    }
                }
            }
        }
    }

    // ---------------- epilogue ----------------
    const int r  = lane >> 2;
    const int c2 = (lane & 3) * 2;
#pragma unroll
    for (int mf = 0; mf < 2; mf++) {
#pragma unroll
        for (int hh = 0; hh < 2; hh++) {
            const int m = m0 + wm + mf * 16 + r + 8 * hh;
            const size_t rofs = (size_t)z * sC + (size_t)m * ldc + n0 + wn;
#pragma unroll
            for (int nf = 0; nf < 8; nf++) {
                float x0 = acc[mf][nf][2 * hh]     * alpha;
                float x1 = acc[mf][nf][2 * hh + 1] * alpha;
                const int nn = nf * 8 + c2;
                if (OUT == OUT_F32RES) {
                    const float2 rr = *(const float2*)(Res + (size_t)m * ldc + n0 + wn + nn);
                    x0 += rr.x; x1 += rr.y;
                } else if (OUT == OUT_RELU_FP16) {
                    x0 = fmaxf(x0, 0.f); x1 = fmaxf(x1, 0.f);
                }
                if (OUT == OUT_F32 || OUT == OUT_F32RES) {
                    *(float2*)(Cf + rofs + nn) = make_float2(x0, x1);
                } else if (OUT == OUT_PAIR_BF16) {
                    uint32_t lo;
                    const uint32_t hi = split2b(x0, x1, lo);
                    *(uint32_t*)(Chi + rofs + nn) = hi;
                    *(uint32_t*)(Clo + rofs + nn) = lo;
                } else {
                    uint32_t lo;
                    const uint32_t hi = split2h(x0, x1, lo);
                    *(uint32_t*)(Chi + rofs + nn) = hi;
                    *(uint32_t*)(Clo + rofs + nn) = lo;
                }
            }
        }
    }
}

// ---------------- launch ----------------
extern "C" void kernel_launch(void* const* d_in, const int* in_sizes, int n_in,
                              void* d_out, int out_size)
{
    const int*   tokens = (const int*)d_in[0];
    const float* temb   = (const float*)d_in[1];
    const float* pemb   = (const float*)d_in[2];
    const float* wq     = (const float*)d_in[3];
    const float* wk     = (const float*)d_in[4];
    const float* wv     = (const float*)d_in[5];
    const float* wo     = (const float*)d_in[6];
    const float* wfi    = (const float*)d_in[7];
    const float* wfo    = (const float*)d_in[8];
    const float* ln1g   = (const float*)d_in[9];
    const float* ln1b   = (const float*)d_in[10];
    const float* ln2g   = (const float*)d_in[11];
    const float* ln2b   = (const float*)d_in[12];
    const float* lnfg   = (const float*)d_in[13];
    const float* lnfb   = (const float*)d_in[14];
    const float* wout   = (const float*)d_in[15];
    float*       out    = (float*)d_out;

    float *px, *px2, *px3, *pat;
    HALF *phh, *phl, *ph2h, *ph2l, *phfh, *phfl, *paoh, *paol, *pffh, *pffl;
    BF16 *pqkvh, *pqkvl, *pvth, *pvtl, *pph, *ppl;
    HALF *pwqkvTh, *pwoTh, *pwfiTh, *pwfoTh, *pwoutTh;
    cudaGetSymbolAddress((void**)&px,   g_x);
    cudaGetSymbolAddress((void**)&px2,  g_x2);
    cudaGetSymbolAddress((void**)&px3,  g_x3);
    cudaGetSymbolAddress((void**)&pat,  g_at);
    cudaGetSymbolAddress((void**)&phh,  g_hh);
    cudaGetSymbolAddress((void**)&phl,  g_hl);
    cudaGetSymbolAddress((void**)&ph2h, g_h2h);
    cudaGetSymbolAddress((void**)&ph2l, g_h2l);
    cudaGetSymbolAddress((void**)&phfh, g_hfh);
    cudaGetSymbolAddress((void**)&phfl, g_hfl);
    cudaGetSymbolAddress((void**)&paoh, g_aoh);
    cudaGetSymbolAddress((void**)&paol, g_aol);
    cudaGetSymbolAddress((void**)&pffh, g_ffh);
    cudaGetSymbolAddress((void**)&pffl, g_ffl);
    cudaGetSymbolAddress((void**)&pqkvh, g_qkvh);
    cudaGetSymbolAddress((void**)&pqkvl, g_qkvl);
    cudaGetSymbolAddress((void**)&pvth, g_vth);
    cudaGetSymbolAddress((void**)&pvtl, g_vtl);
    cudaGetSymbolAddress((void**)&pph,  g_ph);
    cudaGetSymbolAddress((void**)&ppl,  g_pl);
    cudaGetSymbolAddress((void**)&pwqkvTh, g_wqkvTh);
    cudaGetSymbolAddress((void**)&pwoTh, g_woTh);
    cudaGetSymbolAddress((void**)&pwfiTh, g_wfiTh);
    cudaGetSymbolAddress((void**)&pwfoTh, g_wfoTh);
    cudaGetSymbolAddress((void**)&pwoutTh, g_woutTh);

    cudaFuncSetAttribute(tc_gemm<OUT_PAIR_BF16, 2>,
                         cudaFuncAttributeMaxDynamicSharedMemorySize, GEMM_SMEM2);
    cudaFuncSetAttribute(tc_gemm<OUT_F32, 3>,
                         cudaFuncAttributeMaxDynamicSharedMemorySize, GEMM_SMEM3);
    cudaFuncSetAttribute(tc_gemm<OUT_PAIR_FP16, 3>,
                         cudaFuncAttributeMaxDynamicSharedMemorySize, GEMM_SMEM3);
    cudaFuncSetAttribute(tc_gemm<OUT_F32RES, 2>,
                         cudaFuncAttributeMaxDynamicSharedMemorySize, GEMM_SMEM2);
    cudaFuncSetAttribute(tc_gemm<OUT_RELU_FP16, 2>,
                         cudaFuncAttributeMaxDynamicSharedMemorySize, GEMM_SMEM2);
    cudaFuncSetAttribute(tc_gemm<OUT_F32, 2>,
                         cudaFuncAttributeMaxDynamicSharedMemorySize, GEMM_SMEM2);

    // ---- side stream for weight conversions not needed until later ----
    cudaStream_t s2;
    cudaStreamCreateWithFlags(&s2, cudaStreamNonBlocking);
    cudaEvent_t evFork, evWo, evWfi, evWfo, evWout;
    cudaEventCreateWithFlags(&evFork, cudaEventDisableTiming);
    cudaEventCreateWithFlags(&evWo,   cudaEventDisableTiming);
    cudaEventCreateWithFlags(&evWfi,  cudaEventDisableTiming);
    cudaEventCreateWithFlags(&evWfo,  cudaEventDisableTiming);
    cudaEventCreateWithFlags(&evWout, cudaEventDisableTiming);

    detect_tok_kernel<<<1, 256>>>(tokens);
    cudaEventRecord(evFork, 0);
    cudaStreamWaitEvent(s2, evFork, 0);

    // side stream: conversions consumed only after the attention phase
    convT_kernel<<<dim3(D / 32, D / 32), 256, 0, s2>>>(wo, D, D, pwoTh);
    cudaEventRecord(evWo, s2);
    convT_kernel<<<dim3(FF / 32, D / 32), 256, 0, s2>>>(wfi, D, FF, pwfiTh);
    cudaEventRecord(evWfi, s2);
    convT_kernel<<<dim3(D / 32, FF / 32), 256, 0, s2>>>(wfo, FF, D, pwfoTh);
    cudaEventRecord(evWfo, s2);
    convT_kernel<<<dim3(VOC / 32, D / 32), 256, 0, s2>>>(wout, D, VOC, pwoutTh);
    cudaEventRecord(evWout, s2);

    // main stream
    embed_kernel<<<S, 256>>>(tokens, temb, pemb, px);
    convT_kernel<<<dim3(D / 32, D / 32), 256>>>(wq, D, D, pwqkvTh);
    convT_kernel<<<dim3(D / 32, D / 32), 256>>>(wk, D, D, pwqkvTh + DD);
    convT_kernel<<<dim3(D / 32, D / 32), 256>>>(wv, D, D, pwqkvTh + 2 * DD);

    // attention block
    ln_kernel<<<S, 256>>>(px, ln1g, ln1b, phh, phl);
    tc_gemm<OUT_PAIR_BF16, 2><<<dim3(S / 128, D / 128, 3), 256, GEMM_SMEM2>>>(
        (uint16_t*)phh, (uint16_t*)phl, D, 0, (uint16_t*)pwqkvTh, nullptr, D, DD, nullptr,
        nullptr, (uint16_t*)pqkvh, (uint16_t*)pqkvl, D, SD, D, 1.f);
    vtrans_kernel<<<dim3(HD / 32, S / 32, H), 256>>>(pqkvh + 2 * SD, pqkvl + 2 * SD, pvth, pvtl);
    tc_gemm<OUT_F32, 3><<<dim3(S / 128, S / 128, H), 256, GEMM_SMEM3>>>(
        (uint16_t*)pqkvh, (uint16_t*)pqkvl, D, HD,
        (uint16_t*)(pqkvh + SD), (uint16_t*)(pqkvl + SD), D, HD, nullptr,
        pat, nullptr, nullptr, S, (long long)S * S, HD, 0.08838834764831845f);
    softmax_kernel<<<H * S, 256>>>(pat, pph, ppl);
    tc_gemm<OUT_PAIR_FP16, 3><<<dim3(S / 128, 1, H), 256, GEMM_SMEM3>>>(
        (uint16_t*)pph, (uint16_t*)ppl, S, (long long)S * S,
        (uint16_t*)pvth, (uint16_t*)pvtl, S, (long long)HD * S, nullptr,
        nullptr, (uint16_t*)paoh, (uint16_t*)paol, D, HD, S, 1.f);
    cudaStreamWaitEvent(0, evWo, 0);
    tc_gemm<OUT_F32RES, 2><<<dim3(S / 128, D / 128, 1), 256, GEMM_SMEM2>>>(
        (uint16_t*)paoh, (uint16_t*)paol, D, 0, (uint16_t*)pwoTh, nullptr, D, 0, px,
        px2, nullptr, nullptr, D, 0, D, 1.f);

    // FFN block
    ln_kernel<<<S, 256>>>(px2, ln2g, ln2b, ph2h, ph2l);
    cudaStreamWaitEvent(0, evWfi, 0);
    tc_gemm<OUT_RELU_FP16, 2><<<dim3(S / 128, FF / 128, 1), 256, GEMM_SMEM2>>>(
        (uint16_t*)ph2h, (uint16_t*)ph2l, D, 0, (uint16_t*)pwfiTh, nullptr, D, 0, nullptr,
        nullptr, (uint16_t*)pffh, (uint16_t*)pffl, FF, 0, D, 1.f);
    cudaStreamWaitEvent(0, evWfo, 0);
    tc_gemm<OUT_F32RES, 2><<<dim3(S / 128, D / 128, 1), 256, GEMM_SMEM2>>>(
        (uint16_t*)pffh, (uint16_t*)pffl, FF, 0, (uint16_t*)pwfoTh, nullptr, FF, 0, px2,
        px3, nullptr, nullptr, D, 0, FF, 1.f);

    // final LN + logits
    ln_kernel<<<S, 256>>>(px3, lnfg, lnfb, phfh, phfl);
    cudaStreamWaitEvent(0, evWout, 0);
    tc_gemm<OUT_F32, 2><<<dim3(S / 128, VOC / 128, 1), 256, GEMM_SMEM2>>>(
        (uint16_t*)phfh, (uint16_t*)phfl, D, 0, (uint16_t*)pwoutTh, nullptr, D, 0, nullptr,
        out, nullptr, nullptr, VOC, 0, D, 1.f);
}

// round 7
// speedup vs baseline: 6.1938x; 1.3682x over previous
#include <cuda_runtime.h>
#include <cuda_bf16.h>
#include <cuda_fp16.h>
#include <stdint.h>
#include <math.h>

typedef __nv_bfloat16 BF16;
typedef __half        HALF;

// ---------------- dimensions ----------------
#define S   2048
#define D   2048
#define H   16
#define HD  128
#define FF  8192
#define VOC 32000
#define LN_EPS 1e-5f
#define SD  (S * D)
#define DD  (D * D)

// ---------------- scratch ----------------
__device__ float g_x  [SD];
__device__ float g_x2 [SD];
__device__ float g_x3 [SD];
__device__ float g_at [H * S * S];

// fp16 activation splits (A-side of 2-pass GEMMs; lo unused by 1-pass consumers)
__device__ HALF g_hh [SD],  g_hl [SD];
__device__ HALF g_h2h[SD],  g_h2l[SD];
__device__ HALF g_hfh[SD],  g_hfl[SD];
__device__ HALF g_aoh[SD],  g_aol[SD];
__device__ HALF g_ffh[S * FF];

// bf16 splits (attention-internal 3-pass operands)
__device__ BF16 g_qkvh[3 * SD], g_qkvl[3 * SD];
__device__ BF16 g_vth[SD],  g_vtl[SD];
__device__ BF16 g_ph [H * S * S], g_pl [H * S * S];

// fp16 weights, hi only (B-side)
__device__ HALF g_wqkvTh[3 * DD];
__device__ HALF g_woTh[DD];
__device__ HALF g_wfiTh[D * FF];
__device__ HALF g_wfoTh[D * FF];
__device__ HALF g_woutTh[(size_t)D * VOC];

__device__ int g_tok64;

// ---------------- PTX helpers (plain sm_103-legal) ----------------
__device__ __forceinline__ uint32_t smem_u32(const void* p) {
    uint32_t a;
    asm("{ .reg .u64 t; cvta.to.shared.u64 t, %1; cvt.u32.u64 %0, t; }" : "=r"(a) : "l"(p));
    return a;
}
__device__ __forceinline__ void ldm_x4(uint32_t* r, uint32_t addr) {
    asm volatile("ldmatrix.sync.aligned.m8n8.x4.shared.b16 {%0,%1,%2,%3}, [%4];"
                 : "=r"(r[0]), "=r"(r[1]), "=r"(r[2]), "=r"(r[3]) : "r"(addr));
}
__device__ __forceinline__ void mma_bf16(float* c, const uint32_t* a, const uint32_t* b) {
    asm volatile(
        "mma.sync.aligned.m16n8k16.row.col.f32.bf16.bf16.f32 "
        "{%0,%1,%2,%3}, {%4,%5,%6,%7}, {%8,%9}, {%0,%1,%2,%3};"
        : "+f"(c[0]), "+f"(c[1]), "+f"(c[2]), "+f"(c[3])
        : "r"(a[0]), "r"(a[1]), "r"(a[2]), "r"(a[3]), "r"(b[0]), "r"(b[1]));
}
__device__ __forceinline__ void mma_fp16(float* c, const uint32_t* a, const uint32_t* b) {
    asm volatile(
        "mma.sync.aligned.m16n8k16.row.col.f32.f16.f16.f32 "
        "{%0,%1,%2,%3}, {%4,%5,%6,%7}, {%8,%9}, {%0,%1,%2,%3};"
        : "+f"(c[0]), "+f"(c[1]), "+f"(c[2]), "+f"(c[3])
        : "r"(a[0]), "r"(a[1]), "r"(a[2]), "r"(a[3]), "r"(b[0]), "r"(b[1]));
}
#define CP16(dst, src) \
    asm volatile("cp.async.cg.shared.global [%0], [%1], 16;" :: "r"(dst), "l"(src) : "memory")
#define CPCOMMIT() asm volatile("cp.async.commit_group;" ::: "memory")
#define CPWAIT0() asm volatile("cp.async.wait_group 0;" ::: "memory")
#define CPWAIT1() asm volatile("cp.async.wait_group 1;" ::: "memory")

#define SW64(o) ((o) ^ (((o) >> 3) & 0x30))

// split fp32 pair -> bf16 hi pair (ret) + bf16 lo pair (out param)
__device__ __forceinline__ uint32_t split2b(float a, float b, uint32_t& lo)
{
    BF16 ha = __float2bfloat16(a);
    BF16 hb = __float2bfloat16(b);
    __nv_bfloat162 l2;
    l2.x = __float2bfloat16(a - __bfloat162float(ha));
    l2.y = __float2bfloat16(b - __bfloat162float(hb));
    lo = *reinterpret_cast<uint32_t*>(&l2);
    __nv_bfloat162 h2; h2.x = ha; h2.y = hb;
    return *reinterpret_cast<uint32_t*>(&h2);
}
// split fp32 pair -> fp16 hi pair + fp16 lo pair
__device__ __forceinline__ uint32_t split2h(float a, float b, uint32_t& lo)
{
    HALF ha = __float2half_rn(a);
    HALF hb = __float2half_rn(b);
    __half2 l2 = __halves2half2(__float2half_rn(a - __half2float(ha)),
                                __float2half_rn(b - __half2float(hb)));
    lo = *reinterpret_cast<uint32_t*>(&l2);
    __half2 h2 = __halves2half2(ha, hb);
    return *reinterpret_cast<uint32_t*>(&h2);
}

// ---------------- token detect + embed ----------------
__global__ void detect_tok_kernel(const int* __restrict__ t)
{
    __shared__ int any;
    if (threadIdx.x == 0) any = 0;
    __syncthreads();
    int local = 0;
    for (int i = threadIdx.x; i < S / 2; i += blockDim.x)
        if (t[2 * i + 1] != 0) local = 1;
    if (local) any = 1;
    __syncthreads();
    if (threadIdx.x == 0) g_tok64 = (any == 0) ? 1 : 0;
}

__global__ void embed_kernel(const int* __restrict__ tok,
                             const float* __restrict__ te,
                             const float* __restrict__ pe,
                             float* __restrict__ x)
{
    const int s = blockIdx.x;
    const int t = g_tok64 ? tok[2 * s] : tok[s];
    const float4* e = (const float4*)(te + (size_t)t * D);
    const float4* p = (const float4*)(pe + (size_t)s * D);
    float4*       o = (float4*)(x + (size_t)s * D);
    for (int i = threadIdx.x; i < D / 4; i += blockDim.x) {
        float4 a = e[i], b = p[i];
        o[i] = make_float4(a.x + b.x, a.y + b.y, a.z + b.z, a.w + b.w);
    }
}

// ---------------- weight convert + transpose: fp32 [K][N] -> fp16 hi [N][K] ----------------
__global__ void convT_kernel(const float* __restrict__ src, int K, int N,
                             HALF* __restrict__ dhi)
{
    __shared__ float t[32][33];
    const int n0 = blockIdx.x * 32, k0 = blockIdx.y * 32;
    const int tx = threadIdx.x & 31, ty = threadIdx.x >> 5;
#pragma unroll
    for (int r = 0; r < 4; r++)
        t[ty + 8 * r][tx] = src[(size_t)(k0 + ty + 8 * r) * N + n0 + tx];
    __syncthreads();
#pragma unroll
    for (int r = 0; r < 4; r++) {
        const int n = n0 + ty + 8 * r, k = k0 + tx;
        dhi[(size_t)n * K + k] = __float2half_rn(t[tx][ty + 8 * r]);
    }
}

// ---------------- bf16 transpose for V: [S][D] head slice -> [H][HD][S] ----------------
__global__ void vtrans_kernel(const BF16* __restrict__ vh, const BF16* __restrict__ vl,
                              BF16* __restrict__ vth, BF16* __restrict__ vtl)
{
    __shared__ BF16 th[32][33], tl[32][33];
    const int h = blockIdx.z;
    const int d0 = blockIdx.x * 32, s0 = blockIdx.y * 32;
    const int tx = threadIdx.x & 31, ty = threadIdx.x >> 5;
#pragma unroll
    for (int r = 0; r < 4; r++) {
        const size_t src = (size_t)(s0 + ty + 8 * r) * D + h * HD + d0 + tx;
        th[ty + 8 * r][tx] = vh[src];
        tl[ty + 8 * r][tx] = vl[src];
    }
    __syncthreads();
#pragma unroll
    for (int r = 0; r < 4; r++) {
        const size_t dst = ((size_t)h * HD + d0 + ty + 8 * r) * S + s0 + tx;
        vth[dst] = th[tx][ty + 8 * r];
        vtl[dst] = tl[tx][ty + 8 * r];
    }
}

// ---------------- layernorm: fp32 in -> fp16 hi/lo out ----------------
__global__ void ln_kernel(const float* __restrict__ x,
                          const float* __restrict__ g,
                          const float* __restrict__ b,
                          HALF* __restrict__ oh, HALF* __restrict__ ol)
{
    __shared__ float r1[8], r2[8];
    __shared__ float s_mean, s_inv;
    const int s   = blockIdx.x;
    const int tid = threadIdx.x;
    const float4* xr = (const float4*)(x + (size_t)s * D);
    float4 v0 = xr[tid];
    float4 v1 = xr[tid + 256];
    float sum = v0.x + v0.y + v0.z + v0.w + v1.x + v1.y + v1.z + v1.w;
    float sq  = v0.x * v0.x + v0.y * v0.y + v0.z * v0.z + v0.w * v0.w
              + v1.x * v1.x + v1.y * v1.y + v1.z * v1.z + v1.w * v1.w;
#pragma unroll
    for (int o = 16; o; o >>= 1) {
        sum += __shfl_xor_sync(0xffffffffu, sum, o);
        sq  += __shfl_xor_sync(0xffffffffu, sq,  o);
    }
    const int w = tid >> 5;
    if ((tid & 31) == 0) { r1[w] = sum; r2[w] = sq; }
    __syncthreads();
    if (tid == 0) {
        float ts = 0.f, tq = 0.f;
#pragma unroll
        for (int i = 0; i < 8; i++) { ts += r1[i]; tq += r2[i]; }
        const float mean = ts / (float)D;
        const float var  = tq / (float)D - mean * mean;
        s_mean = mean;
        s_inv  = rsqrtf(var + LN_EPS);
    }
    __syncthreads();
    const float mean = s_mean, inv = s_inv;
    const float4* gg = (const float4*)g;
    const float4* bb = (const float4*)b;
    float4 g0 = gg[tid], g1 = gg[tid + 256];
    float4 b0 = bb[tid], b1 = bb[tid + 256];
    float o00 = (v0.x - mean) * inv * g0.x + b0.x;
    float o01 = (v0.y - mean) * inv * g0.y + b0.y;
    float o02 = (v0.z - mean) * inv * g0.z + b0.z;
    float o03 = (v0.w - mean) * inv * g0.w + b0.w;
    float o10 = (v1.x - mean) * inv * g1.x + b1.x;
    float o11 = (v1.y - mean) * inv * g1.y + b1.y;
    float o12 = (v1.z - mean) * inv * g1.z + b1.z;
    float o13 = (v1.w - mean) * inv * g1.w + b1.w;
    uint32_t l0, l1, l2, l3;
    const uint32_t h0 = split2h(o00, o01, l0);
    const uint32_t h1 = split2h(o02, o03, l1);
    const uint32_t h2 = split2h(o10, o11, l2);
    const uint32_t h3 = split2h(o12, o13, l3);
    const size_t e0 = (size_t)s * D + tid * 4;
    *(uint2*)(oh + e0)        = make_uint2(h0, h1);
    *(uint2*)(ol + e0)        = make_uint2(l0, l1);
    *(uint2*)(oh + e0 + 1024) = make_uint2(h2, h3);
    *(uint2*)(ol + e0 + 1024) = make_uint2(l2, l3);
}

// ---------------- softmax: fp32 rows -> bf16 hi/lo prob rows ----------------
__global__ void softmax_kernel(const float* __restrict__ sc,
                               BF16* __restrict__ ph, BF16* __restrict__ pl)
{
    __shared__ float r1[8];
    __shared__ float s_max, s_inv;
    const int tid = threadIdx.x;
    const float* r = sc + (size_t)blockIdx.x * S;
    float4 v0 = ((const float4*)r)[tid];
    float4 v1 = ((const float4*)r)[tid + 256];
    float mx = fmaxf(fmaxf(fmaxf(v0.x, v0.y), fmaxf(v0.z, v0.w)),
                     fmaxf(fmaxf(v1.x, v1.y), fmaxf(v1.z, v1.w)));
#pragma unroll
    for (int o = 16; o; o >>= 1) mx = fmaxf(mx, __shfl_xor_sync(0xffffffffu, mx, o));
    const int w = tid >> 5;
    if ((tid & 31) == 0) r1[w] = mx;
    __syncthreads();
    if (tid == 0) {
        float m = r1[0];
#pragma unroll
        for (int i = 1; i < 8; i++) m = fmaxf(m, r1[i]);
        s_max = m;
    }
    __syncthreads();
    mx = s_max;
    v0.x = expf(v0.x - mx); v0.y = expf(v0.y - mx);
    v0.z = expf(v0.z - mx); v0.w = expf(v0.w - mx);
    v1.x = expf(v1.x - mx); v1.y = expf(v1.y - mx);
    v1.z = expf(v1.z - mx); v1.w = expf(v1.w - mx);
    float sum = v0.x + v0.y + v0.z + v0.w + v1.x + v1.y + v1.z + v1.w;
#pragma unroll
    for (int o = 16; o; o >>= 1) sum += __shfl_xor_sync(0xffffffffu, sum, o);
    __syncthreads();
    if ((tid & 31) == 0) r1[w] = sum;
    __syncthreads();
    if (tid == 0) {
        float t = 0.f;
#pragma unroll
        for (int i = 0; i < 8; i++) t += r1[i];
        s_inv = 1.0f / t;
    }
    __syncthreads();
    const float inv = s_inv;
    v0.x *= inv; v0.y *= inv; v0.z *= inv; v0.w *= inv;
    v1.x *= inv; v1.y *= inv; v1.z *= inv; v1.w *= inv;
    uint32_t l0, l1, l2, l3;
    const uint32_t h0 = split2b(v0.x, v0.y, l0);
    const uint32_t h1 = split2b(v0.z, v0.w, l1);
    const uint32_t h2 = split2b(v1.x, v1.y, l2);
    const uint32_t h3 = split2b(v1.z, v1.w, l3);
    const size_t e0 = (size_t)blockIdx.x * S + tid * 4;
    *(uint2*)(ph + e0)        = make_uint2(h0, h1);
    *(uint2*)(pl + e0)        = make_uint2(l0, l1);
    *(uint2*)(ph + e0 + 1024) = make_uint2(h2, h3);
    *(uint2*)(pl + e0 + 1024) = make_uint2(l2, l3);
}

// ---------------- cp.async pipelined split GEMM ----------------
// C[z] = epi(alpha * A[z] @ B[z]^T (+ Res))
// PASSES==3: bf16 operands, 3 passes (AhBh + AlBh + AhBl) -> ~eps^2 accuracy
// PASSES==2: fp16, 2 passes ((Ah+Al)Bh) -> B half-ulp accuracy
// PASSES==1: fp16, 1 pass  (Ah Bh)     -> A+B half-ulp accuracy
#define OUT_F32       0
#define OUT_F32RES    1
#define OUT_PAIR_BF16 2
#define OUT_PAIR_FP16 3
#define OUT_RELU_HI   4

#define STAGES 3
#define GEMM_SMEM3 (3 * 32768)
#define GEMM_SMEM2 (3 * 24576)
#define GEMM_SMEM1 (3 * 16384)

template <int OUT, int PASSES>
__global__ void __launch_bounds__(256, 2)
tc_gemm(const uint16_t* __restrict__ Ah, const uint16_t* __restrict__ Al, int lda, long long sA,
        const uint16_t* __restrict__ Bh, const uint16_t* __restrict__ Bl, int ldb, long long sB,
        const float* __restrict__ Res,
        float* __restrict__ Cf, uint16_t* __restrict__ Chi, uint16_t* __restrict__ Clo,
        int ldc, long long sC, int K, float alpha)
{
    constexpr int STAGE_BYTES = (PASSES == 3) ? 32768 : (PASSES == 2) ? 24576 : 16384;
    constexpr int BOFF        = (PASSES == 1) ? 8192 : 16384;
    extern __shared__ char smem[];
    const uint32_t sb = smem_u32(smem);
    const int tid = threadIdx.x, wid = tid >> 5, lane = tid & 31;
    const int z = blockIdx.z;
    Ah += (size_t)z * sA;
    if (PASSES >= 2) Al += (size_t)z * sA;
    Bh += (size_t)z * sB;
    if (PASSES == 3) Bl += (size_t)z * sB;
    const int m0 = blockIdx.x * 128;   // M fast-varying
    const int n0 = blockIdx.y * 128;
    const int wm = (wid & 3) * 32;
    const int wn = (wid >> 2) * 64;

    // loader thread mapping: rowL in [0,64), cL = 16B chunk in [0,4)
    const int rowL = tid >> 2;
    const int cL   = tid & 3;
    const uint32_t o0 = SW64((uint32_t)(rowL * 64 + cL * 16));
    const uint32_t o1 = SW64((uint32_t)((rowL + 64) * 64 + cL * 16));
    const uint16_t* aht = Ah + (size_t)(m0 + rowL) * lda + cL * 8;
    const uint16_t* alt = (PASSES >= 2) ? (Al + (size_t)(m0 + rowL) * lda + cL * 8) : nullptr;
    const uint16_t* bht = Bh + (size_t)(n0 + rowL) * ldb + cL * 8;
    const uint16_t* blt = (PASSES == 3) ? (Bl + (size_t)(n0 + rowL) * ldb + cL * 8) : nullptr;
    const size_t a64 = (size_t)64 * lda;
    const size_t b64 = (size_t)64 * ldb;

    auto issue = [&](int idx, int s) {
        const uint32_t st = sb + s * STAGE_BYTES;
        const uint16_t* a1 = aht + idx * 32;
        const uint16_t* b1 = bht + idx * 32;
        CP16(st + o0,        a1);
        CP16(st + BOFF + o0, b1);
        CP16(st + o1,        a1 + a64);
        CP16(st + BOFF + o1, b1 + b64);
        if (PASSES >= 2) {
            const uint16_t* a2 = alt + idx * 32;
            CP16(st + 8192 + o0, a2);
            CP16(st + 8192 + o1, a2 + a64);
        }
        if (PASSES == 3) {
            const uint16_t* b2 = blt + idx * 32;
            CP16(st + 24576 + o0, b2);
            CP16(st + 24576 + o1, b2 + b64);
        }
        CPCOMMIT();
    };

    float acc[2][8][4];
#pragma unroll
    for (int i = 0; i < 2; i++)
#pragma unroll
        for (int j = 0; j < 8; j++)
#pragma unroll
            for (int q = 0; q < 4; q++) acc[i][j][q] = 0.f;

    // ldmatrix lane address components
    const int a_row = lane & 15;
    const int a_kc  = (lane >> 4) * 8;
    const int b_row = (lane & 7) + (lane >> 4) * 8;
    const int b_kc  = ((lane >> 3) & 1) * 8;

    const int nch = K >> 5;
    issue(0, 0);
    issue(1, 1);

    for (int i = 0; i < nch; i++) {
        if (i + 1 < nch) { CPWAIT1(); } else { CPWAIT0(); }
        __syncthreads();                       // single barrier per chunk
        if (i + 2 < nch) issue(i + 2, (i + 2) % STAGES);

        const uint32_t st  = sb + (i % STAGES) * STAGE_BYTES;
        const uint32_t AhS = st, AlS = st + 8192, BhS = st + BOFF, BlS = st + 24576;
#pragma unroll
        for (int ks = 0; ks < 2; ks++) {
            uint32_t ah[2][4], al[2][4];
#pragma unroll
            for (int mf = 0; mf < 2; mf++) {
                const uint32_t swo = SW64((uint32_t)((wm + mf * 16 + a_row) * 64
                                                     + (ks * 16 + a_kc) * 2));
                ldm_x4(ah[mf], AhS + swo);
                if (PASSES >= 2) ldm_x4(al[mf], AlS + swo);
            }
#pragma unroll
            for (int p = 0; p < 4; p++) {
                uint32_t bh[4];
                const uint32_t swo = SW64((uint32_t)((wn + p * 16 + b_row) * 64
                                                     + (ks * 16 + b_kc) * 2));
                ldm_x4(bh, BhS + swo);
                if (PASSES == 3) {
                    uint32_t bl[4];
                    ldm_x4(bl, BlS + swo);
#pragma unroll
                    for (int mf = 0; mf < 2; mf++) {
                        mma_bf16(acc[mf][2 * p],     ah[mf], bh);
                        mma_bf16(acc[mf][2 * p + 1], ah[mf], bh + 2);
                        mma_bf16(acc[mf][2 * p],     al[mf], bh);
                        mma_bf16(acc[mf][2 * p + 1], al[mf], bh + 2);
                        mma_bf16(acc[mf][2 * p],     ah[mf], bl);
                        mma_bf16(acc[mf][2 * p + 1], ah[mf], bl + 2);
                    }
                } else if (PASSES == 2) {
#pragma unroll
                    for (int mf = 0; mf < 2; mf++) {
                        mma_fp16(acc[mf][2 * p],     ah[mf], bh);
                        mma_fp16(acc[mf][2 * p + 1], ah[mf], bh + 2);
                        mma_fp16(acc[mf][2 * p],     al[mf], bh);
                        mma_fp16(acc[mf][2 * p + 1], al[mf], bh + 2);
                    }
                } else {
#pragma unroll
                    for (int mf = 0; mf < 2; mf++) {
                        mma_fp16(acc[mf][2 * p],     ah[mf], bh);
                        mma_fp16(acc[mf][2 * p + 1], ah[mf], bh + 2);
                    }
                }
            }
        }
    }

    // ---------------- epilogue ----------------
    const int r  = lane >> 2;
    const int c2 = (lane & 3) * 2;
#pragma unroll
    for (int mf = 0; mf < 2; mf++) {
#pragma unroll
        for (int hh = 0; hh < 2; hh++) {
            const int m = m0 + wm + mf * 16 + r + 8 * hh;
            const size_t rofs = (size_t)z * sC + (size_t)m * ldc + n0 + wn;
#pragma unroll
            for (int nf = 0; nf < 8; nf++) {
                float x0 = acc[mf][nf][2 * hh]     * alpha;
                float x1 = acc[mf][nf][2 * hh + 1] * alpha;
                const int nn = nf * 8 + c2;
                if (OUT == OUT_F32RES) {
                    const float2 rr = *(const float2*)(Res + (size_t)m * ldc + n0 + wn + nn);
                    x0 += rr.x; x1 += rr.y;
                } else if (OUT == OUT_RELU_HI) {
                    x0 = fmaxf(x0, 0.f); x1 = fmaxf(x1, 0.f);
                }
                if (OUT == OUT_F32 || OUT == OUT_F32RES) {
                    *(float2*)(Cf + rofs + nn) = make_float2(x0, x1);
                } else if (OUT == OUT_PAIR_BF16) {
                    uint32_t lo;
                    const uint32_t hi = split2b(x0, x1, lo);
                    *(uint32_t*)(Chi + rofs + nn) = hi;
                    *(uint32_t*)(Clo + rofs + nn) = lo;
                } else if (OUT == OUT_PAIR_FP16) {
                    uint32_t lo;
                    const uint32_t hi = split2h(x0, x1, lo);
                    *(uint32_t*)(Chi + rofs + nn) = hi;
                    *(uint32_t*)(Clo + rofs + nn) = lo;
                } else {  // OUT_RELU_HI: fp16 hi only
                    __half2 h2 = __halves2half2(__float2half_rn(x0), __float2half_rn(x1));
                    *(uint32_t*)(Chi + rofs + nn) = *reinterpret_cast<uint32_t*>(&h2);
                }
            }
        }
    }
}

// ---------------- launch ----------------
extern "C" void kernel_launch(void* const* d_in, const int* in_sizes, int n_in,
                              void* d_out, int out_size)
{
    const int*   tokens = (const int*)d_in[0];
    const float* temb   = (const float*)d_in[1];
    const float* pemb   = (const float*)d_in[2];
    const float* wq     = (const float*)d_in[3];
    const float* wk     = (const float*)d_in[4];
    const float* wv     = (const float*)d_in[5];
    const float* wo     = (const float*)d_in[6];
    const float* wfi    = (const float*)d_in[7];
    const float* wfo    = (const float*)d_in[8];
    const float* ln1g   = (const float*)d_in[9];
    const float* ln1b   = (const float*)d_in[10];
    const float* ln2g   = (const float*)d_in[11];
    const float* ln2b   = (const float*)d_in[12];
    const float* lnfg   = (const float*)d_in[13];
    const float* lnfb   = (const float*)d_in[14];
    const float* wout   = (const float*)d_in[15];
    float*       out    = (float*)d_out;

    float *px, *px2, *px3, *pat;
    HALF *phh, *phl, *ph2h, *ph2l, *phfh, *phfl, *paoh, *paol, *pffh;
    BF16 *pqkvh, *pqkvl, *pvth, *pvtl, *pph, *ppl;
    HALF *pwqkvTh, *pwoTh, *pwfiTh, *pwfoTh, *pwoutTh;
    cudaGetSymbolAddress((void**)&px,   g_x);
    cudaGetSymbolAddress((void**)&px2,  g_x2);
    cudaGetSymbolAddress((void**)&px3,  g_x3);
    cudaGetSymbolAddress((void**)&pat,  g_at);
    cudaGetSymbolAddress((void**)&phh,  g_hh);
    cudaGetSymbolAddress((void**)&phl,  g_hl);
    cudaGetSymbolAddress((void**)&ph2h, g_h2h);
    cudaGetSymbolAddress((void**)&ph2l, g_h2l);
    cudaGetSymbolAddress((void**)&phfh, g_hfh);
    cudaGetSymbolAddress((void**)&phfl, g_hfl);
    cudaGetSymbolAddress((void**)&paoh, g_aoh);
    cudaGetSymbolAddress((void**)&paol, g_aol);
    cudaGetSymbolAddress((void**)&pffh, g_ffh);
    cudaGetSymbolAddress((void**)&pqkvh, g_qkvh);
    cudaGetSymbolAddress((void**)&pqkvl, g_qkvl);
    cudaGetSymbolAddress((void**)&pvth, g_vth);
    cudaGetSymbolAddress((void**)&pvtl, g_vtl);
    cudaGetSymbolAddress((void**)&pph,  g_ph);
    cudaGetSymbolAddress((void**)&ppl,  g_pl);
    cudaGetSymbolAddress((void**)&pwqkvTh, g_wqkvTh);
    cudaGetSymbolAddress((void**)&pwoTh, g_woTh);
    cudaGetSymbolAddress((void**)&pwfiTh, g_wfiTh);
    cudaGetSymbolAddress((void**)&pwfoTh, g_wfoTh);
    cudaGetSymbolAddress((void**)&pwoutTh, g_woutTh);

    cudaFuncSetAttribute(tc_gemm<OUT_PAIR_BF16, 2>,
                         cudaFuncAttributeMaxDynamicSharedMemorySize, GEMM_SMEM2);
    cudaFuncSetAttribute(tc_gemm<OUT_F32, 3>,
                         cudaFuncAttributeMaxDynamicSharedMemorySize, GEMM_SMEM3);
    cudaFuncSetAttribute(tc_gemm<OUT_PAIR_FP16, 3>,
                         cudaFuncAttributeMaxDynamicSharedMemorySize, GEMM_SMEM3);
    cudaFuncSetAttribute(tc_gemm<OUT_F32RES, 2>,
                         cudaFuncAttributeMaxDynamicSharedMemorySize, GEMM_SMEM2);
    cudaFuncSetAttribute(tc_gemm<OUT_RELU_HI, 1>,
                         cudaFuncAttributeMaxDynamicSharedMemorySize, GEMM_SMEM1);
    cudaFuncSetAttribute(tc_gemm<OUT_F32RES, 1>,
                         cudaFuncAttributeMaxDynamicSharedMemorySize, GEMM_SMEM1);
    cudaFuncSetAttribute(tc_gemm<OUT_F32, 1>,
                         cudaFuncAttributeMaxDynamicSharedMemorySize, GEMM_SMEM1);

    // ---- side stream for weight conversions not needed until later ----
    cudaStream_t s2;
    cudaStreamCreateWithFlags(&s2, cudaStreamNonBlocking);
    cudaEvent_t evFork, evWo, evWfi, evWfo, evWout;
    cudaEventCreateWithFlags(&evFork, cudaEventDisableTiming);
    cudaEventCreateWithFlags(&evWo,   cudaEventDisableTiming);
    cudaEventCreateWithFlags(&evWfi,  cudaEventDisableTiming);
    cudaEventCreateWithFlags(&evWfo,  cudaEventDisableTiming);
    cudaEventCreateWithFlags(&evWout, cudaEventDisableTiming);

    detect_tok_kernel<<<1, 256>>>(tokens);
    cudaEventRecord(evFork, 0);
    cudaStreamWaitEvent(s2, evFork, 0);

    // side stream: conversions consumed only after the attention phase
    convT_kernel<<<dim3(D / 32, D / 32), 256, 0, s2>>>(wo, D, D, pwoTh);
    cudaEventRecord(evWo, s2);
    convT_kernel<<<dim3(FF / 32, D / 32), 256, 0, s2>>>(wfi, D, FF, pwfiTh);
    cudaEventRecord(evWfi, s2);
    convT_kernel<<<dim3(D / 32, FF / 32), 256, 0, s2>>>(wfo, FF, D, pwfoTh);
    cudaEventRecord(evWfo, s2);
    convT_kernel<<<dim3(VOC / 32, D / 32), 256, 0, s2>>>(wout, D, VOC, pwoutTh);
    cudaEventRecord(evWout, s2);

    // main stream
    embed_kernel<<<S, 256>>>(tokens, temb, pemb, px);
    convT_kernel<<<dim3(D / 32, D / 32), 256>>>(wq, D, D, pwqkvTh);
    convT_kernel<<<dim3(D / 32, D / 32), 256>>>(wk, D, D, pwqkvTh + DD);
    convT_kernel<<<dim3(D / 32, D / 32), 256>>>(wv, D, D, pwqkvTh + 2 * DD);

    // attention block
    ln_kernel<<<S, 256>>>(px, ln1g, ln1b, phh, phl);
    tc_gemm<OUT_PAIR_BF16, 2><<<dim3(S / 128, D / 128, 3), 256, GEMM_SMEM2>>>(
        (uint16_t*)phh, (uint16_t*)phl, D, 0, (uint16_t*)pwqkvTh, nullptr, D, DD, nullptr,
        nullptr, (uint16_t*)pqkvh, (uint16_t*)pqkvl, D, SD, D, 1.f);
    vtrans_kernel<<<dim3(HD / 32, S / 32, H), 256>>>(pqkvh + 2 * SD, pqkvl + 2 * SD, pvth, pvtl);
    tc_gemm<OUT_F32, 3><<<dim3(S / 128, S / 128, H), 256, GEMM_SMEM3>>>(
        (uint16_t*)pqkvh, (uint16_t*)pqkvl, D, HD,
        (uint16_t*)(pqkvh + SD), (uint16_t*)(pqkvl + SD), D, HD, nullptr,
        pat, nullptr, nullptr, S, (long long)S * S, HD, 0.08838834764831845f);
    softmax_kernel<<<H * S, 256>>>(pat, pph, ppl);
    tc_gemm<OUT_PAIR_FP16, 3><<<dim3(S / 128, 1, H), 256, GEMM_SMEM3>>>(
        (uint16_t*)pph, (uint16_t*)ppl, S, (long long)S * S,
        (uint16_t*)pvth, (uint16_t*)pvtl, S, (long long)HD * S, nullptr,
        nullptr, (uint16_t*)paoh, (uint16_t*)paol, D, HD, S, 1.f);
    cudaStreamWaitEvent(0, evWo, 0);
    tc_gemm<OUT_F32RES, 2><<<dim3(S / 128, D / 128, 1), 256, GEMM_SMEM2>>>(
        (uint16_t*)paoh, (uint16_t*)paol, D, 0, (uint16_t*)pwoTh, nullptr, D, 0, px,
        px2, nullptr, nullptr, D, 0, D, 1.f);

    // FFN block (1-pass fp16: A-lo dropped)
    ln_kernel<<<S, 256>>>(px2, ln2g, ln2b, ph2h, ph2l);
    cudaStreamWaitEvent(0, evWfi, 0);
    tc_gemm<OUT_RELU_HI, 1><<<dim3(S / 128, FF / 128, 1), 256, GEMM_SMEM1>>>(
        (uint16_t*)ph2h, nullptr, D, 0, (uint16_t*)pwfiTh, nullptr, D, 0, nullptr,
        nullptr, (uint16_t*)pffh, nullptr, FF, 0, D, 1.f);
    cudaStreamWaitEvent(0, evWfo, 0);
    tc_gemm<OUT_F32RES, 1><<<dim3(S / 128, D / 128, 1), 256, GEMM_SMEM1>>>(
        (uint16_t*)pffh, nullptr, FF, 0, (uint16_t*)pwfoTh, nullptr, FF, 0, px2,
        px3, nullptr, nullptr, D, 0, FF, 1.f);

    // final LN + logits (1-pass fp16)
    ln_kernel<<<S, 256>>>(px3, lnfg, lnfb, phfh, phfl);
    cudaStreamWaitEvent(0, evWout, 0);
    tc_gemm<OUT_F32, 1><<<dim3(S / 128, VOC / 128, 1), 256, GEMM_SMEM1>>>(
        (uint16_t*)phfh, nullptr, D, 0, (uint16_t*)pwoutTh, nullptr, D, 0, nullptr,
        out, nullptr, nullptr, VOC, 0, D, 1.f);
}

// round 8
// speedup vs baseline: 6.6795x; 1.0784x over previous
#include <cuda_runtime.h>
#include <cuda_bf16.h>
#include <cuda_fp16.h>
#include <stdint.h>
#include <math.h>

typedef __nv_bfloat16 BF16;
typedef __half        HALF;

// ---------------- dimensions ----------------
#define S   2048
#define D   2048
#define H   16
#define HD  128
#define FF  8192
#define VOC 32000
#define LN_EPS 1e-5f
#define SD  (S * D)
#define DD  (D * D)

// ---------------- scratch ----------------
__device__ float g_x  [SD];
__device__ float g_x2 [SD];
__device__ float g_x3 [SD];
__device__ float g_at [H * S * S];

// fp16 activation splits
__device__ HALF g_hh [SD],  g_hl [SD];
__device__ HALF g_h2h[SD],  g_h2l[SD];
__device__ HALF g_hfh[SD],  g_hfl[SD];
__device__ HALF g_aoh[SD];
__device__ HALF g_ffh[S * FF];
__device__ HALF g_ph [H * S * S], g_pl [H * S * S];   // P fp16 hi/lo
__device__ HALF g_vth[SD];                            // V^T fp16 hi

// bf16 splits (QK 3-pass operands)
__device__ BF16 g_qkvh[3 * SD], g_qkvl[3 * SD];

// fp16 weights, hi only
__device__ HALF g_wqkvTh[3 * DD];
__device__ HALF g_woTh[DD];
__device__ HALF g_wfiTh[D * FF];
__device__ HALF g_wfoTh[D * FF];
__device__ HALF g_woutTh[(size_t)D * VOC];

__device__ int g_tok64;

// ---------------- PTX helpers (plain sm_103-legal) ----------------
__device__ __forceinline__ uint32_t smem_u32(const void* p) {
    uint32_t a;
    asm("{ .reg .u64 t; cvta.to.shared.u64 t, %1; cvt.u32.u64 %0, t; }" : "=r"(a) : "l"(p));
    return a;
}
__device__ __forceinline__ void ldm_x4(uint32_t* r, uint32_t addr) {
    asm volatile("ldmatrix.sync.aligned.m8n8.x4.shared.b16 {%0,%1,%2,%3}, [%4];"
                 : "=r"(r[0]), "=r"(r[1]), "=r"(r[2]), "=r"(r[3]) : "r"(addr));
}
__device__ __forceinline__ void mma_bf16(float* c, const uint32_t* a, const uint32_t* b) {
    asm volatile(
        "mma.sync.aligned.m16n8k16.row.col.f32.bf16.bf16.f32 "
        "{%0,%1,%2,%3}, {%4,%5,%6,%7}, {%8,%9}, {%0,%1,%2,%3};"
        : "+f"(c[0]), "+f"(c[1]), "+f"(c[2]), "+f"(c[3])
        : "r"(a[0]), "r"(a[1]), "r"(a[2]), "r"(a[3]), "r"(b[0]), "r"(b[1]));
}
__device__ __forceinline__ void mma_fp16(float* c, const uint32_t* a, const uint32_t* b) {
    asm volatile(
        "mma.sync.aligned.m16n8k16.row.col.f32.f16.f16.f32 "
        "{%0,%1,%2,%3}, {%4,%5,%6,%7}, {%8,%9}, {%0,%1,%2,%3};"
        : "+f"(c[0]), "+f"(c[1]), "+f"(c[2]), "+f"(c[3])
        : "r"(a[0]), "r"(a[1]), "r"(a[2]), "r"(a[3]), "r"(b[0]), "r"(b[1]));
}
#define CP16(dst, src) \
    asm volatile("cp.async.cg.shared.global [%0], [%1], 16;" :: "r"(dst), "l"(src) : "memory")
#define CPCOMMIT() asm volatile("cp.async.commit_group;" ::: "memory")
#define CPWAIT0() asm volatile("cp.async.wait_group 0;" ::: "memory")
#define CPWAIT1() asm volatile("cp.async.wait_group 1;" ::: "memory")
#define CPWAIT2() asm volatile("cp.async.wait_group 2;" ::: "memory")

#define SW64(o) ((o) ^ (((o) >> 3) & 0x30))

// split fp32 pair -> bf16 hi pair (ret) + bf16 lo pair (out param)
__device__ __forceinline__ uint32_t split2b(float a, float b, uint32_t& lo)
{
    BF16 ha = __float2bfloat16(a);
    BF16 hb = __float2bfloat16(b);
    __nv_bfloat162 l2;
    l2.x = __float2bfloat16(a - __bfloat162float(ha));
    l2.y = __float2bfloat16(b - __bfloat162float(hb));
    lo = *reinterpret_cast<uint32_t*>(&l2);
    __nv_bfloat162 h2; h2.x = ha; h2.y = hb;
    return *reinterpret_cast<uint32_t*>(&h2);
}
// split fp32 pair -> fp16 hi pair + fp16 lo pair
__device__ __forceinline__ uint32_t split2h(float a, float b, uint32_t& lo)
{
    HALF ha = __float2half_rn(a);
    HALF hb = __float2half_rn(b);
    __half2 l2 = __halves2half2(__float2half_rn(a - __half2float(ha)),
                                __float2half_rn(b - __half2float(hb)));
    lo = *reinterpret_cast<uint32_t*>(&l2);
    __half2 h2 = __halves2half2(ha, hb);
    return *reinterpret_cast<uint32_t*>(&h2);
}

// ---------------- token detect + embed ----------------
__global__ void detect_tok_kernel(const int* __restrict__ t)
{
    __shared__ int any;
    if (threadIdx.x == 0) any = 0;
    __syncthreads();
    int local = 0;
    for (int i = threadIdx.x; i < S / 2; i += blockDim.x)
        if (t[2 * i + 1] != 0) local = 1;
    if (local) any = 1;
    __syncthreads();
    if (threadIdx.x == 0) g_tok64 = (any == 0) ? 1 : 0;
}

__global__ void embed_kernel(const int* __restrict__ tok,
                             const float* __restrict__ te,
                             const float* __restrict__ pe,
                             float* __restrict__ x)
{
    const int s = blockIdx.x;
    const int t = g_tok64 ? tok[2 * s] : tok[s];
    const float4* e = (const float4*)(te + (size_t)t * D);
    const float4* p = (const float4*)(pe + (size_t)s * D);
    float4*       o = (float4*)(x + (size_t)s * D);
    for (int i = threadIdx.x; i < D / 4; i += blockDim.x) {
        float4 a = e[i], b = p[i];
        o[i] = make_float4(a.x + b.x, a.y + b.y, a.z + b.z, a.w + b.w);
    }
}

// ---------------- weight convert + transpose: fp32 [K][N] -> fp16 hi [N][K] ----------------
__global__ void convT_kernel(const float* __restrict__ src, int K, int N,
                             HALF* __restrict__ dhi)
{
    __shared__ float t[32][33];
    const int n0 = blockIdx.x * 32, k0 = blockIdx.y * 32;
    const int tx = threadIdx.x & 31, ty = threadIdx.x >> 5;
#pragma unroll
    for (int r = 0; r < 4; r++)
        t[ty + 8 * r][tx] = src[(size_t)(k0 + ty + 8 * r) * N + n0 + tx];
    __syncthreads();
#pragma unroll
    for (int r = 0; r < 4; r++) {
        const int n = n0 + ty + 8 * r, k = k0 + tx;
        dhi[(size_t)n * K + k] = __float2half_rn(t[tx][ty + 8 * r]);
    }
}

// ---------------- V transpose: bf16 hi/lo [S][D] head slice -> fp16 [H][HD][S] ----------------
__global__ void vtrans_kernel(const BF16* __restrict__ vh, const BF16* __restrict__ vl,
                              HALF* __restrict__ vth)
{
    __shared__ HALF th[32][33];
    const int h = blockIdx.z;
    const int d0 = blockIdx.x * 32, s0 = blockIdx.y * 32;
    const int tx = threadIdx.x & 31, ty = threadIdx.x >> 5;
#pragma unroll
    for (int r = 0; r < 4; r++) {
        const size_t src = (size_t)(s0 + ty + 8 * r) * D + h * HD + d0 + tx;
        const float v = __bfloat162float(vh[src]) + __bfloat162float(vl[src]);
        th[ty + 8 * r][tx] = __float2half_rn(v);
    }
    __syncthreads();
#pragma unroll
    for (int r = 0; r < 4; r++) {
        const size_t dst = ((size_t)h * HD + d0 + ty + 8 * r) * S + s0 + tx;
        vth[dst] = th[tx][ty + 8 * r];
    }
}

// ---------------- layernorm: fp32 in -> fp16 hi/lo out ----------------
__global__ void ln_kernel(const float* __restrict__ x,
                          const float* __restrict__ g,
                          const float* __restrict__ b,
                          HALF* __restrict__ oh, HALF* __restrict__ ol)
{
    __shared__ float r1[8], r2[8];
    __shared__ float s_mean, s_inv;
    const int s   = blockIdx.x;
    const int tid = threadIdx.x;
    const float4* xr = (const float4*)(x + (size_t)s * D);
    float4 v0 = xr[tid];
    float4 v1 = xr[tid + 256];
    float sum = v0.x + v0.y + v0.z + v0.w + v1.x + v1.y + v1.z + v1.w;
    float sq  = v0.x * v0.x + v0.y * v0.y + v0.z * v0.z + v0.w * v0.w
              + v1.x * v1.x + v1.y * v1.y + v1.z * v1.z + v1.w * v1.w;
#pragma unroll
    for (int o = 16; o; o >>= 1) {
        sum += __shfl_xor_sync(0xffffffffu, sum, o);
        sq  += __shfl_xor_sync(0xffffffffu, sq,  o);
    }
    const int w = tid >> 5;
    if ((tid & 31) == 0) { r1[w] = sum; r2[w] = sq; }
    __syncthreads();
    if (tid == 0) {
        float ts = 0.f, tq = 0.f;
#pragma unroll
        for (int i = 0; i < 8; i++) { ts += r1[i]; tq += r2[i]; }
        const float mean = ts / (float)D;
        const float var  = tq / (float)D - mean * mean;
        s_mean = mean;
        s_inv  = rsqrtf(var + LN_EPS);
    }
    __syncthreads();
    const float mean = s_mean, inv = s_inv;
    const float4* gg = (const float4*)g;
    const float4* bb = (const float4*)b;
    float4 g0 = gg[tid], g1 = gg[tid + 256];
    float4 b0 = bb[tid], b1 = bb[tid + 256];
    float o00 = (v0.x - mean) * inv * g0.x + b0.x;
    float o01 = (v0.y - mean) * inv * g0.y + b0.y;
    float o02 = (v0.z - mean) * inv * g0.z + b0.z;
    float o03 = (v0.w - mean) * inv * g0.w + b0.w;
    float o10 = (v1.x - mean) * inv * g1.x + b1.x;
    float o11 = (v1.y - mean) * inv * g1.y + b1.y;
    float o12 = (v1.z - mean) * inv * g1.z + b1.z;
    float o13 = (v1.w - mean) * inv * g1.w + b1.w;
    uint32_t l0, l1, l2, l3;
    const uint32_t h0 = split2h(o00, o01, l0);
    const uint32_t h1 = split2h(o02, o03, l1);
    const uint32_t h2 = split2h(o10, o11, l2);
    const uint32_t h3 = split2h(o12, o13, l3);
    const size_t e0 = (size_t)s * D + tid * 4;
    *(uint2*)(oh + e0)        = make_uint2(h0, h1);
    *(uint2*)(ol + e0)        = make_uint2(l0, l1);
    *(uint2*)(oh + e0 + 1024) = make_uint2(h2, h3);
    *(uint2*)(ol + e0 + 1024) = make_uint2(l2, l3);
}

// ---------------- softmax: fp32 rows -> fp16 hi/lo prob rows ----------------
__global__ void softmax_kernel(const float* __restrict__ sc,
                               HALF* __restrict__ ph, HALF* __restrict__ pl)
{
    __shared__ float r1[8];
    __shared__ float s_max, s_inv;
    const int tid = threadIdx.x;
    const float* r = sc + (size_t)blockIdx.x * S;
    float4 v0 = ((const float4*)r)[tid];
    float4 v1 = ((const float4*)r)[tid + 256];
    float mx = fmaxf(fmaxf(fmaxf(v0.x, v0.y), fmaxf(v0.z, v0.w)),
                     fmaxf(fmaxf(v1.x, v1.y), fmaxf(v1.z, v1.w)));
#pragma unroll
    for (int o = 16; o; o >>= 1) mx = fmaxf(mx, __shfl_xor_sync(0xffffffffu, mx, o));
    const int w = tid >> 5;
    if ((tid & 31) == 0) r1[w] = mx;
    __syncthreads();
    if (tid == 0) {
        float m = r1[0];
#pragma unroll
        for (int i = 1; i < 8; i++) m = fmaxf(m, r1[i]);
        s_max = m;
    }
    __syncthreads();
    mx = s_max;
    v0.x = expf(v0.x - mx); v0.y = expf(v0.y - mx);
    v0.z = expf(v0.z - mx); v0.w = expf(v0.w - mx);
    v1.x = expf(v1.x - mx); v1.y = expf(v1.y - mx);
    v1.z = expf(v1.z - mx); v1.w = expf(v1.w - mx);
    float sum = v0.x + v0.y + v0.z + v0.w + v1.x + v1.y + v1.z + v1.w;
#pragma unroll
    for (int o = 16; o; o >>= 1) sum += __shfl_xor_sync(0xffffffffu, sum, o);
    __syncthreads();
    if ((tid & 31) == 0) r1[w] = sum;
    __syncthreads();
    if (tid == 0) {
        float t = 0.f;
#pragma unroll
        for (int i = 0; i < 8; i++) t += r1[i];
        s_inv = 1.0f / t;
    }
    __syncthreads();
    const float inv = s_inv;
    v0.x *= inv; v0.y *= inv; v0.z *= inv; v0.w *= inv;
    v1.x *= inv; v1.y *= inv; v1.z *= inv; v1.w *= inv;
    uint32_t l0, l1, l2, l3;
    const uint32_t h0 = split2h(v0.x, v0.y, l0);
    const uint32_t h1 = split2h(v0.z, v0.w, l1);
    const uint32_t h2 = split2h(v1.x, v1.y, l2);
    const uint32_t h3 = split2h(v1.z, v1.w, l3);
    const size_t e0 = (size_t)blockIdx.x * S + tid * 4;
    *(uint2*)(ph + e0)        = make_uint2(h0, h1);
    *(uint2*)(pl + e0)        = make_uint2(l0, l1);
    *(uint2*)(ph + e0 + 1024) = make_uint2(h2, h3);
    *(uint2*)(pl + e0 + 1024) = make_uint2(l2, l3);
}

// ---------------- cp.async pipelined split GEMM ----------------
// C[z] = epi(alpha * A[z] @ B[z]^T (+ Res))
// PASSES==3: bf16, 3 passes (AhBh + AlBh + AhBl); 3-stage pipeline
// PASSES==2: fp16, 2 passes ((Ah+Al)Bh);          4-stage pipeline
// PASSES==1: fp16, 1 pass  (Ah Bh);               4-stage pipeline
#define OUT_F32       0
#define OUT_F32RES    1
#define OUT_PAIR_BF16 2
#define OUT_PAIR_FP16 3
#define OUT_RELU_HI   4
#define OUT_HI        5

#define GEMM_SMEM3 (3 * 32768)
#define GEMM_SMEM2 (4 * 24576)
#define GEMM_SMEM1 (4 * 16384)

template <int OUT, int PASSES>
__global__ void __launch_bounds__(256, 2)
tc_gemm(const uint16_t* __restrict__ Ah, const uint16_t* __restrict__ Al, int lda, long long sA,
        const uint16_t* __restrict__ Bh, const uint16_t* __restrict__ Bl, int ldb, long long sB,
        const float* __restrict__ Res,
        float* __restrict__ Cf, uint16_t* __restrict__ Chi, uint16_t* __restrict__ Clo,
        int ldc, long long sC, int K, float alpha)
{
    constexpr int STAGE_BYTES = (PASSES == 3) ? 32768 : (PASSES == 2) ? 24576 : 16384;
    constexpr int BOFF        = (PASSES == 1) ? 8192 : 16384;
    constexpr int NSTAGE      = (PASSES == 3) ? 3 : 4;
    extern __shared__ char smem[];
    const uint32_t sb = smem_u32(smem);
    const int tid = threadIdx.x, wid = tid >> 5, lane = tid & 31;
    const int z = blockIdx.z;
    Ah += (size_t)z * sA;
    if (PASSES >= 2) Al += (size_t)z * sA;
    Bh += (size_t)z * sB;
    if (PASSES == 3) Bl += (size_t)z * sB;
    const int m0 = blockIdx.x * 128;   // M fast-varying
    const int n0 = blockIdx.y * 128;
    const int wm = (wid & 3) * 32;
    const int wn = (wid >> 2) * 64;

    // loader thread mapping: rowL in [0,64), cL = 16B chunk in [0,4)
    const int rowL = tid >> 2;
    const int cL   = tid & 3;
    const uint32_t o0 = SW64((uint32_t)(rowL * 64 + cL * 16));
    const uint32_t o1 = SW64((uint32_t)((rowL + 64) * 64 + cL * 16));
    const uint16_t* aht = Ah + (size_t)(m0 + rowL) * lda + cL * 8;
    const uint16_t* alt = (PASSES >= 2) ? (Al + (size_t)(m0 + rowL) * lda + cL * 8) : nullptr;
    const uint16_t* bht = Bh + (size_t)(n0 + rowL) * ldb + cL * 8;
    const uint16_t* blt = (PASSES == 3) ? (Bl + (size_t)(n0 + rowL) * ldb + cL * 8) : nullptr;
    const size_t a64 = (size_t)64 * lda;
    const size_t b64 = (size_t)64 * ldb;

    auto issue = [&](int idx, int s) {
        const uint32_t st = sb + s * STAGE_BYTES;
        const uint16_t* a1 = aht + idx * 32;
        const uint16_t* b1 = bht + idx * 32;
        CP16(st + o0,        a1);
        CP16(st + BOFF + o0, b1);
        CP16(st + o1,        a1 + a64);
        CP16(st + BOFF + o1, b1 + b64);
        if (PASSES >= 2) {
            const uint16_t* a2 = alt + idx * 32;
            CP16(st + 8192 + o0, a2);
            CP16(st + 8192 + o1, a2 + a64);
        }
        if (PASSES == 3) {
            const uint16_t* b2 = blt + idx * 32;
            CP16(st + 24576 + o0, b2);
            CP16(st + 24576 + o1, b2 + b64);
        }
        CPCOMMIT();
    };

    float acc[2][8][4];
#pragma unroll
    for (int i = 0; i < 2; i++)
#pragma unroll
        for (int j = 0; j < 8; j++)
#pragma unroll
            for (int q = 0; q < 4; q++) acc[i][j][q] = 0.f;

    // ldmatrix lane address components
    const int a_row = lane & 15;
    const int a_kc  = (lane >> 4) * 8;
    const int b_row = (lane & 7) + (lane >> 4) * 8;
    const int b_kc  = ((lane >> 3) & 1) * 8;

    const int nch = K >> 5;
    issue(0, 0);
    issue(1, 1);
    if (NSTAGE == 4 && nch > 2) issue(2, 2);

    for (int i = 0; i < nch; i++) {
        if (NSTAGE == 4) {
            if (i + 2 < nch)      { CPWAIT2(); }
            else if (i + 1 < nch) { CPWAIT1(); }
            else                  { CPWAIT0(); }
        } else {
            if (i + 1 < nch)      { CPWAIT1(); }
            else                  { CPWAIT0(); }
        }
        __syncthreads();                       // single barrier per chunk
        if (i + NSTAGE - 1 < nch) issue(i + NSTAGE - 1, (i + NSTAGE - 1) % NSTAGE);

        const uint32_t st  = sb + (i % NSTAGE) * STAGE_BYTES;
        const uint32_t AhS = st, AlS = st + 8192, BhS = st + BOFF, BlS = st + 24576;
#pragma unroll
        for (int ks = 0; ks < 2; ks++) {
            uint32_t ah[2][4], al[2][4];
#pragma unroll
            for (int mf = 0; mf < 2; mf++) {
                const uint32_t swo = SW64((uint32_t)((wm + mf * 16 + a_row) * 64
                                                     + (ks * 16 + a_kc) * 2));
                ldm_x4(ah[mf], AhS + swo);
                if (PASSES >= 2) ldm_x4(al[mf], AlS + swo);
            }
#pragma unroll
            for (int p = 0; p < 4; p++) {
                uint32_t bh[4];
                const uint32_t swo = SW64((uint32_t)((wn + p * 16 + b_row) * 64
                                                     + (ks * 16 + b_kc) * 2));
                ldm_x4(bh, BhS + swo);
                if (PASSES == 3) {
                    uint32_t bl[4];
                    ldm_x4(bl, BlS + swo);
#pragma unroll
                    for (int mf = 0; mf < 2; mf++) {
                        mma_bf16(acc[mf][2 * p],     ah[mf], bh);
                        mma_bf16(acc[mf][2 * p + 1], ah[mf], bh + 2);
                        mma_bf16(acc[mf][2 * p],     al[mf], bh);
                        mma_bf16(acc[mf][2 * p + 1], al[mf], bh + 2);
                        mma_bf16(acc[mf][2 * p],     ah[mf], bl);
                        mma_bf16(acc[mf][2 * p + 1], ah[mf], bl + 2);
                    }
                } else if (PASSES == 2) {
#pragma unroll
                    for (int mf = 0; mf < 2; mf++) {
                        mma_fp16(acc[mf][2 * p],     ah[mf], bh);
                        mma_fp16(acc[mf][2 * p + 1], ah[mf], bh + 2);
                        mma_fp16(acc[mf][2 * p],     al[mf], bh);
                        mma_fp16(acc[mf][2 * p + 1], al[mf], bh + 2);
                    }
                } else {
#pragma unroll
                    for (int mf = 0; mf < 2; mf++) {
                        mma_fp16(acc[mf][2 * p],     ah[mf], bh);
                        mma_fp16(acc[mf][2 * p + 1], ah[mf], bh + 2);
                    }
                }
            }
        }
    }

    // ---------------- epilogue ----------------
    const int r  = lane >> 2;
    const int c2 = (lane & 3) * 2;
#pragma unroll
    for (int mf = 0; mf < 2; mf++) {
#pragma unroll
        for (int hh = 0; hh < 2; hh++) {
            const int m = m0 + wm + mf * 16 + r + 8 * hh;
            const size_t rofs = (size_t)z * sC + (size_t)m * ldc + n0 + wn;
#pragma unroll
            for (int nf = 0; nf < 8; nf++) {
                float x0 = acc[mf][nf][2 * hh]     * alpha;
                float x1 = acc[mf][nf][2 * hh + 1] * alpha;
                const int nn = nf * 8 + c2;
                if (OUT == OUT_F32RES) {
                    const float2 rr = *(const float2*)(Res + (size_t)m * ldc + n0 + wn + nn);
                    x0 += rr.x; x1 += rr.y;
                } else if (OUT == OUT_RELU_HI) {
                    x0 = fmaxf(x0, 0.f); x1 = fmaxf(x1, 0.f);
                }
                if (OUT == OUT_F32 || OUT == OUT_F32RES) {
                    *(float2*)(Cf + rofs + nn) = make_float2(x0, x1);
                } else if (OUT == OUT_PAIR_BF16) {
                    uint32_t lo;
                    const uint32_t hi = split2b(x0, x1, lo);
                    *(uint32_t*)(Chi + rofs + nn) = hi;
                    *(uint32_t*)(Clo + rofs + nn) = lo;
                } else if (OUT == OUT_PAIR_FP16) {
                    uint32_t lo;
                    const uint32_t hi = split2h(x0, x1, lo);
                    *(uint32_t*)(Chi + rofs + nn) = hi;
                    *(uint32_t*)(Clo + rofs + nn) = lo;
                } else {  // OUT_RELU_HI / OUT_HI: fp16 hi only
                    __half2 h2 = __halves2half2(__float2half_rn(x0), __float2half_rn(x1));
                    *(uint32_t*)(Chi + rofs + nn) = *reinterpret_cast<uint32_t*>(&h2);
                }
            }
        }
    }
}

// ---------------- launch ----------------
extern "C" void kernel_launch(void* const* d_in, const int* in_sizes, int n_in,
                              void* d_out, int out_size)
{
    const int*   tokens = (const int*)d_in[0];
    const float* temb   = (const float*)d_in[1];
    const float* pemb   = (const float*)d_in[2];
    const float* wq     = (const float*)d_in[3];
    const float* wk     = (const float*)d_in[4];
    const float* wv     = (const float*)d_in[5];
    const float* wo     = (const float*)d_in[6];
    const float* wfi    = (const float*)d_in[7];
    const float* wfo    = (const float*)d_in[8];
    const float* ln1g   = (const float*)d_in[9];
    const float* ln1b   = (const float*)d_in[10];
    const float* ln2g   = (const float*)d_in[11];
    const float* ln2b   = (const float*)d_in[12];
    const float* lnfg   = (const float*)d_in[13];
    const float* lnfb   = (const float*)d_in[14];
    const float* wout   = (const float*)d_in[15];
    float*       out    = (float*)d_out;

    float *px, *px2, *px3, *pat;
    HALF *phh, *phl, *ph2h, *ph2l, *phfh, *phfl, *paoh, *pffh, *pph, *ppl, *pvth;
    BF16 *pqkvh, *pqkvl;
    HALF *pwqkvTh, *pwoTh, *pwfiTh, *pwfoTh, *pwoutTh;
    cudaGetSymbolAddress((void**)&px,   g_x);
    cudaGetSymbolAddress((void**)&px2,  g_x2);
    cudaGetSymbolAddress((void**)&px3,  g_x3);
    cudaGetSymbolAddress((void**)&pat,  g_at);
    cudaGetSymbolAddress((void**)&phh,  g_hh);
    cudaGetSymbolAddress((void**)&phl,  g_hl);
    cudaGetSymbolAddress((void**)&ph2h, g_h2h);
    cudaGetSymbolAddress((void**)&ph2l, g_h2l);
    cudaGetSymbolAddress((void**)&phfh, g_hfh);
    cudaGetSymbolAddress((void**)&phfl, g_hfl);
    cudaGetSymbolAddress((void**)&paoh, g_aoh);
    cudaGetSymbolAddress((void**)&pffh, g_ffh);
    cudaGetSymbolAddress((void**)&pph,  g_ph);
    cudaGetSymbolAddress((void**)&ppl,  g_pl);
    cudaGetSymbolAddress((void**)&pvth, g_vth);
    cudaGetSymbolAddress((void**)&pqkvh, g_qkvh);
    cudaGetSymbolAddress((void**)&pqkvl, g_qkvl);
    cudaGetSymbolAddress((void**)&pwqkvTh, g_wqkvTh);
    cudaGetSymbolAddress((void**)&pwoTh, g_woTh);
    cudaGetSymbolAddress((void**)&pwfiTh, g_wfiTh);
    cudaGetSymbolAddress((void**)&pwfoTh, g_wfoTh);
    cudaGetSymbolAddress((void**)&pwoutTh, g_woutTh);

    cudaFuncSetAttribute(tc_gemm<OUT_PAIR_BF16, 2>,
                         cudaFuncAttributeMaxDynamicSharedMemorySize, GEMM_SMEM2);
    cudaFuncSetAttribute(tc_gemm<OUT_F32, 3>,
                         cudaFuncAttributeMaxDynamicSharedMemorySize, GEMM_SMEM3);
    cudaFuncSetAttribute(tc_gemm<OUT_HI, 2>,
                         cudaFuncAttributeMaxDynamicSharedMemorySize, GEMM_SMEM2);
    cudaFuncSetAttribute(tc_gemm<OUT_F32RES, 1>,
                         cudaFuncAttributeMaxDynamicSharedMemorySize, GEMM_SMEM1);
    cudaFuncSetAttribute(tc_gemm<OUT_RELU_HI, 1>,
                         cudaFuncAttributeMaxDynamicSharedMemorySize, GEMM_SMEM1);
    cudaFuncSetAttribute(tc_gemm<OUT_F32, 1>,
                         cudaFuncAttributeMaxDynamicSharedMemorySize, GEMM_SMEM1);

    // ---- side stream for all weight conversions ----
    cudaStream_t s2;
    cudaStreamCreateWithFlags(&s2, cudaStreamNonBlocking);
    cudaEvent_t evFork, evWqkv, evWo, evWfi, evWfo, evWout;
    cudaEventCreateWithFlags(&evFork, cudaEventDisableTiming);
    cudaEventCreateWithFlags(&evWqkv, cudaEventDisableTiming);
    cudaEventCreateWithFlags(&evWo,   cudaEventDisableTiming);
    cudaEventCreateWithFlags(&evWfi,  cudaEventDisableTiming);
    cudaEventCreateWithFlags(&evWfo,  cudaEventDisableTiming);
    cudaEventCreateWithFlags(&evWout, cudaEventDisableTiming);

    detect_tok_kernel<<<1, 256>>>(tokens);
    cudaEventRecord(evFork, 0);
    cudaStreamWaitEvent(s2, evFork, 0);

    // side stream: wqkv first (needed earliest), then later weights
    convT_kernel<<<dim3(D / 32, D / 32), 256, 0, s2>>>(wq, D, D, pwqkvTh);
    convT_kernel<<<dim3(D / 32, D / 32), 256, 0, s2>>>(wk, D, D, pwqkvTh + DD);
    convT_kernel<<<dim3(D / 32, D / 32), 256, 0, s2>>>(wv, D, D, pwqkvTh + 2 * DD);
    cudaEventRecord(evWqkv, s2);
    convT_kernel<<<dim3(D / 32, D / 32), 256, 0, s2>>>(wo, D, D, pwoTh);
    cudaEventRecord(evWo, s2);
    convT_kernel<<<dim3(FF / 32, D / 32), 256, 0, s2>>>(wfi, D, FF, pwfiTh);
    cudaEventRecord(evWfi, s2);
    convT_kernel<<<dim3(D / 32, FF / 32), 256, 0, s2>>>(wfo, FF, D, pwfoTh);
    cudaEventRecord(evWfo, s2);
    convT_kernel<<<dim3(VOC / 32, D / 32), 256, 0, s2>>>(wout, D, VOC, pwoutTh);
    cudaEventRecord(evWout, s2);

    // main stream (embed + ln1 overlap the wqkv conversion)
    embed_kernel<<<S, 256>>>(tokens, temb, pemb, px);
    ln_kernel<<<S, 256>>>(px, ln1g, ln1b, phh, phl);
    cudaStreamWaitEvent(0, evWqkv, 0);

    // attention block
    tc_gemm<OUT_PAIR_BF16, 2><<<dim3(S / 128, D / 128, 3), 256, GEMM_SMEM2>>>(
        (uint16_t*)phh, (uint16_t*)phl, D, 0, (uint16_t*)pwqkvTh, nullptr, D, DD, nullptr,
        nullptr, (uint16_t*)pqkvh, (uint16_t*)pqkvl, D, SD, D, 1.f);
    vtrans_kernel<<<dim3(HD / 32, S / 32, H), 256>>>(pqkvh + 2 * SD, pqkvl + 2 * SD, pvth);
    tc_gemm<OUT_F32, 3><<<dim3(S / 128, S / 128, H), 256, GEMM_SMEM3>>>(
        (uint16_t*)pqkvh, (uint16_t*)pqkvl, D, HD,
        (uint16_t*)(pqkvh + SD), (uint16_t*)(pqkvl + SD), D, HD, nullptr,
        pat, nullptr, nullptr, S, (long long)S * S, HD, 0.08838834764831845f);
    softmax_kernel<<<H * S, 256>>>(pat, pph, ppl);
    // attn_out = P @ V^T  : 2-pass fp16 (P hi/lo x V hi)
    tc_gemm<OUT_HI, 2><<<dim3(S / 128, 1, H), 256, GEMM_SMEM2>>>(
        (uint16_t*)pph, (uint16_t*)ppl, S, (long long)S * S,
        (uint16_t*)pvth, nullptr, S, (long long)HD * S, nullptr,
        nullptr, (uint16_t*)paoh, nullptr, D, HD, S, 1.f);
    cudaStreamWaitEvent(0, evWo, 0);
    // x2 = x + attn_out @ Wo : 1-pass fp16
    tc_gemm<OUT_F32RES, 1><<<dim3(S / 128, D / 128, 1), 256, GEMM_SMEM1>>>(
        (uint16_t*)paoh, nullptr, D, 0, (uint16_t*)pwoTh, nullptr, D, 0, px,
        px2, nullptr, nullptr, D, 0, D, 1.f);

    // FFN block (1-pass fp16)
    ln_kernel<<<S, 256>>>(px2, ln2g, ln2b, ph2h, ph2l);
    cudaStreamWaitEvent(0, evWfi, 0);
    tc_gemm<OUT_RELU_HI, 1><<<dim3(S / 128, FF / 128, 1), 256, GEMM_SMEM1>>>(
        (uint16_t*)ph2h, nullptr, D, 0, (uint16_t*)pwfiTh, nullptr, D, 0, nullptr,
        nullptr, (uint16_t*)pffh, nullptr, FF, 0, D, 1.f);
    cudaStreamWaitEvent(0, evWfo, 0);
    tc_gemm<OUT_F32RES, 1><<<dim3(S / 128, D / 128, 1), 256, GEMM_SMEM1>>>(
        (uint16_t*)pffh, nullptr, FF, 0, (uint16_t*)pwfoTh, nullptr, FF, 0, px2,
        px3, nullptr, nullptr, D, 0, FF, 1.f);

    // final LN + logits (1-pass fp16)
    ln_kernel<<<S, 256>>>(px3, lnfg, lnfb, phfh, phfl);
    cudaStreamWaitEvent(0, evWout, 0);
    tc_gemm<OUT_F32, 1><<<dim3(S / 128, VOC / 128, 1), 256, GEMM_SMEM1>>>(
        (uint16_t*)phfh, nullptr, D, 0, (uint16_t*)pwoutTh, nullptr, D, 0, nullptr,
        out, nullptr, nullptr, VOC, 0, D, 1.f);
}

// round 9
// speedup vs baseline: 7.2251x; 1.0817x over previous
#include <cuda_runtime.h>
#include <cuda_bf16.h>
#include <cuda_fp16.h>
#include <stdint.h>
#include <math.h>

typedef __nv_bfloat16 BF16;
typedef __half        HALF;

// ---------------- dimensions ----------------
#define S   2048
#define D   2048
#define H   16
#define HD  128
#define FF  8192
#define VOC 32000
#define LN_EPS 1e-5f
#define SD  (S * D)
#define DD  (D * D)

// ---------------- scratch ----------------
__device__ float g_x  [SD];
__device__ float g_x2 [SD];
__device__ float g_x3 [SD];
__device__ float g_at [H * S * S];

// fp16 activations (hi only where consumers are 1-pass)
__device__ HALF g_hh [SD];
__device__ HALF g_h2h[SD];
__device__ HALF g_hfh[SD];
__device__ HALF g_aoh[SD];
__device__ HALF g_ffh[S * FF];
__device__ HALF g_ph [H * S * S];     // P fp16 hi
__device__ HALF g_vth[SD];            // V^T fp16 hi

// bf16 splits (QK 3-pass operands)
__device__ BF16 g_qkvh[3 * SD], g_qkvl[3 * SD];

// fp16 weights, hi only
__device__ HALF g_wqkvTh[3 * DD];
__device__ HALF g_woTh[DD];
__device__ HALF g_wfiTh[D * FF];
__device__ HALF g_wfoTh[D * FF];
__device__ HALF g_woutTh[(size_t)D * VOC];

__device__ int g_tok64;

// ---------------- PTX helpers (plain sm_103-legal) ----------------
__device__ __forceinline__ uint32_t smem_u32(const void* p) {
    uint32_t a;
    asm("{ .reg .u64 t; cvta.to.shared.u64 t, %1; cvt.u32.u64 %0, t; }" : "=r"(a) : "l"(p));
    return a;
}
__device__ __forceinline__ void ldm_x4(uint32_t* r, uint32_t addr) {
    asm volatile("ldmatrix.sync.aligned.m8n8.x4.shared.b16 {%0,%1,%2,%3}, [%4];"
                 : "=r"(r[0]), "=r"(r[1]), "=r"(r[2]), "=r"(r[3]) : "r"(addr));
}
__device__ __forceinline__ void mma_bf16(float* c, const uint32_t* a, const uint32_t* b) {
    asm volatile(
        "mma.sync.aligned.m16n8k16.row.col.f32.bf16.bf16.f32 "
        "{%0,%1,%2,%3}, {%4,%5,%6,%7}, {%8,%9}, {%0,%1,%2,%3};"
        : "+f"(c[0]), "+f"(c[1]), "+f"(c[2]), "+f"(c[3])
        : "r"(a[0]), "r"(a[1]), "r"(a[2]), "r"(a[3]), "r"(b[0]), "r"(b[1]));
}
__device__ __forceinline__ void mma_fp16(float* c, const uint32_t* a, const uint32_t* b) {
    asm volatile(
        "mma.sync.aligned.m16n8k16.row.col.f32.f16.f16.f32 "
        "{%0,%1,%2,%3}, {%4,%5,%6,%7}, {%8,%9}, {%0,%1,%2,%3};"
        : "+f"(c[0]), "+f"(c[1]), "+f"(c[2]), "+f"(c[3])
        : "r"(a[0]), "r"(a[1]), "r"(a[2]), "r"(a[3]), "r"(b[0]), "r"(b[1]));
}
#define CP16(dst, src) \
    asm volatile("cp.async.cg.shared.global [%0], [%1], 16;" :: "r"(dst), "l"(src) : "memory")
#define CPCOMMIT() asm volatile("cp.async.commit_group;" ::: "memory")
#define CPWAIT0() asm volatile("cp.async.wait_group 0;" ::: "memory")
#define CPWAIT1() asm volatile("cp.async.wait_group 1;" ::: "memory")
#define CPWAIT2() asm volatile("cp.async.wait_group 2;" ::: "memory")

#define SW64(o) ((o) ^ (((o) >> 3) & 0x30))

// split fp32 pair -> bf16 hi pair (ret) + bf16 lo pair (out param)
__device__ __forceinline__ uint32_t split2b(float a, float b, uint32_t& lo)
{
    BF16 ha = __float2bfloat16(a);
    BF16 hb = __float2bfloat16(b);
    __nv_bfloat162 l2;
    l2.x = __float2bfloat16(a - __bfloat162float(ha));
    l2.y = __float2bfloat16(b - __bfloat162float(hb));
    lo = *reinterpret_cast<uint32_t*>(&l2);
    __nv_bfloat162 h2; h2.x = ha; h2.y = hb;
    return *reinterpret_cast<uint32_t*>(&h2);
}
// split fp32 pair -> fp16 hi pair + fp16 lo pair
__device__ __forceinline__ uint32_t split2h(float a, float b, uint32_t& lo)
{
    HALF ha = __float2half_rn(a);
    HALF hb = __float2half_rn(b);
    __half2 l2 = __halves2half2(__float2half_rn(a - __half2float(ha)),
                                __float2half_rn(b - __half2float(hb)));
    lo = *reinterpret_cast<uint32_t*>(&l2);
    __half2 h2 = __halves2half2(ha, hb);
    return *reinterpret_cast<uint32_t*>(&h2);
}
// fp32 pair -> fp16 pair (packed)
__device__ __forceinline__ uint32_t pack2h(float a, float b)
{
    __half2 h2 = __halves2half2(__float2half_rn(a), __float2half_rn(b));
    return *reinterpret_cast<uint32_t*>(&h2);
}

// ---------------- token detect + embed ----------------
__global__ void detect_tok_kernel(const int* __restrict__ t)
{
    __shared__ int any;
    if (threadIdx.x == 0) any = 0;
    __syncthreads();
    int local = 0;
    for (int i = threadIdx.x; i < S / 2; i += blockDim.x)
        if (t[2 * i + 1] != 0) local = 1;
    if (local) any = 1;
    __syncthreads();
    if (threadIdx.x == 0) g_tok64 = (any == 0) ? 1 : 0;
}

__global__ void embed_kernel(const int* __restrict__ tok,
                             const float* __restrict__ te,
                             const float* __restrict__ pe,
                             float* __restrict__ x)
{
    const int s = blockIdx.x;
    const int t = g_tok64 ? tok[2 * s] : tok[s];
    const float4* e = (const float4*)(te + (size_t)t * D);
    const float4* p = (const float4*)(pe + (size_t)s * D);
    float4*       o = (float4*)(x + (size_t)s * D);
    for (int i = threadIdx.x; i < D / 4; i += blockDim.x) {
        float4 a = e[i], b = p[i];
        o[i] = make_float4(a.x + b.x, a.y + b.y, a.z + b.z, a.w + b.w);
    }
}

// ---------------- weight convert + transpose: fp32 [K][N] -> fp16 hi [N][K] ----------------
__global__ void convT_kernel(const float* __restrict__ src, int K, int N,
                             HALF* __restrict__ dhi)
{
    __shared__ float t[32][33];
    const int n0 = blockIdx.x * 32, k0 = blockIdx.y * 32;
    const int tx = threadIdx.x & 31, ty = threadIdx.x >> 5;
#pragma unroll
    for (int r = 0; r < 4; r++)
        t[ty + 8 * r][tx] = src[(size_t)(k0 + ty + 8 * r) * N + n0 + tx];
    __syncthreads();
#pragma unroll
    for (int r = 0; r < 4; r++) {
        const int n = n0 + ty + 8 * r, k = k0 + tx;
        dhi[(size_t)n * K + k] = __float2half_rn(t[tx][ty + 8 * r]);
    }
}

// ---------------- V transpose: bf16 hi/lo [S][D] head slice -> fp16 [H][HD][S] ----------------
__global__ void vtrans_kernel(const BF16* __restrict__ vh, const BF16* __restrict__ vl,
                              HALF* __restrict__ vth)
{
    __shared__ HALF th[32][33];
    const int h = blockIdx.z;
    const int d0 = blockIdx.x * 32, s0 = blockIdx.y * 32;
    const int tx = threadIdx.x & 31, ty = threadIdx.x >> 5;
#pragma unroll
    for (int r = 0; r < 4; r++) {
        const size_t src = (size_t)(s0 + ty + 8 * r) * D + h * HD + d0 + tx;
        const float v = __bfloat162float(vh[src]) + __bfloat162float(vl[src]);
        th[ty + 8 * r][tx] = __float2half_rn(v);
    }
    __syncthreads();
#pragma unroll
    for (int r = 0; r < 4; r++) {
        const size_t dst = ((size_t)h * HD + d0 + ty + 8 * r) * S + s0 + tx;
        vth[dst] = th[tx][ty + 8 * r];
    }
}

// ---------------- layernorm: fp32 in -> fp16 hi out ----------------
__global__ void ln_kernel(const float* __restrict__ x,
                          const float* __restrict__ g,
                          const float* __restrict__ b,
                          HALF* __restrict__ oh)
{
    __shared__ float r1[8], r2[8];
    __shared__ float s_mean, s_inv;
    const int s   = blockIdx.x;
    const int tid = threadIdx.x;
    const float4* xr = (const float4*)(x + (size_t)s * D);
    float4 v0 = xr[tid];
    float4 v1 = xr[tid + 256];
    float sum = v0.x + v0.y + v0.z + v0.w + v1.x + v1.y + v1.z + v1.w;
    float sq  = v0.x * v0.x + v0.y * v0.y + v0.z * v0.z + v0.w * v0.w
              + v1.x * v1.x + v1.y * v1.y + v1.z * v1.z + v1.w * v1.w;
#pragma unroll
    for (int o = 16; o; o >>= 1) {
        sum += __shfl_xor_sync(0xffffffffu, sum, o);
        sq  += __shfl_xor_sync(0xffffffffu, sq,  o);
    }
    const int w = tid >> 5;
    if ((tid & 31) == 0) { r1[w] = sum; r2[w] = sq; }
    __syncthreads();
    if (tid == 0) {
        float ts = 0.f, tq = 0.f;
#pragma unroll
        for (int i = 0; i < 8; i++) { ts += r1[i]; tq += r2[i]; }
        const float mean = ts / (float)D;
        const float var  = tq / (float)D - mean * mean;
        s_mean = mean;
        s_inv  = rsqrtf(var + LN_EPS);
    }
    __syncthreads();
    const float mean = s_mean, inv = s_inv;
    const float4* gg = (const float4*)g;
    const float4* bb = (const float4*)b;
    float4 g0 = gg[tid], g1 = gg[tid + 256];
    float4 b0 = bb[tid], b1 = bb[tid + 256];
    float o00 = (v0.x - mean) * inv * g0.x + b0.x;
    float o01 = (v0.y - mean) * inv * g0.y + b0.y;
    float o02 = (v0.z - mean) * inv * g0.z + b0.z;
    float o03 = (v0.w - mean) * inv * g0.w + b0.w;
    float o10 = (v1.x - mean) * inv * g1.x + b1.x;
    float o11 = (v1.y - mean) * inv * g1.y + b1.y;
    float o12 = (v1.z - mean) * inv * g1.z + b1.z;
    float o13 = (v1.w - mean) * inv * g1.w + b1.w;
    const size_t e0 = (size_t)s * D + tid * 4;
    *(uint2*)(oh + e0)        = make_uint2(pack2h(o00, o01), pack2h(o02, o03));
    *(uint2*)(oh + e0 + 1024) = make_uint2(pack2h(o10, o11), pack2h(o12, o13));
}

// ---------------- softmax: fp32 rows -> fp16 hi prob rows ----------------
__global__ void softmax_kernel(const float* __restrict__ sc,
                               HALF* __restrict__ ph)
{
    __shared__ float r1[8];
    __shared__ float s_max, s_inv;
    const int tid = threadIdx.x;
    const float* r = sc + (size_t)blockIdx.x * S;
    float4 v0 = ((const float4*)r)[tid];
    float4 v1 = ((const float4*)r)[tid + 256];
    float mx = fmaxf(fmaxf(fmaxf(v0.x, v0.y), fmaxf(v0.z, v0.w)),
                     fmaxf(fmaxf(v1.x, v1.y), fmaxf(v1.z, v1.w)));
#pragma unroll
    for (int o = 16; o; o >>= 1) mx = fmaxf(mx, __shfl_xor_sync(0xffffffffu, mx, o));
    const int w = tid >> 5;
    if ((tid & 31) == 0) r1[w] = mx;
    __syncthreads();
    if (tid == 0) {
        float m = r1[0];
#pragma unroll
        for (int i = 1; i < 8; i++) m = fmaxf(m, r1[i]);
        s_max = m;
    }
    __syncthreads();
    mx = s_max;
    v0.x = expf(v0.x - mx); v0.y = expf(v0.y - mx);
    v0.z = expf(v0.z - mx); v0.w = expf(v0.w - mx);
    v1.x = expf(v1.x - mx); v1.y = expf(v1.y - mx);
    v1.z = expf(v1.z - mx); v1.w = expf(v1.w - mx);
    float sum = v0.x + v0.y + v0.z + v0.w + v1.x + v1.y + v1.z + v1.w;
#pragma unroll
    for (int o = 16; o; o >>= 1) sum += __shfl_xor_sync(0xffffffffu, sum, o);
    __syncthreads();
    if ((tid & 31) == 0) r1[w] = sum;
    __syncthreads();
    if (tid == 0) {
        float t = 0.f;
#pragma unroll
        for (int i = 0; i < 8; i++) t += r1[i];
        s_inv = 1.0f / t;
    }
    __syncthreads();
    const float inv = s_inv;
    v0.x *= inv; v0.y *= inv; v0.z *= inv; v0.w *= inv;
    v1.x *= inv; v1.y *= inv; v1.z *= inv; v1.w *= inv;
    const size_t e0 = (size_t)blockIdx.x * S + tid * 4;
    *(uint2*)(ph + e0)        = make_uint2(pack2h(v0.x, v0.y), pack2h(v0.z, v0.w));
    *(uint2*)(ph + e0 + 1024) = make_uint2(pack2h(v1.x, v1.y), pack2h(v1.z, v1.w));
}

// ---------------- cp.async pipelined split GEMM ----------------
// C[z] = epi(alpha * A[z] @ B[z]^T (+ Res))
// PASSES==3: bf16, 3 passes (AhBh + AlBh + AhBl); 3-stage pipeline
// PASSES==2: fp16, 2 passes ((Ah+Al)Bh);          4-stage pipeline
// PASSES==1: fp16, 1 pass  (Ah Bh);               4-stage pipeline
#define OUT_F32       0
#define OUT_F32RES    1
#define OUT_PAIR_BF16 2
#define OUT_RELU_HI   4
#define OUT_HI        5

#define GEMM_SMEM3 (3 * 32768)
#define GEMM_SMEM2 (4 * 24576)
#define GEMM_SMEM1 (4 * 16384)

template <int OUT, int PASSES>
__global__ void __launch_bounds__(256, 2)
tc_gemm(const uint16_t* __restrict__ Ah, const uint16_t* __restrict__ Al, int lda, long long sA,
        const uint16_t* __restrict__ Bh, const uint16_t* __restrict__ Bl, int ldb, long long sB,
        const float* __restrict__ Res,
        float* __restrict__ Cf, uint16_t* __restrict__ Chi, uint16_t* __restrict__ Clo,
        int ldc, long long sC, int K, float alpha)
{
    constexpr int STAGE_BYTES = (PASSES == 3) ? 32768 : (PASSES == 2) ? 24576 : 16384;
    constexpr int BOFF        = (PASSES == 1) ? 8192 : 16384;
    constexpr int NSTAGE      = (PASSES == 3) ? 3 : 4;
    extern __shared__ char smem[];
    const uint32_t sb = smem_u32(smem);
    const int tid = threadIdx.x, wid = tid >> 5, lane = tid & 31;
    const int z = blockIdx.z;
    Ah += (size_t)z * sA;
    if (PASSES >= 2) Al += (size_t)z * sA;
    Bh += (size_t)z * sB;
    if (PASSES == 3) Bl += (size_t)z * sB;
    const int m0 = blockIdx.x * 128;   // M fast-varying
    const int n0 = blockIdx.y * 128;
    const int wm = (wid & 3) * 32;
    const int wn = (wid >> 2) * 64;

    // loader thread mapping: rowL in [0,64), cL = 16B chunk in [0,4)
    const int rowL = tid >> 2;
    const int cL   = tid & 3;
    const uint32_t o0 = SW64((uint32_t)(rowL * 64 + cL * 16));
    const uint32_t o1 = SW64((uint32_t)((rowL + 64) * 64 + cL * 16));
    const uint16_t* aht = Ah + (size_t)(m0 + rowL) * lda + cL * 8;
    const uint16_t* alt = (PASSES >= 2) ? (Al + (size_t)(m0 + rowL) * lda + cL * 8) : nullptr;
    const uint16_t* bht = Bh + (size_t)(n0 + rowL) * ldb + cL * 8;
    const uint16_t* blt = (PASSES == 3) ? (Bl + (size_t)(n0 + rowL) * ldb + cL * 8) : nullptr;
    const size_t a64 = (size_t)64 * lda;
    const size_t b64 = (size_t)64 * ldb;

    auto issue = [&](int idx, int s) {
        const uint32_t st = sb + s * STAGE_BYTES;
        const uint16_t* a1 = aht + idx * 32;
        const uint16_t* b1 = bht + idx * 32;
        CP16(st + o0,        a1);
        CP16(st + BOFF + o0, b1);
        CP16(st + o1,        a1 + a64);
        CP16(st + BOFF + o1, b1 + b64);
        if (PASSES >= 2) {
            const uint16_t* a2 = alt + idx * 32;
            CP16(st + 8192 + o0, a2);
            CP16(st + 8192 + o1, a2 + a64);
        }
        if (PASSES == 3) {
            const uint16_t* b2 = blt + idx * 32;
            CP16(st + 24576 + o0, b2);
            CP16(st + 24576 + o1, b2 + b64);
        }
        CPCOMMIT();
    };

    float acc[2][8][4];
#pragma unroll
    for (int i = 0; i < 2; i++)
#pragma unroll
        for (int j = 0; j < 8; j++)
#pragma unroll
            for (int q = 0; q < 4; q++) acc[i][j][q] = 0.f;

    // ldmatrix lane address components
    const int a_row = lane & 15;
    const int a_kc  = (lane >> 4) * 8;
    const int b_row = (lane & 7) + (lane >> 4) * 8;
    const int b_kc  = ((lane >> 3) & 1) * 8;

    const int nch = K >> 5;
    issue(0, 0);
    issue(1, 1);
    if (NSTAGE == 4 && nch > 2) issue(2, 2);

    for (int i = 0; i < nch; i++) {
        if (NSTAGE == 4) {
            if (i + 2 < nch)      { CPWAIT2(); }
            else if (i + 1 < nch) { CPWAIT1(); }
            else                  { CPWAIT0(); }
        } else {
            if (i + 1 < nch)      { CPWAIT1(); }
            else                  { CPWAIT0(); }
        }
        __syncthreads();                       // single barrier per chunk
        if (i + NSTAGE - 1 < nch) issue(i + NSTAGE - 1, (i + NSTAGE - 1) % NSTAGE);

        const uint32_t st  = sb + (i % NSTAGE) * STAGE_BYTES;
        const uint32_t AhS = st, AlS = st + 8192, BhS = st + BOFF, BlS = st + 24576;
#pragma unroll
        for (int ks = 0; ks < 2; ks++) {
            uint32_t ah[2][4], al[2][4];
#pragma unroll
            for (int mf = 0; mf < 2; mf++) {
                const uint32_t swo = SW64((uint32_t)((wm + mf * 16 + a_row) * 64
                                                     + (ks * 16 + a_kc) * 2));
                ldm_x4(ah[mf], AhS + swo);
                if (PASSES >= 2) ldm_x4(al[mf], AlS + swo);
            }
#pragma unroll
            for (int p = 0; p < 4; p++) {
                uint32_t bh[4];
                const uint32_t swo = SW64((uint32_t)((wn + p * 16 + b_row) * 64
                                                     + (ks * 16 + b_kc) * 2));
                ldm_x4(bh, BhS + swo);
                if (PASSES == 3) {
                    uint32_t bl[4];
                    ldm_x4(bl, BlS + swo);
#pragma unroll
                    for (int mf = 0; mf < 2; mf++) {
                        mma_bf16(acc[mf][2 * p],     ah[mf], bh);
                        mma_bf16(acc[mf][2 * p + 1], ah[mf], bh + 2);
                        mma_bf16(acc[mf][2 * p],     al[mf], bh);
                        mma_bf16(acc[mf][2 * p + 1], al[mf], bh + 2);
                        mma_bf16(acc[mf][2 * p],     ah[mf], bl);
                        mma_bf16(acc[mf][2 * p + 1], ah[mf], bl + 2);
                    }
                } else if (PASSES == 2) {
#pragma unroll
                    for (int mf = 0; mf < 2; mf++) {
                        mma_fp16(acc[mf][2 * p],     ah[mf], bh);
                        mma_fp16(acc[mf][2 * p + 1], ah[mf], bh + 2);
                        mma_fp16(acc[mf][2 * p],     al[mf], bh);
                        mma_fp16(acc[mf][2 * p + 1], al[mf], bh + 2);
                    }
                } else {
#pragma unroll
                    for (int mf = 0; mf < 2; mf++) {
                        mma_fp16(acc[mf][2 * p],     ah[mf], bh);
                        mma_fp16(acc[mf][2 * p + 1], ah[mf], bh + 2);
                    }
                }
            }
        }
    }

    // ---------------- epilogue ----------------
    const int r  = lane >> 2;
    const int c2 = (lane & 3) * 2;
#pragma unroll
    for (int mf = 0; mf < 2; mf++) {
#pragma unroll
        for (int hh = 0; hh < 2; hh++) {
            const int m = m0 + wm + mf * 16 + r + 8 * hh;
            const size_t rofs = (size_t)z * sC + (size_t)m * ldc + n0 + wn;
#pragma unroll
            for (int nf = 0; nf < 8; nf++) {
                float x0 = acc[mf][nf][2 * hh]     * alpha;
                float x1 = acc[mf][nf][2 * hh + 1] * alpha;
                const int nn = nf * 8 + c2;
                if (OUT == OUT_F32RES) {
                    const float2 rr = *(const float2*)(Res + (size_t)m * ldc + n0 + wn + nn);
                    x0 += rr.x; x1 += rr.y;
                } else if (OUT == OUT_RELU_HI) {
                    x0 = fmaxf(x0, 0.f); x1 = fmaxf(x1, 0.f);
                }
                if (OUT == OUT_F32 || OUT == OUT_F32RES) {
                    *(float2*)(Cf + rofs + nn) = make_float2(x0, x1);
                } else if (OUT == OUT_PAIR_BF16) {
                    uint32_t lo;
                    const uint32_t hi = split2b(x0, x1, lo);
                    *(uint32_t*)(Chi + rofs + nn) = hi;
                    *(uint32_t*)(Clo + rofs + nn) = lo;
                } else {  // OUT_RELU_HI / OUT_HI: fp16 hi only
                    *(uint32_t*)(Chi + rofs + nn) = pack2h(x0, x1);
                }
            }
        }
    }
}

// ---------------- launch ----------------
extern "C" void kernel_launch(void* const* d_in, const int* in_sizes, int n_in,
                              void* d_out, int out_size)
{
    const int*   tokens = (const int*)d_in[0];
    const float* temb   = (const float*)d_in[1];
    const float* pemb   = (const float*)d_in[2];
    const float* wq     = (const float*)d_in[3];
    const float* wk     = (const float*)d_in[4];
    const float* wv     = (const float*)d_in[5];
    const float* wo     = (const float*)d_in[6];
    const float* wfi    = (const float*)d_in[7];
    const float* wfo    = (const float*)d_in[8];
    const float* ln1g   = (const float*)d_in[9];
    const float* ln1b   = (const float*)d_in[10];
    const float* ln2g   = (const float*)d_in[11];
    const float* ln2b   = (const float*)d_in[12];
    const float* lnfg   = (const float*)d_in[13];
    const float* lnfb   = (const float*)d_in[14];
    const float* wout   = (const float*)d_in[15];
    float*       out    = (float*)d_out;

    float *px, *px2, *px3, *pat;
    HALF *phh, *ph2h, *phfh, *paoh, *pffh, *pph, *pvth;
    BF16 *pqkvh, *pqkvl;
    HALF *pwqkvTh, *pwoTh, *pwfiTh, *pwfoTh, *pwoutTh;
    cudaGetSymbolAddress((void**)&px,   g_x);
    cudaGetSymbolAddress((void**)&px2,  g_x2);
    cudaGetSymbolAddress((void**)&px3,  g_x3);
    cudaGetSymbolAddress((void**)&pat,  g_at);
    cudaGetSymbolAddress((void**)&phh,  g_hh);
    cudaGetSymbolAddress((void**)&ph2h, g_h2h);
    cudaGetSymbolAddress((void**)&phfh, g_hfh);
    cudaGetSymbolAddress((void**)&paoh, g_aoh);
    cudaGetSymbolAddress((void**)&pffh, g_ffh);
    cudaGetSymbolAddress((void**)&pph,  g_ph);
    cudaGetSymbolAddress((void**)&pvth, g_vth);
    cudaGetSymbolAddress((void**)&pqkvh, g_qkvh);
    cudaGetSymbolAddress((void**)&pqkvl, g_qkvl);
    cudaGetSymbolAddress((void**)&pwqkvTh, g_wqkvTh);
    cudaGetSymbolAddress((void**)&pwoTh, g_woTh);
    cudaGetSymbolAddress((void**)&pwfiTh, g_wfiTh);
    cudaGetSymbolAddress((void**)&pwfoTh, g_wfoTh);
    cudaGetSymbolAddress((void**)&pwoutTh, g_woutTh);

    cudaFuncSetAttribute(tc_gemm<OUT_PAIR_BF16, 1>,
                         cudaFuncAttributeMaxDynamicSharedMemorySize, GEMM_SMEM1);
    cudaFuncSetAttribute(tc_gemm<OUT_F32, 3>,
                         cudaFuncAttributeMaxDynamicSharedMemorySize, GEMM_SMEM3);
    cudaFuncSetAttribute(tc_gemm<OUT_HI, 1>,
                         cudaFuncAttributeMaxDynamicSharedMemorySize, GEMM_SMEM1);
    cudaFuncSetAttribute(tc_gemm<OUT_F32RES, 1>,
                         cudaFuncAttributeMaxDynamicSharedMemorySize, GEMM_SMEM1);
    cudaFuncSetAttribute(tc_gemm<OUT_RELU_HI, 1>,
                         cudaFuncAttributeMaxDynamicSharedMemorySize, GEMM_SMEM1);
    cudaFuncSetAttribute(tc_gemm<OUT_F32, 1>,
                         cudaFuncAttributeMaxDynamicSharedMemorySize, GEMM_SMEM1);

    // ---- side stream for all weight conversions ----
    cudaStream_t s2;
    cudaStreamCreateWithFlags(&s2, cudaStreamNonBlocking);
    cudaEvent_t evFork, evWqkv, evWo, evWfi, evWfo, evWout;
    cudaEventCreateWithFlags(&evFork, cudaEventDisableTiming);
    cudaEventCreateWithFlags(&evWqkv, cudaEventDisableTiming);
    cudaEventCreateWithFlags(&evWo,   cudaEventDisableTiming);
    cudaEventCreateWithFlags(&evWfi,  cudaEventDisableTiming);
    cudaEventCreateWithFlags(&evWfo,  cudaEventDisableTiming);
    cudaEventCreateWithFlags(&evWout, cudaEventDisableTiming);

    detect_tok_kernel<<<1, 256>>>(tokens);
    cudaEventRecord(evFork, 0);
    cudaStreamWaitEvent(s2, evFork, 0);

    // side stream: wqkv first (needed earliest), then later weights
    convT_kernel<<<dim3(D / 32, D / 32), 256, 0, s2>>>(wq, D, D, pwqkvTh);
    convT_kernel<<<dim3(D / 32, D / 32), 256, 0, s2>>>(wk, D, D, pwqkvTh + DD);
    convT_kernel<<<dim3(D / 32, D / 32), 256, 0, s2>>>(wv, D, D, pwqkvTh + 2 * DD);
    cudaEventRecord(evWqkv, s2);
    convT_kernel<<<dim3(D / 32, D / 32), 256, 0, s2>>>(wo, D, D, pwoTh);
    cudaEventRecord(evWo, s2);
    convT_kernel<<<dim3(FF / 32, D / 32), 256, 0, s2>>>(wfi, D, FF, pwfiTh);
    cudaEventRecord(evWfi, s2);
    convT_kernel<<<dim3(D / 32, FF / 32), 256, 0, s2>>>(wfo, FF, D, pwfoTh);
    cudaEventRecord(evWfo, s2);
    convT_kernel<<<dim3(VOC / 32, D / 32), 256, 0, s2>>>(wout, D, VOC, pwoutTh);
    cudaEventRecord(evWout, s2);

    // main stream (embed + ln1 overlap the wqkv conversion)
    embed_kernel<<<S, 256>>>(tokens, temb, pemb, px);
    ln_kernel<<<S, 256>>>(px, ln1g, ln1b, phh);
    cudaStreamWaitEvent(0, evWqkv, 0);

    // attention block: QKV 1-pass fp16, bf16-pair output for QK precision
    tc_gemm<OUT_PAIR_BF16, 1><<<dim3(S / 128, D / 128, 3), 256, GEMM_SMEM1>>>(
        (uint16_t*)phh, nullptr, D, 0, (uint16_t*)pwqkvTh, nullptr, D, DD, nullptr,
        nullptr, (uint16_t*)pqkvh, (uint16_t*)pqkvl, D, SD, D, 1.f);
    vtrans_kernel<<<dim3(HD / 32, S / 32, H), 256>>>(pqkvh + 2 * SD, pqkvl + 2 * SD, pvth);
    tc_gemm<OUT_F32, 3><<<dim3(S / 128, S / 128, H), 256, GEMM_SMEM3>>>(
        (uint16_t*)pqkvh, (uint16_t*)pqkvl, D, HD,
        (uint16_t*)(pqkvh + SD), (uint16_t*)(pqkvl + SD), D, HD, nullptr,
        pat, nullptr, nullptr, S, (long long)S * S, HD, 0.08838834764831845f);
    softmax_kernel<<<H * S, 256>>>(pat, pph);
    // attn_out = P @ V^T  : 1-pass fp16
    tc_gemm<OUT_HI, 1><<<dim3(S / 128, 1, H), 256, GEMM_SMEM1>>>(
        (uint16_t*)pph, nullptr, S, (long long)S * S,
        (uint16_t*)pvth, nullptr, S, (long long)HD * S, nullptr,
        nullptr, (uint16_t*)paoh, nullptr, D, HD, S, 1.f);
    cudaStreamWaitEvent(0, evWo, 0);
    // x2 = x + attn_out @ Wo : 1-pass fp16
    tc_gemm<OUT_F32RES, 1><<<dim3(S / 128, D / 128, 1), 256, GEMM_SMEM1>>>(
        (uint16_t*)paoh, nullptr, D, 0, (uint16_t*)pwoTh, nullptr, D, 0, px,
        px2, nullptr, nullptr, D, 0, D, 1.f);

    // FFN block (1-pass fp16)
    ln_kernel<<<S, 256>>>(px2, ln2g, ln2b, ph2h);
    cudaStreamWaitEvent(0, evWfi, 0);
    tc_gemm<OUT_RELU_HI, 1><<<dim3(S / 128, FF / 128, 1), 256, GEMM_SMEM1>>>(
        (uint16_t*)ph2h, nullptr, D, 0, (uint16_t*)pwfiTh, nullptr, D, 0, nullptr,
        nullptr, (uint16_t*)pffh, nullptr, FF, 0, D, 1.f);
    cudaStreamWaitEvent(0, evWfo, 0);
    tc_gemm<OUT_F32RES, 1><<<dim3(S / 128, D / 128, 1), 256, GEMM_SMEM1>>>(
        (uint16_t*)pffh, nullptr, FF, 0, (uint16_t*)pwfoTh, nullptr, FF, 0, px2,
        px3, nullptr, nullptr, D, 0, FF, 1.f);

    // final LN + logits (1-pass fp16)
    ln_kernel<<<S, 256>>>(px3, lnfg, lnfb, phfh);
    cudaStreamWaitEvent(0, evWout, 0);
    tc_gemm<OUT_F32, 1><<<dim3(S / 128, VOC / 128, 1), 256, GEMM_SMEM1>>>(
        (uint16_t*)phfh, nullptr, D, 0, (uint16_t*)pwoutTh, nullptr, D, 0, nullptr,
        out, nullptr, nullptr, VOC, 0, D, 1.f);
}

// round 10
// speedup vs baseline: 7.4064x; 1.0251x over previous
#include <cuda_runtime.h>
#include <cuda_bf16.h>
#include <cuda_fp16.h>
#include <stdint.h>
#include <math.h>

typedef __nv_bfloat16 BF16;
typedef __half        HALF;

// ---------------- dimensions ----------------
#define S   2048
#define D   2048
#define H   16
#define HD  128
#define FF  8192
#define VOC 32000
#define LN_EPS 1e-5f
#define SD  (S * D)
#define DD  (D * D)

// ---------------- scratch ----------------
__device__ float g_x  [SD];
__device__ float g_x2 [SD];
__device__ float g_x3 [SD];
__device__ float g_at [H * S * S];

// fp16 activations
__device__ HALF g_hh [SD];
__device__ HALF g_h2h[SD];
__device__ HALF g_hfh[SD];
__device__ HALF g_aoh[SD];
__device__ HALF g_ffh[S * FF];
__device__ HALF g_ph [H * S * S];     // P fp16 hi
__device__ HALF g_vth[SD];            // V^T fp16 hi

// fp16 hi/lo pairs for q/k/v (QK uses q pair + k hi)
__device__ HALF g_qkvh[3 * SD], g_qkvl[3 * SD];

// fp16 weights, hi only
__device__ HALF g_wqkvTh[3 * DD];
__device__ HALF g_woTh[DD];
__device__ HALF g_wfiTh[D * FF];
__device__ HALF g_wfoTh[D * FF];
__device__ HALF g_woutTh[(size_t)D * VOC];

__device__ int g_tok64;

// ---------------- PTX helpers (plain sm_103-legal) ----------------
__device__ __forceinline__ uint32_t smem_u32(const void* p) {
    uint32_t a;
    asm("{ .reg .u64 t; cvta.to.shared.u64 t, %1; cvt.u32.u64 %0, t; }" : "=r"(a) : "l"(p));
    return a;
}
__device__ __forceinline__ void ldm_x4(uint32_t* r, uint32_t addr) {
    asm volatile("ldmatrix.sync.aligned.m8n8.x4.shared.b16 {%0,%1,%2,%3}, [%4];"
                 : "=r"(r[0]), "=r"(r[1]), "=r"(r[2]), "=r"(r[3]) : "r"(addr));
}
__device__ __forceinline__ void mma_fp16(float* c, const uint32_t* a, const uint32_t* b) {
    asm volatile(
        "mma.sync.aligned.m16n8k16.row.col.f32.f16.f16.f32 "
        "{%0,%1,%2,%3}, {%4,%5,%6,%7}, {%8,%9}, {%0,%1,%2,%3};"
        : "+f"(c[0]), "+f"(c[1]), "+f"(c[2]), "+f"(c[3])
        : "r"(a[0]), "r"(a[1]), "r"(a[2]), "r"(a[3]), "r"(b[0]), "r"(b[1]));
}
#define CP16(dst, src) \
    asm volatile("cp.async.cg.shared.global [%0], [%1], 16;" :: "r"(dst), "l"(src) : "memory")
#define CPCOMMIT() asm volatile("cp.async.commit_group;" ::: "memory")
#define CPWAIT0() asm volatile("cp.async.wait_group 0;" ::: "memory")
#define CPWAIT1() asm volatile("cp.async.wait_group 1;" ::: "memory")
#define CPWAIT2() asm volatile("cp.async.wait_group 2;" ::: "memory")

#define SW64(o) ((o) ^ (((o) >> 3) & 0x30))

// split fp32 pair -> fp16 hi pair + fp16 lo pair
__device__ __forceinline__ uint32_t split2h(float a, float b, uint32_t& lo)
{
    HALF ha = __float2half_rn(a);
    HALF hb = __float2half_rn(b);
    __half2 l2 = __halves2half2(__float2half_rn(a - __half2float(ha)),
                                __float2half_rn(b - __half2float(hb)));
    lo = *reinterpret_cast<uint32_t*>(&l2);
    __half2 h2 = __halves2half2(ha, hb);
    return *reinterpret_cast<uint32_t*>(&h2);
}
// fp32 pair -> fp16 pair (packed)
__device__ __forceinline__ uint32_t pack2h(float a, float b)
{
    __half2 h2 = __halves2half2(__float2half_rn(a), __float2half_rn(b));
    return *reinterpret_cast<uint32_t*>(&h2);
}

// ---------------- token detect + embed ----------------
__global__ void detect_tok_kernel(const int* __restrict__ t)
{
    __shared__ int any;
    if (threadIdx.x == 0) any = 0;
    __syncthreads();
    int local = 0;
    for (int i = threadIdx.x; i < S / 2; i += blockDim.x)
        if (t[2 * i + 1] != 0) local = 1;
    if (local) any = 1;
    __syncthreads();
    if (threadIdx.x == 0) g_tok64 = (any == 0) ? 1 : 0;
}

__global__ void embed_kernel(const int* __restrict__ tok,
                             const float* __restrict__ te,
                             const float* __restrict__ pe,
                             float* __restrict__ x)
{
    const int s = blockIdx.x;
    const int t = g_tok64 ? tok[2 * s] : tok[s];
    const float4* e = (const float4*)(te + (size_t)t * D);
    const float4* p = (const float4*)(pe + (size_t)s * D);
    float4*       o = (float4*)(x + (size_t)s * D);
    for (int i = threadIdx.x; i < D / 4; i += blockDim.x) {
        float4 a = e[i], b = p[i];
        o[i] = make_float4(a.x + b.x, a.y + b.y, a.z + b.z, a.w + b.w);
    }
}

// ---------------- weight convert + transpose: fp32 [K][N] -> fp16 hi [N][K] ----------------
__global__ void convT_kernel(const float* __restrict__ src, int K, int N,
                             HALF* __restrict__ dhi)
{
    __shared__ float t[32][33];
    const int n0 = blockIdx.x * 32, k0 = blockIdx.y * 32;
    const int tx = threadIdx.x & 31, ty = threadIdx.x >> 5;
#pragma unroll
    for (int r = 0; r < 4; r++)
        t[ty + 8 * r][tx] = src[(size_t)(k0 + ty + 8 * r) * N + n0 + tx];
    __syncthreads();
#pragma unroll
    for (int r = 0; r < 4; r++) {
        const int n = n0 + ty + 8 * r, k = k0 + tx;
        dhi[(size_t)n * K + k] = __float2half_rn(t[tx][ty + 8 * r]);
    }
}

// ---------------- V transpose: fp16 hi [S][D] head slice -> fp16 [H][HD][S] ----------------
__global__ void vtrans_kernel(const HALF* __restrict__ vh, HALF* __restrict__ vth)
{
    __shared__ HALF th[32][33];
    const int h = blockIdx.z;
    const int d0 = blockIdx.x * 32, s0 = blockIdx.y * 32;
    const int tx = threadIdx.x & 31, ty = threadIdx.x >> 5;
#pragma unroll
    for (int r = 0; r < 4; r++) {
        const size_t src = (size_t)(s0 + ty + 8 * r) * D + h * HD + d0 + tx;
        th[ty + 8 * r][tx] = vh[src];
    }
    __syncthreads();
#pragma unroll
    for (int r = 0; r < 4; r++) {
        const size_t dst = ((size_t)h * HD + d0 + ty + 8 * r) * S + s0 + tx;
        vth[dst] = th[tx][ty + 8 * r];
    }
}

// ---------------- layernorm: fp32 in -> fp16 hi out ----------------
__global__ void ln_kernel(const float* __restrict__ x,
                          const float* __restrict__ g,
                          const float* __restrict__ b,
                          HALF* __restrict__ oh)
{
    __shared__ float r1[8], r2[8];
    __shared__ float s_mean, s_inv;
    const int s   = blockIdx.x;
    const int tid = threadIdx.x;
    const float4* xr = (const float4*)(x + (size_t)s * D);
    float4 v0 = xr[tid];
    float4 v1 = xr[tid + 256];
    float sum = v0.x + v0.y + v0.z + v0.w + v1.x + v1.y + v1.z + v1.w;
    float sq  = v0.x * v0.x + v0.y * v0.y + v0.z * v0.z + v0.w * v0.w
              + v1.x * v1.x + v1.y * v1.y + v1.z * v1.z + v1.w * v1.w;
#pragma unroll
    for (int o = 16; o; o >>= 1) {
        sum += __shfl_xor_sync(0xffffffffu, sum, o);
        sq  += __shfl_xor_sync(0xffffffffu, sq,  o);
    }
    const int w = tid >> 5;
    if ((tid & 31) == 0) { r1[w] = sum; r2[w] = sq; }
    __syncthreads();
    if (tid == 0) {
        float ts = 0.f, tq = 0.f;
#pragma unroll
        for (int i = 0; i < 8; i++) { ts += r1[i]; tq += r2[i]; }
        const float mean = ts / (float)D;
        const float var  = tq / (float)D - mean * mean;
        s_mean = mean;
        s_inv  = rsqrtf(var + LN_EPS);
    }
    __syncthreads();
    const float mean = s_mean, inv = s_inv;
    const float4* gg = (const float4*)g;
    const float4* bb = (const float4*)b;
    float4 g0 = gg[tid], g1 = gg[tid + 256];
    float4 b0 = bb[tid], b1 = bb[tid + 256];
    float o00 = (v0.x - mean) * inv * g0.x + b0.x;
    float o01 = (v0.y - mean) * inv * g0.y + b0.y;
    float o02 = (v0.z - mean) * inv * g0.z + b0.z;
    float o03 = (v0.w - mean) * inv * g0.w + b0.w;
    float o10 = (v1.x - mean) * inv * g1.x + b1.x;
    float o11 = (v1.y - mean) * inv * g1.y + b1.y;
    float o12 = (v1.z - mean) * inv * g1.z + b1.z;
    float o13 = (v1.w - mean) * inv * g1.w + b1.w;
    const size_t e0 = (size_t)s * D + tid * 4;
    *(uint2*)(oh + e0)        = make_uint2(pack2h(o00, o01), pack2h(o02, o03));
    *(uint2*)(oh + e0 + 1024) = make_uint2(pack2h(o10, o11), pack2h(o12, o13));
}

// ---------------- softmax: fp32 rows -> fp16 hi prob rows ----------------
__global__ void softmax_kernel(const float* __restrict__ sc,
                               HALF* __restrict__ ph)
{
    __shared__ float r1[8];
    __shared__ float s_max, s_inv;
    const int tid = threadIdx.x;
    const float* r = sc + (size_t)blockIdx.x * S;
    float4 v0 = ((const float4*)r)[tid];
    float4 v1 = ((const float4*)r)[tid + 256];
    float mx = fmaxf(fmaxf(fmaxf(v0.x, v0.y), fmaxf(v0.z, v0.w)),
                     fmaxf(fmaxf(v1.x, v1.y), fmaxf(v1.z, v1.w)));
#pragma unroll
    for (int o = 16; o; o >>= 1) mx = fmaxf(mx, __shfl_xor_sync(0xffffffffu, mx, o));
    const int w = tid >> 5;
    if ((tid & 31) == 0) r1[w] = mx;
    __syncthreads();
    if (tid == 0) {
        float m = r1[0];
#pragma unroll
        for (int i = 1; i < 8; i++) m = fmaxf(m, r1[i]);
        s_max = m;
    }
    __syncthreads();
    mx = s_max;
    v0.x = expf(v0.x - mx); v0.y = expf(v0.y - mx);
    v0.z = expf(v0.z - mx); v0.w = expf(v0.w - mx);
    v1.x = expf(v1.x - mx); v1.y = expf(v1.y - mx);
    v1.z = expf(v1.z - mx); v1.w = expf(v1.w - mx);
    float sum = v0.x + v0.y + v0.z + v0.w + v1.x + v1.y + v1.z + v1.w;
#pragma unroll
    for (int o = 16; o; o >>= 1) sum += __shfl_xor_sync(0xffffffffu, sum, o);
    __syncthreads();
    if ((tid & 31) == 0) r1[w] = sum;
    __syncthreads();
    if (tid == 0) {
        float t = 0.f;
#pragma unroll
        for (int i = 0; i < 8; i++) t += r1[i];
        s_inv = 1.0f / t;
    }
    __syncthreads();
    const float inv = s_inv;
    v0.x *= inv; v0.y *= inv; v0.z *= inv; v0.w *= inv;
    v1.x *= inv; v1.y *= inv; v1.z *= inv; v1.w *= inv;
    const size_t e0 = (size_t)blockIdx.x * S + tid * 4;
    *(uint2*)(ph + e0)        = make_uint2(pack2h(v0.x, v0.y), pack2h(v0.z, v0.w));
    *(uint2*)(ph + e0 + 1024) = make_uint2(pack2h(v1.x, v1.y), pack2h(v1.z, v1.w));
}

// ---------------- cp.async pipelined split GEMM ----------------
// C[z] = epi(alpha * A[z] @ B[z]^T (+ Res))
// PASSES==2: fp16, 2 passes ((Ah+Al)Bh);          4-stage pipeline
// PASSES==1: fp16, 1 pass  (Ah Bh);               4-stage pipeline
#define OUT_F32       0
#define OUT_F32RES    1
#define OUT_PAIR_FP16 3
#define OUT_RELU_HI   4
#define OUT_HI        5

#define GEMM_SMEM2 (4 * 24576)
#define GEMM_SMEM1 (4 * 16384)

template <int OUT, int PASSES>
__global__ void __launch_bounds__(256, 2)
tc_gemm(const uint16_t* __restrict__ Ah, const uint16_t* __restrict__ Al, int lda, long long sA,
        const uint16_t* __restrict__ Bh, int ldb, long long sB,
        const float* __restrict__ Res,
        float* __restrict__ Cf, uint16_t* __restrict__ Chi, uint16_t* __restrict__ Clo,
        int ldc, long long sC, int K, float alpha)
{
    constexpr int STAGE_BYTES = (PASSES == 2) ? 24576 : 16384;
    constexpr int BOFF        = (PASSES == 1) ? 8192 : 16384;
    constexpr int NSTAGE      = 4;
    extern __shared__ char smem[];
    const uint32_t sb = smem_u32(smem);
    const int tid = threadIdx.x, wid = tid >> 5, lane = tid & 31;
    const int z = blockIdx.z;
    Ah += (size_t)z * sA;
    if (PASSES >= 2) Al += (size_t)z * sA;
    Bh += (size_t)z * sB;
    const int m0 = blockIdx.x * 128;   // M fast-varying
    const int n0 = blockIdx.y * 128;
    const int wm = (wid & 3) * 32;
    const int wn = (wid >> 2) * 64;

    // loader thread mapping: rowL in [0,64), cL = 16B chunk in [0,4)
    const int rowL = tid >> 2;
    const int cL   = tid & 3;
    const uint32_t o0 = SW64((uint32_t)(rowL * 64 + cL * 16));
    const uint32_t o1 = SW64((uint32_t)((rowL + 64) * 64 + cL * 16));
    const uint16_t* aht = Ah + (size_t)(m0 + rowL) * lda + cL * 8;
    const uint16_t* alt = (PASSES >= 2) ? (Al + (size_t)(m0 + rowL) * lda + cL * 8) : nullptr;
    const uint16_t* bht = Bh + (size_t)(n0 + rowL) * ldb + cL * 8;
    const size_t a64 = (size_t)64 * lda;
    const size_t b64 = (size_t)64 * ldb;

    auto issue = [&](int idx, int s) {
        const uint32_t st = sb + s * STAGE_BYTES;
        const uint16_t* a1 = aht + idx * 32;
        const uint16_t* b1 = bht + idx * 32;
        CP16(st + o0,        a1);
        CP16(st + BOFF + o0, b1);
        CP16(st + o1,        a1 + a64);
        CP16(st + BOFF + o1, b1 + b64);
        if (PASSES >= 2) {
            const uint16_t* a2 = alt + idx * 32;
            CP16(st + 8192 + o0, a2);
            CP16(st + 8192 + o1, a2 + a64);
        }
        CPCOMMIT();
    };

    float acc[2][8][4];
#pragma unroll
    for (int i = 0; i < 2; i++)
#pragma unroll
        for (int j = 0; j < 8; j++)
#pragma unroll
            for (int q = 0; q < 4; q++) acc[i][j][q] = 0.f;

    // ldmatrix lane address components
    const int a_row = lane & 15;
    const int a_kc  = (lane >> 4) * 8;
    const int b_row = (lane & 7) + (lane >> 4) * 8;
    const int b_kc  = ((lane >> 3) & 1) * 8;

    const int nch = K >> 5;
    issue(0, 0);
    issue(1, 1);
    if (nch > 2) issue(2, 2);

    for (int i = 0; i < nch; i++) {
        if (i + 2 < nch)      { CPWAIT2(); }
        else if (i + 1 < nch) { CPWAIT1(); }
        else                  { CPWAIT0(); }
        __syncthreads();                       // single barrier per chunk
        if (i + NSTAGE - 1 < nch) issue(i + NSTAGE - 1, (i + NSTAGE - 1) % NSTAGE);

        const uint32_t st  = sb + (i % NSTAGE) * STAGE_BYTES;
        const uint32_t AhS = st, AlS = st + 8192, BhS = st + BOFF;
#pragma unroll
        for (int ks = 0; ks < 2; ks++) {
            uint32_t ah[2][4], al[2][4];
#pragma unroll
            for (int mf = 0; mf < 2; mf++) {
                const uint32_t swo = SW64((uint32_t)((wm + mf * 16 + a_row) * 64
                                                     + (ks * 16 + a_kc) * 2));
                ldm_x4(ah[mf], AhS + swo);
                if (PASSES >= 2) ldm_x4(al[mf], AlS + swo);
            }
#pragma unroll
            for (int p = 0; p < 4; p++) {
                uint32_t bh[4];
                const uint32_t swo = SW64((uint32_t)((wn + p * 16 + b_row) * 64
                                                     + (ks * 16 + b_kc) * 2));
                ldm_x4(bh, BhS + swo);
                if (PASSES == 2) {
#pragma unroll
                    for (int mf = 0; mf < 2; mf++) {
                        mma_fp16(acc[mf][2 * p],     ah[mf], bh);
                        mma_fp16(acc[mf][2 * p + 1], ah[mf], bh + 2);
                        mma_fp16(acc[mf][2 * p],     al[mf], bh);
                        mma_fp16(acc[mf][2 * p + 1], al[mf], bh + 2);
                    }
                } else {
#pragma unroll
                    for (int mf = 0; mf < 2; mf++) {
                        mma_fp16(acc[mf][2 * p],     ah[mf], bh);
                        mma_fp16(acc[mf][2 * p + 1], ah[mf], bh + 2);
                    }
                }
            }
        }
    }

    // ---------------- epilogue ----------------
    const int r  = lane >> 2;
    const int c2 = (lane & 3) * 2;
#pragma unroll
    for (int mf = 0; mf < 2; mf++) {
#pragma unroll
        for (int hh = 0; hh < 2; hh++) {
            const int m = m0 + wm + mf * 16 + r + 8 * hh;
            const size_t rofs = (size_t)z * sC + (size_t)m * ldc + n0 + wn;
#pragma unroll
            for (int nf = 0; nf < 8; nf++) {
                float x0 = acc[mf][nf][2 * hh]     * alpha;
                float x1 = acc[mf][nf][2 * hh + 1] * alpha;
                const int nn = nf * 8 + c2;
                if (OUT == OUT_F32RES) {
                    const float2 rr = *(const float2*)(Res + (size_t)m * ldc + n0 + wn + nn);
                    x0 += rr.x; x1 += rr.y;
                } else if (OUT == OUT_RELU_HI) {
                    x0 = fmaxf(x0, 0.f); x1 = fmaxf(x1, 0.f);
                }
                if (OUT == OUT_F32 || OUT == OUT_F32RES) {
                    *(float2*)(Cf + rofs + nn) = make_float2(x0, x1);
                } else if (OUT == OUT_PAIR_FP16) {
                    uint32_t lo;
                    const uint32_t hi = split2h(x0, x1, lo);
                    *(uint32_t*)(Chi + rofs + nn) = hi;
                    *(uint32_t*)(Clo + rofs + nn) = lo;
                } else {  // OUT_RELU_HI / OUT_HI: fp16 hi only
                    *(uint32_t*)(Chi + rofs + nn) = pack2h(x0, x1);
                }
            }
        }
    }
}

// ---------------- launch ----------------
extern "C" void kernel_launch(void* const* d_in, const int* in_sizes, int n_in,
                              void* d_out, int out_size)
{
    const int*   tokens = (const int*)d_in[0];
    const float* temb   = (const float*)d_in[1];
    const float* pemb   = (const float*)d_in[2];
    const float* wq     = (const float*)d_in[3];
    const float* wk     = (const float*)d_in[4];
    const float* wv     = (const float*)d_in[5];
    const float* wo     = (const float*)d_in[6];
    const float* wfi    = (const float*)d_in[7];
    const float* wfo    = (const float*)d_in[8];
    const float* ln1g   = (const float*)d_in[9];
    const float* ln1b   = (const float*)d_in[10];
    const float* ln2g   = (const float*)d_in[11];
    const float* ln2b   = (const float*)d_in[12];
    const float* lnfg   = (const float*)d_in[13];
    const float* lnfb   = (const float*)d_in[14];
    const float* wout   = (const float*)d_in[15];
    float*       out    = (float*)d_out;

    float *px, *px2, *px3, *pat;
    HALF *phh, *ph2h, *phfh, *paoh, *pffh, *pph, *pvth;
    HALF *pqkvh, *pqkvl;
    HALF *pwqkvTh, *pwoTh, *pwfiTh, *pwfoTh, *pwoutTh;
    cudaGetSymbolAddress((void**)&px,   g_x);
    cudaGetSymbolAddress((void**)&px2,  g_x2);
    cudaGetSymbolAddress((void**)&px3,  g_x3);
    cudaGetSymbolAddress((void**)&pat,  g_at);
    cudaGetSymbolAddress((void**)&phh,  g_hh);
    cudaGetSymbolAddress((void**)&ph2h, g_h2h);
    cudaGetSymbolAddress((void**)&phfh, g_hfh);
    cudaGetSymbolAddress((void**)&paoh, g_aoh);
    cudaGetSymbolAddress((void**)&pffh, g_ffh);
    cudaGetSymbolAddress((void**)&pph,  g_ph);
    cudaGetSymbolAddress((void**)&pvth, g_vth);
    cudaGetSymbolAddress((void**)&pqkvh, g_qkvh);
    cudaGetSymbolAddress((void**)&pqkvl, g_qkvl);
    cudaGetSymbolAddress((void**)&pwqkvTh, g_wqkvTh);
    cudaGetSymbolAddress((void**)&pwoTh, g_woTh);
    cudaGetSymbolAddress((void**)&pwfiTh, g_wfiTh);
    cudaGetSymbolAddress((void**)&pwfoTh, g_wfoTh);
    cudaGetSymbolAddress((void**)&pwoutTh, g_woutTh);

    cudaFuncSetAttribute(tc_gemm<OUT_PAIR_FP16, 1>,
                         cudaFuncAttributeMaxDynamicSharedMemorySize, GEMM_SMEM1);
    cudaFuncSetAttribute(tc_gemm<OUT_F32, 2>,
                         cudaFuncAttributeMaxDynamicSharedMemorySize, GEMM_SMEM2);
    cudaFuncSetAttribute(tc_gemm<OUT_HI, 1>,
                         cudaFuncAttributeMaxDynamicSharedMemorySize, GEMM_SMEM1);
    cudaFuncSetAttribute(tc_gemm<OUT_F32RES, 1>,
                         cudaFuncAttributeMaxDynamicSharedMemorySize, GEMM_SMEM1);
    cudaFuncSetAttribute(tc_gemm<OUT_RELU_HI, 1>,
                         cudaFuncAttributeMaxDynamicSharedMemorySize, GEMM_SMEM1);
    cudaFuncSetAttribute(tc_gemm<OUT_F32, 1>,
                         cudaFuncAttributeMaxDynamicSharedMemorySize, GEMM_SMEM1);

    // ---- side stream for all weight conversions ----
    cudaStream_t s2;
    cudaStreamCreateWithFlags(&s2, cudaStreamNonBlocking);
    cudaEvent_t evFork, evWqkv, evWo, evWfi, evWfo, evWout;
    cudaEventCreateWithFlags(&evFork, cudaEventDisableTiming);
    cudaEventCreateWithFlags(&evWqkv, cudaEventDisableTiming);
    cudaEventCreateWithFlags(&evWo,   cudaEventDisableTiming);
    cudaEventCreateWithFlags(&evWfi,  cudaEventDisableTiming);
    cudaEventCreateWithFlags(&evWfo,  cudaEventDisableTiming);
    cudaEventCreateWithFlags(&evWout, cudaEventDisableTiming);

    detect_tok_kernel<<<1, 256>>>(tokens);
    cudaEventRecord(evFork, 0);
    cudaStreamWaitEvent(s2, evFork, 0);

    // side stream: wqkv first (needed earliest), then later weights
    convT_kernel<<<dim3(D / 32, D / 32), 256, 0, s2>>>(wq, D, D, pwqkvTh);
    convT_kernel<<<dim3(D / 32, D / 32), 256, 0, s2>>>(wk, D, D, pwqkvTh + DD);
    convT_kernel<<<dim3(D / 32, D / 32), 256, 0, s2>>>(wv, D, D, pwqkvTh + 2 * DD);
    cudaEventRecord(evWqkv, s2);
    convT_kernel<<<dim3(D / 32, D / 32), 256, 0, s2>>>(wo, D, D, pwoTh);
    cudaEventRecord(evWo, s2);
    convT_kernel<<<dim3(FF / 32, D / 32), 256, 0, s2>>>(wfi, D, FF, pwfiTh);
    cudaEventRecord(evWfi, s2);
    convT_kernel<<<dim3(D / 32, FF / 32), 256, 0, s2>>>(wfo, FF, D, pwfoTh);
    cudaEventRecord(evWfo, s2);
    convT_kernel<<<dim3(VOC / 32, D / 32), 256, 0, s2>>>(wout, D, VOC, pwoutTh);
    cudaEventRecord(evWout, s2);

    // main stream (embed + ln1 overlap the wqkv conversion)
    embed_kernel<<<S, 256>>>(tokens, temb, pemb, px);
    ln_kernel<<<S, 256>>>(px, ln1g, ln1b, phh);
    cudaStreamWaitEvent(0, evWqkv, 0);

    // attention block: QKV 1-pass fp16, fp16-pair output (q exactness for QK)
    tc_gemm<OUT_PAIR_FP16, 1><<<dim3(S / 128, D / 128, 3), 256, GEMM_SMEM1>>>(
        (uint16_t*)phh, nullptr, D, 0, (uint16_t*)pwqkvTh, D, DD, nullptr,
        nullptr, (uint16_t*)pqkvh, (uint16_t*)pqkvl, D, SD, D, 1.f);
    vtrans_kernel<<<dim3(HD / 32, S / 32, H), 256>>>(pqkvh + 2 * SD, pvth);
    // scores = (1/sqrt(hd)) (Qh+Ql) Kh^T : 2-pass fp16
    tc_gemm<OUT_F32, 2><<<dim3(S / 128, S / 128, H), 256, GEMM_SMEM2>>>(
        (uint16_t*)pqkvh, (uint16_t*)pqkvl, D, HD,
        (uint16_t*)(pqkvh + SD), D, HD, nullptr,
        pat, nullptr, nullptr, S, (long long)S * S, HD, 0.08838834764831845f);
    softmax_kernel<<<H * S, 256>>>(pat, pph);
    // attn_out = P @ V^T  : 1-pass fp16
    tc_gemm<OUT_HI, 1><<<dim3(S / 128, 1, H), 256, GEMM_SMEM1>>>(
        (uint16_t*)pph, nullptr, S, (long long)S * S,
        (uint16_t*)pvth, S, (long long)HD * S, nullptr,
        nullptr, (uint16_t*)paoh, nullptr, D, HD, S, 1.f);
    cudaStreamWaitEvent(0, evWo, 0);
    // x2 = x + attn_out @ Wo : 1-pass fp16
    tc_gemm<OUT_F32RES, 1><<<dim3(S / 128, D / 128, 1), 256, GEMM_SMEM1>>>(
        (uint16_t*)paoh, nullptr, D, 0, (uint16_t*)pwoTh, D, 0, px,
        px2, nullptr, nullptr, D, 0, D, 1.f);

    // FFN block (1-pass fp16)
    ln_kernel<<<S, 256>>>(px2, ln2g, ln2b, ph2h);
    cudaStreamWaitEvent(0, evWfi, 0);
    tc_gemm<OUT_RELU_HI, 1><<<dim3(S / 128, FF / 128, 1), 256, GEMM_SMEM1>>>(
        (uint16_t*)ph2h, nullptr, D, 0, (uint16_t*)pwfiTh, D, 0, nullptr,
        nullptr, (uint16_t*)pffh, nullptr, FF, 0, D, 1.f);
    cudaStreamWaitEvent(0, evWfo, 0);
    tc_gemm<OUT_F32RES, 1><<<dim3(S / 128, D / 128, 1), 256, GEMM_SMEM1>>>(
        (uint16_t*)pffh, nullptr, FF, 0, (uint16_t*)pwfoTh, FF, 0, px2,
        px3, nullptr, nullptr, D, 0, FF, 1.f);

    // final LN + logits (1-pass fp16)
    ln_kernel<<<S, 256>>>(px3, lnfg, lnfb, phfh);
    cudaStreamWaitEvent(0, evWout, 0);
    tc_gemm<OUT_F32, 1><<<dim3(S / 128, VOC / 128, 1), 256, GEMM_SMEM1>>>(
        (uint16_t*)phfh, nullptr, D, 0, (uint16_t*)pwoutTh, D, 0, nullptr,
        out, nullptr, nullptr, VOC, 0, D, 1.f);
}

// round 11
// speedup vs baseline: 7.6154x; 1.0282x over previous
#include <cuda_runtime.h>
#include <cuda_bf16.h>
#include <cuda_fp16.h>
#include <stdint.h>
#include <math.h>

typedef __half HALF;

// ---------------- dimensions ----------------
#define S   2048
#define D   2048
#define H   16
#define HD  128
#define FF  8192
#define VOC 32000
#define LN_EPS 1e-5f
#define SD  (S * D)
#define DD  (D * D)

// ---------------- scratch ----------------
__device__ float g_x  [SD];
__device__ float g_x2 [SD];
__device__ float g_x3 [SD];

__device__ HALF g_hh [SD];
__device__ HALF g_h2h[SD];
__device__ HALF g_hfh[SD];
__device__ HALF g_aoh[SD];
__device__ HALF g_ffh[S * FF];
__device__ HALF g_qkvh[3 * SD];       // q,k,v fp16 hi
__device__ HALF g_vth[SD];            // V^T fp16 [H][HD][S]

__device__ HALF g_wqkvTh[3 * DD];
__device__ HALF g_woTh[DD];
__device__ HALF g_wfiTh[D * FF];
__device__ HALF g_wfoTh[D * FF];
__device__ HALF g_woutTh[(size_t)D * VOC];

__device__ int g_tok64;

// ---------------- PTX helpers (plain sm_103-legal) ----------------
__device__ __forceinline__ uint32_t smem_u32(const void* p) {
    uint32_t a;
    asm("{ .reg .u64 t; cvta.to.shared.u64 t, %1; cvt.u32.u64 %0, t; }" : "=r"(a) : "l"(p));
    return a;
}
__device__ __forceinline__ void ldm_x4(uint32_t* r, uint32_t addr) {
    asm volatile("ldmatrix.sync.aligned.m8n8.x4.shared.b16 {%0,%1,%2,%3}, [%4];"
                 : "=r"(r[0]), "=r"(r[1]), "=r"(r[2]), "=r"(r[3]) : "r"(addr));
}
__device__ __forceinline__ void mma_fp16(float* c, const uint32_t* a, const uint32_t* b) {
    asm volatile(
        "mma.sync.aligned.m16n8k16.row.col.f32.f16.f16.f32 "
        "{%0,%1,%2,%3}, {%4,%5,%6,%7}, {%8,%9}, {%0,%1,%2,%3};"
        : "+f"(c[0]), "+f"(c[1]), "+f"(c[2]), "+f"(c[3])
        : "r"(a[0]), "r"(a[1]), "r"(a[2]), "r"(a[3]), "r"(b[0]), "r"(b[1]));
}
#define CP16(dst, src) \
    asm volatile("cp.async.cg.shared.global [%0], [%1], 16;" :: "r"(dst), "l"(src) : "memory")
#define CPCOMMIT() asm volatile("cp.async.commit_group;" ::: "memory")
#define CPWAIT0() asm volatile("cp.async.wait_group 0;" ::: "memory")
#define CPWAIT1() asm volatile("cp.async.wait_group 1;" ::: "memory")
#define CPWAIT2() asm volatile("cp.async.wait_group 2;" ::: "memory")

#define SW64(o) ((o) ^ (((o) >> 3) & 0x30))

// split fp32 pair -> fp16 hi pair + fp16 lo pair
__device__ __forceinline__ uint32_t split2h(float a, float b, uint32_t& lo)
{
    HALF ha = __float2half_rn(a);
    HALF hb = __float2half_rn(b);
    __half2 l2 = __halves2half2(__float2half_rn(a - __half2float(ha)),
                                __float2half_rn(b - __half2float(hb)));
    lo = *reinterpret_cast<uint32_t*>(&l2);
    __half2 h2 = __halves2half2(ha, hb);
    return *reinterpret_cast<uint32_t*>(&h2);
}
__device__ __forceinline__ uint32_t pack2h(float a, float b)
{
    __half2 h2 = __halves2half2(__float2half_rn(a), __float2half_rn(b));
    return *reinterpret_cast<uint32_t*>(&h2);
}

// ---------------- token detect + embed ----------------
__global__ void detect_tok_kernel(const int* __restrict__ t)
{
    __shared__ int any;
    if (threadIdx.x == 0) any = 0;
    __syncthreads();
    int local = 0;
    for (int i = threadIdx.x; i < S / 2; i += blockDim.x)
        if (t[2 * i + 1] != 0) local = 1;
    if (local) any = 1;
    __syncthreads();
    if (threadIdx.x == 0) g_tok64 = (any == 0) ? 1 : 0;
}

__global__ void embed_kernel(const int* __restrict__ tok,
                             const float* __restrict__ te,
                             const float* __restrict__ pe,
                             float* __restrict__ x)
{
    const int s = blockIdx.x;
    const int t = g_tok64 ? tok[2 * s] : tok[s];
    const float4* e = (const float4*)(te + (size_t)t * D);
    const float4* p = (const float4*)(pe + (size_t)s * D);
    float4*       o = (float4*)(x + (size_t)s * D);
    for (int i = threadIdx.x; i < D / 4; i += blockDim.x) {
        float4 a = e[i], b = p[i];
        o[i] = make_float4(a.x + b.x, a.y + b.y, a.z + b.z, a.w + b.w);
    }
}

// ---------------- weight convert + transpose: fp32 [K][N] -> fp16 hi [N][K] ----------------
__global__ void convT_kernel(const float* __restrict__ src, int K, int N,
                             HALF* __restrict__ dhi)
{
    __shared__ float t[32][33];
    const int n0 = blockIdx.x * 32, k0 = blockIdx.y * 32;
    const int tx = threadIdx.x & 31, ty = threadIdx.x >> 5;
#pragma unroll
    for (int r = 0; r < 4; r++)
        t[ty + 8 * r][tx] = src[(size_t)(k0 + ty + 8 * r) * N + n0 + tx];
    __syncthreads();
#pragma unroll
    for (int r = 0; r < 4; r++) {
        const int n = n0 + ty + 8 * r, k = k0 + tx;
        dhi[(size_t)n * K + k] = __float2half_rn(t[tx][ty + 8 * r]);
    }
}

// ---------------- V transpose: fp16 [S][D] head slice -> fp16 [H][HD][S] ----------------
__global__ void vtrans_kernel(const HALF* __restrict__ vh, HALF* __restrict__ vth)
{
    __shared__ HALF th[32][33];
    const int h = blockIdx.z;
    const int d0 = blockIdx.x * 32, s0 = blockIdx.y * 32;
    const int tx = threadIdx.x & 31, ty = threadIdx.x >> 5;
#pragma unroll
    for (int r = 0; r < 4; r++) {
        const size_t src = (size_t)(s0 + ty + 8 * r) * D + h * HD + d0 + tx;
        th[ty + 8 * r][tx] = vh[src];
    }
    __syncthreads();
#pragma unroll
    for (int r = 0; r < 4; r++) {
        const size_t dst = ((size_t)h * HD + d0 + ty + 8 * r) * S + s0 + tx;
        vth[dst] = th[tx][ty + 8 * r];
    }
}

// ---------------- layernorm: fp32 in -> fp16 hi out ----------------
__global__ void ln_kernel(const float* __restrict__ x,
                          const float* __restrict__ g,
                          const float* __restrict__ b,
                          HALF* __restrict__ oh)
{
    __shared__ float r1[8], r2[8];
    __shared__ float s_mean, s_inv;
    const int s   = blockIdx.x;
    const int tid = threadIdx.x;
    const float4* xr = (const float4*)(x + (size_t)s * D);
    float4 v0 = xr[tid];
    float4 v1 = xr[tid + 256];
    float sum = v0.x + v0.y + v0.z + v0.w + v1.x + v1.y + v1.z + v1.w;
    float sq  = v0.x * v0.x + v0.y * v0.y + v0.z * v0.z + v0.w * v0.w
              + v1.x * v1.x + v1.y * v1.y + v1.z * v1.z + v1.w * v1.w;
#pragma unroll
    for (int o = 16; o; o >>= 1) {
        sum += __shfl_xor_sync(0xffffffffu, sum, o);
        sq  += __shfl_xor_sync(0xffffffffu, sq,  o);
    }
    const int w = tid >> 5;
    if ((tid & 31) == 0) { r1[w] = sum; r2[w] = sq; }
    __syncthreads();
    if (tid == 0) {
        float ts = 0.f, tq = 0.f;
#pragma unroll
        for (int i = 0; i < 8; i++) { ts += r1[i]; tq += r2[i]; }
        const float mean = ts / (float)D;
        const float var  = tq / (float)D - mean * mean;
        s_mean = mean;
        s_inv  = rsqrtf(var + LN_EPS);
    }
    __syncthreads();
    const float mean = s_mean, inv = s_inv;
    const float4* gg = (const float4*)g;
    const float4* bb = (const float4*)b;
    float4 g0 = gg[tid], g1 = gg[tid + 256];
    float4 b0 = bb[tid], b1 = bb[tid + 256];
    float o00 = (v0.x - mean) * inv * g0.x + b0.x;
    float o01 = (v0.y - mean) * inv * g0.y + b0.y;
    float o02 = (v0.z - mean) * inv * g0.z + b0.z;
    float o03 = (v0.w - mean) * inv * g0.w + b0.w;
    float o10 = (v1.x - mean) * inv * g1.x + b1.x;
    float o11 = (v1.y - mean) * inv * g1.y + b1.y;
    float o12 = (v1.z - mean) * inv * g1.z + b1.z;
    float o13 = (v1.w - mean) * inv * g1.w + b1.w;
    const size_t e0 = (size_t)s * D + tid * 4;
    *(uint2*)(oh + e0)        = make_uint2(pack2h(o00, o01), pack2h(o02, o03));
    *(uint2*)(oh + e0 + 1024) = make_uint2(pack2h(o10, o11), pack2h(o12, o13));
}

// ---------------- fused flash attention ----------------
// grid (S/128, H), 256 threads, 1 CTA/SM.
// Q fp16 [S][D] (head slice), K fp16 [S][D], V^T fp16 [H][HD][S].
// out: attn fp16 [S][D].
#define FLASH_STAGE 65536               // K tile 32KB + V tile 32KB
#define FLASH_SMEM  (3 * FLASH_STAGE)

__global__ void __launch_bounds__(256, 1)
flash_kernel(const HALF* __restrict__ q, const HALF* __restrict__ k,
             const HALF* __restrict__ vt, HALF* __restrict__ out, float alpha)
{
    extern __shared__ char smem[];
    const uint32_t sb = smem_u32(smem);
    const int tid = threadIdx.x, wid = tid >> 5, lane = tid & 31;
    const int q0 = blockIdx.x * 128;
    const int h  = blockIdx.y;

    // loader mapping: rowL in [0,128), half in {0,1}; 4x16B per (chunk,thread)
    const int rowL = tid >> 1;
    const int half = tid & 1;
    uint32_t so[2][4];
#pragma unroll
    for (int c = 0; c < 2; c++)
#pragma unroll
        for (int u = 0; u < 4; u++)
            so[c][u] = c * 16384 + SW64((uint32_t)(rowL * 128 + half * 64 + u * 16));
    const int gofs = half * 32;   // halves

    // ldmatrix lane components (same as GEMM kernel)
    const int a_row = lane & 15;
    const int a_kc  = (lane >> 4) * 8;
    const int b_row = (lane & 7) + (lane >> 4) * 8;
    const int b_kc  = ((lane >> 3) & 1) * 8;

    // ---- load Q tile (128x128) into stage 0, then to register frags ----
    {
        const HALF* qp = q + (size_t)(q0 + rowL) * D + h * HD + gofs;
#pragma unroll
        for (int c = 0; c < 2; c++)
#pragma unroll
            for (int u = 0; u < 4; u++)
                CP16(sb + so[c][u], qp + c * 64 + u * 8);
        CPCOMMIT(); CPWAIT0();
    }
    __syncthreads();
    uint32_t qf[8][4];
    {
        const int wq = wid * 16;
#pragma unroll
        for (int j = 0; j < 8; j++) {
            const int kcol = j * 16 + a_kc;
            ldm_x4(qf[j], sb + (kcol >> 6) * 16384
                             + SW64((uint32_t)((wq + a_row) * 128 + (kcol & 63) * 2)));
        }
    }
    __syncthreads();

    // ---- KV pipeline ----
    const HALF* kbase = k + (size_t)rowL * D + h * HD + gofs;
    const HALF* vbase = vt + ((size_t)h * HD + rowL) * S + gofs;

    auto issue = [&](int t, int st) {
        const uint32_t sB = sb + st * FLASH_STAGE;
        const HALF* kp = kbase + (size_t)(t * 128) * D;
        const HALF* vp = vbase + t * 128;
#pragma unroll
        for (int c = 0; c < 2; c++)
#pragma unroll
            for (int u = 0; u < 4; u++) {
                CP16(sB + so[c][u],         kp + c * 64 + u * 8);
                CP16(sB + 32768 + so[c][u], vp + c * 64 + u * 8);
            }
        CPCOMMIT();
    };

    float oa[16][4];
#pragma unroll
    for (int i = 0; i < 16; i++)
#pragma unroll
        for (int j = 0; j < 4; j++) oa[i][j] = 0.f;
    float m0 = -1e30f, m1 = -1e30f, l0 = 0.f, l1 = 0.f;

    issue(0, 0);
    issue(1, 1);

    for (int t = 0; t < 16; t++) {
        if (t + 1 < 16) { CPWAIT1(); } else { CPWAIT0(); }
        __syncthreads();
        if (t + 2 < 16) issue(t + 2, (t + 2) % 3);   // overwrites stage (t-1)%3, safe post-sync

        const uint32_t stK = sb + (t % 3) * FLASH_STAGE;
        const uint32_t stV = stK + 32768;

        // scores: S[16 rows][128 cols]
        float s[16][4];
#pragma unroll
        for (int i = 0; i < 16; i++)
#pragma unroll
            for (int j = 0; j < 4; j++) s[i][j] = 0.f;
#pragma unroll
        for (int j = 0; j < 8; j++) {
            const int kcol = j * 16 + b_kc;
            const uint32_t kadd = stK + (kcol >> 6) * 16384;
            const uint32_t kc2 = (kcol & 63) * 2;
#pragma unroll
            for (int nt2 = 0; nt2 < 8; nt2++) {
                uint32_t bh[4];
                ldm_x4(bh, kadd + SW64((uint32_t)((nt2 * 16 + b_row) * 128) + kc2));
                mma_fp16(s[2 * nt2],     qf[j], bh);
                mma_fp16(s[2 * nt2 + 1], qf[j], bh + 2);
            }
        }

        // online softmax (rows r0 = lane>>2, r1 = r0+8)
        float tm0 = -1e30f, tm1 = -1e30f;
#pragma unroll
        for (int nt = 0; nt < 16; nt++) {
            s[nt][0] *= alpha; s[nt][1] *= alpha;
            s[nt][2] *= alpha; s[nt][3] *= alpha;
            tm0 = fmaxf(tm0, fmaxf(s[nt][0], s[nt][1]));
            tm1 = fmaxf(tm1, fmaxf(s[nt][2], s[nt][3]));
        }
        tm0 = fmaxf(tm0, __shfl_xor_sync(0xffffffffu, tm0, 1));
        tm0 = fmaxf(tm0, __shfl_xor_sync(0xffffffffu, tm0, 2));
        tm1 = fmaxf(tm1, __shfl_xor_sync(0xffffffffu, tm1, 1));
        tm1 = fmaxf(tm1, __shfl_xor_sync(0xffffffffu, tm1, 2));
        const float nm0 = fmaxf(m0, tm0), nm1 = fmaxf(m1, tm1);
        const float f0 = __expf(m0 - nm0), f1 = __expf(m1 - nm1);
        m0 = nm0; m1 = nm1;
        float ps0 = 0.f, ps1 = 0.f;
#pragma unroll
        for (int nt = 0; nt < 16; nt++) {
            s[nt][0] = __expf(s[nt][0] - nm0); ps0 += s[nt][0];
            s[nt][1] = __expf(s[nt][1] - nm0); ps0 += s[nt][1];
            s[nt][2] = __expf(s[nt][2] - nm1); ps1 += s[nt][2];
            s[nt][3] = __expf(s[nt][3] - nm1); ps1 += s[nt][3];
        }
        ps0 += __shfl_xor_sync(0xffffffffu, ps0, 1);
        ps0 += __shfl_xor_sync(0xffffffffu, ps0, 2);
        ps1 += __shfl_xor_sync(0xffffffffu, ps1, 1);
        ps1 += __shfl_xor_sync(0xffffffffu, ps1, 2);
        l0 = l0 * f0 + ps0;
        l1 = l1 * f1 + ps1;
#pragma unroll
        for (int vtt = 0; vtt < 16; vtt++) {
            oa[vtt][0] *= f0; oa[vtt][1] *= f0;
            oa[vtt][2] *= f1; oa[vtt][3] *= f1;
        }

        // PV: A = P frags (C->A register identity), B = V^T tile
#pragma unroll
        for (int ks = 0; ks < 8; ks++) {
            uint32_t af[4];
            af[0] = pack2h(s[2 * ks][0],     s[2 * ks][1]);
            af[1] = pack2h(s[2 * ks][2],     s[2 * ks][3]);
            af[2] = pack2h(s[2 * ks + 1][0], s[2 * ks + 1][1]);
            af[3] = pack2h(s[2 * ks + 1][2], s[2 * ks + 1][3]);
            const int scol = ks * 16 + b_kc;
            const uint32_t vadd = stV + (scol >> 6) * 16384;
            const uint32_t sc2 = (scol & 63) * 2;
#pragma unroll
            for (int vt2 = 0; vt2 < 8; vt2++) {
                uint32_t bh[4];
                ldm_x4(bh, vadd + SW64((uint32_t)((vt2 * 16 + b_row) * 128) + sc2));
                mma_fp16(oa[2 * vt2],     af, bh);
                mma_fp16(oa[2 * vt2 + 1], af, bh + 2);
            }
        }
    }

    // ---- epilogue: normalize and store fp16 ----
    const float i0 = 1.f / l0, i1 = 1.f / l1;
    const int r0 = q0 + wid * 16 + (lane >> 2);
    HALF* op0 = out + (size_t)r0 * D + h * HD + (lane & 3) * 2;
    HALF* op1 = op0 + (size_t)8 * D;
#pragma unroll
    for (int vtt = 0; vtt < 16; vtt++) {
        *(uint32_t*)(op0 + vtt * 8) = pack2h(oa[vtt][0] * i0, oa[vtt][1] * i0);
        *(uint32_t*)(op1 + vtt * 8) = pack2h(oa[vtt][2] * i1, oa[vtt][3] * i1);
    }
}

// ---------------- cp.async pipelined GEMM (fp16, 1-pass) ----------------
#define OUT_F32       0
#define OUT_F32RES    1
#define OUT_RELU_HI   4
#define OUT_HI        5

#define GEMM_SMEM1 (4 * 16384)

template <int OUT>
__global__ void __launch_bounds__(256, 2)
tc_gemm(const uint16_t* __restrict__ Ah, int lda, long long sA,
        const uint16_t* __restrict__ Bh, int ldb, long long sB,
        const float* __restrict__ Res,
        float* __restrict__ Cf, uint16_t* __restrict__ Chi,
        int ldc, long long sC, int K, float alpha)
{
    constexpr int STAGE_BYTES = 16384;
    constexpr int BOFF        = 8192;
    constexpr int NSTAGE      = 4;
    extern __shared__ char smem[];
    const uint32_t sb = smem_u32(smem);
    const int tid = threadIdx.x, wid = tid >> 5, lane = tid & 31;
    const int z = blockIdx.z;
    Ah += (size_t)z * sA;
    Bh += (size_t)z * sB;
    const int m0 = blockIdx.x * 128;   // M fast-varying
    const int n0 = blockIdx.y * 128;
    const int wm = (wid & 3) * 32;
    const int wn = (wid >> 2) * 64;

    const int rowL = tid >> 2;
    const int cL   = tid & 3;
    const uint32_t o0 = SW64((uint32_t)(rowL * 64 + cL * 16));
    const uint32_t o1 = SW64((uint32_t)((rowL + 64) * 64 + cL * 16));
    const uint16_t* aht = Ah + (size_t)(m0 + rowL) * lda + cL * 8;
    const uint16_t* bht = Bh + (size_t)(n0 + rowL) * ldb + cL * 8;
    const size_t a64 = (size_t)64 * lda;
    const size_t b64 = (size_t)64 * ldb;

    auto issue = [&](int idx, int s) {
        const uint32_t st = sb + s * STAGE_BYTES;
        const uint16_t* a1 = aht + idx * 32;
        const uint16_t* b1 = bht + idx * 32;
        CP16(st + o0,        a1);
        CP16(st + BOFF + o0, b1);
        CP16(st + o1,        a1 + a64);
        CP16(st + BOFF + o1, b1 + b64);
        CPCOMMIT();
    };

    float acc[2][8][4];
#pragma unroll
    for (int i = 0; i < 2; i++)
#pragma unroll
        for (int j = 0; j < 8; j++)
#pragma unroll
            for (int q = 0; q < 4; q++) acc[i][j][q] = 0.f;

    const int a_row = lane & 15;
    const int a_kc  = (lane >> 4) * 8;
    const int b_row = (lane & 7) + (lane >> 4) * 8;
    const int b_kc  = ((lane >> 3) & 1) * 8;

    const int nch = K >> 5;
    issue(0, 0);
    issue(1, 1);
    if (nch > 2) issue(2, 2);

    for (int i = 0; i < nch; i++) {
        if (i + 2 < nch)      { CPWAIT2(); }
        else if (i + 1 < nch) { CPWAIT1(); }
        else                  { CPWAIT0(); }
        __syncthreads();
        if (i + NSTAGE - 1 < nch) issue(i + NSTAGE - 1, (i + NSTAGE - 1) % NSTAGE);

        const uint32_t st  = sb + (i % NSTAGE) * STAGE_BYTES;
        const uint32_t AhS = st, BhS = st + BOFF;
#pragma unroll
        for (int ks = 0; ks < 2; ks++) {
            uint32_t ah[2][4];
#pragma unroll
            for (int mf = 0; mf < 2; mf++) {
                const uint32_t swo = SW64((uint32_t)((wm + mf * 16 + a_row) * 64
                                                     + (ks * 16 + a_kc) * 2));
                ldm_x4(ah[mf], AhS + swo);
            }
#pragma unroll
            for (int p = 0; p < 4; p++) {
                uint32_t bh[4];
                const uint32_t swo = SW64((uint32_t)((wn + p * 16 + b_row) * 64
                                                     + (ks * 16 + b_kc) * 2));
                ldm_x4(bh, BhS + swo);
#pragma unroll
                for (int mf = 0; mf < 2; mf++) {
                    mma_fp16(acc[mf][2 * p],     ah[mf], bh);
                    mma_fp16(acc[mf][2 * p + 1], ah[mf], bh + 2);
                }
            }
        }
    }

    const int r  = lane >> 2;
    const int c2 = (lane & 3) * 2;
#pragma unroll
    for (int mf = 0; mf < 2; mf++) {
#pragma unroll
        for (int hh = 0; hh < 2; hh++) {
            const int m = m0 + wm + mf * 16 + r + 8 * hh;
            const size_t rofs = (size_t)z * sC + (size_t)m * ldc + n0 + wn;
#pragma unroll
            for (int nf = 0; nf < 8; nf++) {
                float x0 = acc[mf][nf][2 * hh]     * alpha;
                float x1 = acc[mf][nf][2 * hh + 1] * alpha;
                const int nn = nf * 8 + c2;
                if (OUT == OUT_F32RES) {
                    const float2 rr = *(const float2*)(Res + (size_t)m * ldc + n0 + wn + nn);
                    x0 += rr.x; x1 += rr.y;
                } else if (OUT == OUT_RELU_HI) {
                    x0 = fmaxf(x0, 0.f); x1 = fmaxf(x1, 0.f);
                }
                if (OUT == OUT_F32 || OUT == OUT_F32RES) {
                    *(float2*)(Cf + rofs + nn) = make_float2(x0, x1);
                } else {
                    *(uint32_t*)(Chi + rofs + nn) = pack2h(x0, x1);
                }
            }
        }
    }
}

// ---------------- launch ----------------
extern "C" void kernel_launch(void* const* d_in, const int* in_sizes, int n_in,
                              void* d_out, int out_size)
{
    const int*   tokens = (const int*)d_in[0];
    const float* temb   = (const float*)d_in[1];
    const float* pemb   = (const float*)d_in[2];
    const float* wq     = (const float*)d_in[3];
    const float* wk     = (const float*)d_in[4];
    const float* wv     = (const float*)d_in[5];
    const float* wo     = (const float*)d_in[6];
    const float* wfi    = (const float*)d_in[7];
    const float* wfo    = (const float*)d_in[8];
    const float* ln1g   = (const float*)d_in[9];
    const float* ln1b   = (const float*)d_in[10];
    const float* ln2g   = (const float*)d_in[11];
    const float* ln2b   = (const float*)d_in[12];
    const float* lnfg   = (const float*)d_in[13];
    const float* lnfb   = (const float*)d_in[14];
    const float* wout   = (const float*)d_in[15];
    float*       out    = (float*)d_out;

    float *px, *px2, *px3;
    HALF *phh, *ph2h, *phfh, *paoh, *pffh, *pvth, *pqkvh;
    HALF *pwqkvTh, *pwoTh, *pwfiTh, *pwfoTh, *pwoutTh;
    cudaGetSymbolAddress((void**)&px,   g_x);
    cudaGetSymbolAddress((void**)&px2,  g_x2);
    cudaGetSymbolAddress((void**)&px3,  g_x3);
    cudaGetSymbolAddress((void**)&phh,  g_hh);
    cudaGetSymbolAddress((void**)&ph2h, g_h2h);
    cudaGetSymbolAddress((void**)&phfh, g_hfh);
    cudaGetSymbolAddress((void**)&paoh, g_aoh);
    cudaGetSymbolAddress((void**)&pffh, g_ffh);
    cudaGetSymbolAddress((void**)&pvth, g_vth);
    cudaGetSymbolAddress((void**)&pqkvh, g_qkvh);
    cudaGetSymbolAddress((void**)&pwqkvTh, g_wqkvTh);
    cudaGetSymbolAddress((void**)&pwoTh, g_woTh);
    cudaGetSymbolAddress((void**)&pwfiTh, g_wfiTh);
    cudaGetSymbolAddress((void**)&pwfoTh, g_wfoTh);
    cudaGetSymbolAddress((void**)&pwoutTh, g_woutTh);

    cudaFuncSetAttribute(tc_gemm<OUT_HI>,
                         cudaFuncAttributeMaxDynamicSharedMemorySize, GEMM_SMEM1);
    cudaFuncSetAttribute(tc_gemm<OUT_F32RES>,
                         cudaFuncAttributeMaxDynamicSharedMemorySize, GEMM_SMEM1);
    cudaFuncSetAttribute(tc_gemm<OUT_RELU_HI>,
                         cudaFuncAttributeMaxDynamicSharedMemorySize, GEMM_SMEM1);
    cudaFuncSetAttribute(tc_gemm<OUT_F32>,
                         cudaFuncAttributeMaxDynamicSharedMemorySize, GEMM_SMEM1);
    cudaFuncSetAttribute(flash_kernel,
                         cudaFuncAttributeMaxDynamicSharedMemorySize, FLASH_SMEM);

    // ---- side stream for all weight conversions ----
    cudaStream_t s2;
    cudaStreamCreateWithFlags(&s2, cudaStreamNonBlocking);
    cudaEvent_t evFork, evWqkv, evWo, evWfi, evWfo, evWout;
    cudaEventCreateWithFlags(&evFork, cudaEventDisableTiming);
    cudaEventCreateWithFlags(&evWqkv, cudaEventDisableTiming);
    cudaEventCreateWithFlags(&evWo,   cudaEventDisableTiming);
    cudaEventCreateWithFlags(&evWfi,  cudaEventDisableTiming);
    cudaEventCreateWithFlags(&evWfo,  cudaEventDisableTiming);
    cudaEventCreateWithFlags(&evWout, cudaEventDisableTiming);

    detect_tok_kernel<<<1, 256>>>(tokens);
    cudaEventRecord(evFork, 0);
    cudaStreamWaitEvent(s2, evFork, 0);

    convT_kernel<<<dim3(D / 32, D / 32), 256, 0, s2>>>(wq, D, D, pwqkvTh);
    convT_kernel<<<dim3(D / 32, D / 32), 256, 0, s2>>>(wk, D, D, pwqkvTh + DD);
    convT_kernel<<<dim3(D / 32, D / 32), 256, 0, s2>>>(wv, D, D, pwqkvTh + 2 * DD);
    cudaEventRecord(evWqkv, s2);
    convT_kernel<<<dim3(D / 32, D / 32), 256, 0, s2>>>(wo, D, D, pwoTh);
    cudaEventRecord(evWo, s2);
    convT_kernel<<<dim3(FF / 32, D / 32), 256, 0, s2>>>(wfi, D, FF, pwfiTh);
    cudaEventRecord(evWfi, s2);
    convT_kernel<<<dim3(D / 32, FF / 32), 256, 0, s2>>>(wfo, FF, D, pwfoTh);
    cudaEventRecord(evWfo, s2);
    convT_kernel<<<dim3(VOC / 32, D / 32), 256, 0, s2>>>(wout, D, VOC, pwoutTh);
    cudaEventRecord(evWout, s2);

    // main stream
    embed_kernel<<<S, 256>>>(tokens, temb, pemb, px);
    ln_kernel<<<S, 256>>>(px, ln1g, ln1b, phh);
    cudaStreamWaitEvent(0, evWqkv, 0);

    // attention: QKV 1-pass -> flash fused QK+softmax+PV
    tc_gemm<OUT_HI><<<dim3(S / 128, D / 128, 3), 256, GEMM_SMEM1>>>(
        (uint16_t*)phh, D, 0, (uint16_t*)pwqkvTh, D, DD, nullptr,
        nullptr, (uint16_t*)pqkvh, D, SD, D, 1.f);
    vtrans_kernel<<<dim3(HD / 32, S / 32, H), 256>>>(pqkvh + 2 * SD, pvth);
    flash_kernel<<<dim3(S / 128, H), 256, FLASH_SMEM>>>(
        pqkvh, pqkvh + SD, pvth, paoh, 0.08838834764831845f);
    cudaStreamWaitEvent(0, evWo, 0);
    tc_gemm<OUT_F32RES><<<dim3(S / 128, D / 128, 1), 256, GEMM_SMEM1>>>(
        (uint16_t*)paoh, D, 0, (uint16_t*)pwoTh, D, 0, px,
        px2, nullptr, D, 0, D, 1.f);

    // FFN block
    ln_kernel<<<S, 256>>>(px2, ln2g, ln2b, ph2h);
    cudaStreamWaitEvent(0, evWfi, 0);
    tc_gemm<OUT_RELU_HI><<<dim3(S / 128, FF / 128, 1), 256, GEMM_SMEM1>>>(
        (uint16_t*)ph2h, D, 0, (uint16_t*)pwfiTh, D, 0, nullptr,
        nullptr, (uint16_t*)pffh, FF, 0, D, 1.f);
    cudaStreamWaitEvent(0, evWfo, 0);
    tc_gemm<OUT_F32RES><<<dim3(S / 128, D / 128, 1), 256, GEMM_SMEM1>>>(
        (uint16_t*)pffh, FF, 0, (uint16_t*)pwfoTh, FF, 0, px2,
        px3, nullptr, D, 0, FF, 1.f);

    // final LN + logits
    ln_kernel<<<S, 256>>>(px3, lnfg, lnfb, phfh);
    cudaStreamWaitEvent(0, evWout, 0);
    tc_gemm<OUT_F32><<<dim3(S / 128, VOC / 128, 1), 256, GEMM_SMEM1>>>(
        (uint16_t*)phfh, D, 0, (uint16_t*)pwoutTh, D, 0, nullptr,
        out, nullptr, VOC, 0, D, 1.f);
}